// round 10
// baseline (speedup 1.0000x reference)
#include <cuda_runtime.h>
#include <cuda_bf16.h>
#include <math.h>
#include <stdint.h>

#define D_ 31
#define H_ 96
#define W_ 96
#define HW (H_*W_)        // 9216
#define VOX (D_*HW)       // 285696

// ---- scratch (device globals; no allocation allowed) ----
__device__ float g_conv[256 * VOX];
__device__ float g_h  [16 * VOX];
__device__ float g_e0 [32 * VOX];
__device__ float g_e1 [64 * VOX];
__device__ float g_d0 [32 * VOX];
__device__ float g_d1 [16 * VOX];
__device__ __nv_bfloat16 g_Ahi[262144];   // weights bf16-hi, [M x Kpad]
__device__ __nv_bfloat16 g_Alo[262144];   // weights bf16-lo

__device__ __forceinline__ float sigm(float a) { return 1.0f / (1.0f + expf(-a)); }

typedef unsigned long long u64;
__device__ __forceinline__ void fma2(u64& d, u64 a, u64 b) {
    asm("fma.rn.f32x2 %0, %1, %2, %0;" : "+l"(d) : "l"(a), "l"(b));
}
__device__ __forceinline__ u64 pk2(float x, float y) {
    u64 r; asm("mov.b64 %0, {%1, %2};" : "=l"(r) : "f"(x), "f"(y)); return r;
}
__device__ __forceinline__ float2 unpk2(u64 a) {
    float x, y; asm("mov.b64 {%0, %1}, %2;" : "=f"(x), "=f"(y) : "l"(a));
    return make_float2(x, y);
}
__device__ __forceinline__ uint32_t smem_u32(const void* p) {
    uint32_t a;
    asm("{ .reg .u64 t; cvta.to.shared.u64 t, %1; cvt.u32.u64 %0, t; }" : "=r"(a) : "l"(p));
    return a;
}
__device__ __forceinline__ void ldsm4(uint32_t* r, uint32_t addr) {
    asm volatile("ldmatrix.sync.aligned.m8n8.x4.shared.b16 {%0,%1,%2,%3}, [%4];"
                 : "=r"(r[0]), "=r"(r[1]), "=r"(r[2]), "=r"(r[3]) : "r"(addr));
}
__device__ __forceinline__ void mma16816(float* c, const uint32_t* a, uint32_t b0, uint32_t b1) {
    asm volatile("mma.sync.aligned.m16n8k16.row.col.f32.bf16.bf16.f32 "
                 "{%0,%1,%2,%3},{%4,%5,%6,%7},{%8,%9},{%0,%1,%2,%3};"
                 : "+f"(c[0]), "+f"(c[1]), "+f"(c[2]), "+f"(c[3])
                 : "r"(a[0]), "r"(a[1]), "r"(a[2]), "r"(a[3]), "r"(b0), "r"(b1));
}
// pack truncated-hi bf16 of two floats: low half <- a, high half <- b
__device__ __forceinline__ uint32_t prmt_hi(float a, float b) {
    uint32_t r;
    asm("prmt.b32 %0, %1, %2, 0x7632;" : "=r"(r) : "r"(__float_as_uint(a)), "r"(__float_as_uint(b)));
    return r;
}
// pack rn bf16 of two floats: high half <- hi, low half <- lo
__device__ __forceinline__ uint32_t cvt_bf2(float hi, float lo) {
    uint32_t r;
    asm("cvt.rn.bf16x2.f32 %0, %1, %2;" : "=r"(r) : "f"(hi), "f"(lo));
    return r;
}
__device__ __forceinline__ float trunc16(float v) {
    return __uint_as_float(__float_as_uint(v) & 0xFFFF0000u);
}

// ============================================================================
// Weight prep: split fp32 weights into bf16 hi/lo, layout A[m][k], k=ci*32+t.
// ============================================================================
__global__ void prep_k(const float* __restrict__ w, __nv_bfloat16* __restrict__ Ahi,
                       __nv_bfloat16* __restrict__ Alo,
                       int Cin, int Cout, int Kpad, int deconv, int total)
{
    int i = blockIdx.x * 256 + threadIdx.x;
    if (i >= total) return;
    int m = i / Kpad, k = i - m * Kpad;
    int t = k & 31, ci = k >> 5;
    float v = 0.f;
    if (t < 27 && m < Cout && ci < Cin)
        v = deconv ? w[((size_t)ci * Cout + m) * 27 + (26 - t)]
                   : w[((size_t)m * Cin + ci) * 27 + t];
    __nv_bfloat16 h = __float2bfloat16(v);
    Ahi[i] = h;
    Alo[i] = __float2bfloat16(v - __bfloat162float(h));
}

// ============================================================================
// Tensor-core implicit-GEMM conv. Block tile: M=64 co, N=384 (96x * 4y).
// 8 warps, each: full M=64 x 48 N (1 y-row x 48 x). K chunks of 16.
// Raw input tile (18 rows x 100 + zero pad) per ci; B fragments built in regs;
// tap bases precomputed per parity (invalid -> zero pad). A via ldmatrix.
// ============================================================================
#define KS 24
#define AS_E (64*KS)
#define RAW_E 1800        // 18 rows * 100
#define RAW_T 1928        // + 128 zero-pad floats

__global__ __launch_bounds__(256)
void conv_mma_k(const float* __restrict__ in,
                const __nv_bfloat16* __restrict__ Ahi,
                const __nv_bfloat16* __restrict__ Alo,
                float* __restrict__ out,
                int Cin, int Kpad, int NC2)
{
    __shared__ __align__(16) __nv_bfloat16 AsH[2][AS_E], AsL[2][AS_E];
    __shared__ __align__(16) float rawS[2][RAW_T];

    const int tid  = threadIdx.x;
    const int wid  = tid >> 5, lane = tid & 31;
    const int g    = lane >> 2, t4 = lane & 3;
    const int bx   = blockIdx.x, mb = blockIdx.y;
    const int z    = bx / 24, y0 = (bx - z * 24) * 4;

    const int yp = wid >> 1;           // warp-uniform y row (0..3)
    const int xw = (wid & 1) * 48;     // warp x base

    // ---- raw tile slot descriptors (loop-invariant) ----
    int  roff[8]; bool rvalid[8];
    #pragma unroll
    for (int k = 0; k < 8; k++) {
        int i = tid + k * 256;
        if (i < RAW_E) {
            int row = i / 100, col = i - row * 100;
            int dzr = row / 6, yy = row - dzr * 6;
            int zz = z + dzr - 1;
            int gy = y0 + yy - 1;
            int gx = col - 1;
            rvalid[k] = (col < 98) && ((unsigned)zz < D_) && ((unsigned)gy < H_) && ((unsigned)gx < W_);
            roff[k] = zz * HW + gy * 96 + gx;
        } else { rvalid[k] = false; roff[k] = 0; }
    }

    // ---- per-parity tap bases (loop-invariant; invalid -> zero pad) ----
    int tb[2][4];
    #pragma unroll
    for (int par = 0; par < 2; par++) {
        #pragma unroll
        for (int q = 0; q < 4; q++) {
            int t = par * 16 + 2 * t4 + (q & 1) + (q >> 1) * 8;
            if (t < 27) {
                int dz = t / 9, r9 = t - dz * 9;
                int dy = r9 / 3, dx = r9 - dy * 3;
                tb[par][q] = (dz * 6 + dy + yp) * 100 + xw + g + dx;
            } else {
                tb[par][q] = RAW_E + g;
            }
        }
    }

    // ---- A staging descriptors ----
    const int kp = tid & 7, rb = tid >> 3;        // rb 0..31
    const uint32_t offA = (uint32_t)(((lane & 7) + ((lane >> 3) & 1) * 8) * KS + (lane >> 4) * 8) * 2;
    const uint32_t baAH = smem_u32(AsH), baAL = smem_u32(AsL);

    float acc[4][6][4];
    #pragma unroll
    for (int mt = 0; mt < 4; mt++)
        #pragma unroll
        for (int nt = 0; nt < 6; nt++)
            #pragma unroll
            for (int j = 0; j < 4; j++) acc[mt][nt][j] = 0.f;

    uint32_t avh[2], avl[2];
    float rreg[8];

    auto loadA = [&](int c) {
        const size_t ab = (size_t)(mb * 64 + rb) * Kpad + c * 16 + 2 * kp;
        avh[0] = *(const uint32_t*)(Ahi + ab);
        avh[1] = *(const uint32_t*)(Ahi + ab + (size_t)32 * Kpad);
        avl[0] = *(const uint32_t*)(Alo + ab);
        avl[1] = *(const uint32_t*)(Alo + ab + (size_t)32 * Kpad);
    };
    auto stsA = [&](int st) {
        #pragma unroll
        for (int r = 0; r < 2; r++) {
            int m = rb + r * 32;
            *(uint32_t*)&AsH[st][m * KS + 2 * kp] = avh[r];
            *(uint32_t*)&AsL[st][m * KS + 2 * kp] = avl[r];
        }
    };

    // ---- prologue: zero pads, raw(ci=0), A(chunk 0) ----
    if (tid < RAW_T - RAW_E) {
        rawS[0][RAW_E + tid] = 0.f;
        rawS[1][RAW_E + tid] = 0.f;
    }
    #pragma unroll
    for (int k = 0; k < 8; k++) rreg[k] = rvalid[k] ? __ldg(in + roff[k]) : 0.f;
    #pragma unroll
    for (int k = 0; k < 8; k++) {
        int i = tid + k * 256;
        if (i < RAW_E) rawS[0][i] = rreg[k];
    }
    loadA(0);
    stsA(0);
    __syncthreads();

    for (int c = 0; c < NC2; c++) {
        const int ci = c >> 1, st = c & 1;
        const bool more = (c + 1 < NC2);
        const bool evenPf = (!(c & 1)) && (ci + 1 < Cin);
        const bool oddSt  = ((c & 1))  && (ci + 1 < Cin);

        if (more) loadA(c + 1);
        if (evenPf) {
            const float* inp = in + (size_t)(ci + 1) * VOX;
            #pragma unroll
            for (int k = 0; k < 8; k++) rreg[k] = rvalid[k] ? __ldg(inp + roff[k]) : 0.f;
        }

        // ---- A fragments (all 4 m-tiles, hi+lo), hoisted out of nt loop ----
        const uint32_t sa = st * (AS_E * 2);
        uint32_t ah[4][4], al[4][4];
        #pragma unroll
        for (int mt = 0; mt < 4; mt++) {
            ldsm4(ah[mt], baAH + sa + (mt * 16) * (KS*2) + offA);
            ldsm4(al[mt], baAL + sa + (mt * 16) * (KS*2) + offA);
        }

        // ---- per n-tile: build B, 12 MMAs ----
        const float* rp = rawS[ci & 1];
        const int* tq = tb[st];
        #pragma unroll
        for (int nt = 0; nt < 6; nt++) {
            const int o = nt * 8;
            float vA = rp[tq[0] + o];
            float vB = rp[tq[1] + o];
            float vC = rp[tq[2] + o];
            float vD = rp[tq[3] + o];
            uint32_t b0h = prmt_hi(vA, vB);
            uint32_t b1h = prmt_hi(vC, vD);
            uint32_t b0l = cvt_bf2(vB - trunc16(vB), vA - trunc16(vA));
            uint32_t b1l = cvt_bf2(vD - trunc16(vD), vC - trunc16(vC));
            #pragma unroll
            for (int mt = 0; mt < 4; mt++) {
                mma16816(acc[mt][nt], ah[mt], b0h, b1h);
                mma16816(acc[mt][nt], al[mt], b0h, b1h);
                mma16816(acc[mt][nt], ah[mt], b0l, b1l);
            }
        }

        if (oddSt) {
            float* rw = rawS[(ci + 1) & 1];
            #pragma unroll
            for (int k = 0; k < 8; k++) {
                int i = tid + k * 256;
                if (i < RAW_E) rw[i] = rreg[k];
            }
        }
        if (more) stsA(1 - st);
        __syncthreads();
    }

    // epilogue: Cout multiple of 64 for all mma layers
    const size_t zy = (size_t)z * HW + (size_t)(y0 + yp) * 96;
    #pragma unroll
    for (int mt = 0; mt < 4; mt++) {
        int co = mb * 64 + mt * 16 + g;
        #pragma unroll
        for (int nt = 0; nt < 6; nt++) {
            int x = xw + nt * 8 + t4 * 2;
            float* op = out + (size_t)co * VOX + zy + x;
            *(float2*)op = make_float2(acc[mt][nt][0], acc[mt][nt][1]);
            *(float2*)(op + (size_t)8 * VOX) = make_float2(acc[mt][nt][2], acc[mt][nt][3]);
        }
    }
}

// ============================================================================
// Scalar FFMA2 conv (head Cin=1 and tail Cout=6 layers).
// ============================================================================
#define HALO 1080
#define WTOT 864

__global__ __launch_bounds__(256, 2)
void conv3d_k(const float* __restrict__ in, const float* __restrict__ w,
              float* __restrict__ out, int Cin, int Cout, int deconv)
{
    __shared__ __align__(16) float  in_s[HALO];
    __shared__ __align__(8)  float2 w_s2[WTOT];

    const int tid = threadIdx.x;
    const int tx  = tid & 3;
    const int ty  = (tid >> 2) & 7;
    const int cg  = tid >> 5;

    const int x0 = blockIdx.x * 32;
    const int y0 = (blockIdx.y % 12) * 8;
    const int zb = blockIdx.y / 12;
    const int coBase = blockIdx.z * 32;

    int  hoff[5]; bool hval[5];
    #pragma unroll
    for (int k = 0; k < 5; k++) {
        int i = tid + k * 256;
        if (i < HALO) {
            int dz  = i / 360;
            int rem = i - dz * 360;
            int yy  = rem / 36;
            int xx  = rem - yy * 36;
            int z = zb + dz - 1, y = y0 + yy - 1, x = x0 + xx - 1;
            hval[k] = ((unsigned)z < D_) && ((unsigned)y < H_) && ((unsigned)x < W_) && (xx < 34);
            hoff[k] = z * HW + y * W_ + x;
        } else { hval[k] = false; hoff[k] = 0; }
    }
    int wbase[4]; bool wvalid[4];
    const int wstride = deconv ? Cout * 27 : 27;
    #pragma unroll
    for (int k = 0; k < 4; k++) {
        int idx = tid + k * 256;
        if (idx < WTOT) {
            int co = idx / 27, t = idx - co * 27;
            int coG = coBase + co;
            wvalid[k] = (coG < Cout);
            wbase[k]  = deconv ? (coG * 27 + (26 - t)) : (coG * Cin * 27 + t);
        } else { wvalid[k] = false; wbase[k] = 0; }
    }

    u64 acc[4][4];
    #pragma unroll
    for (int c = 0; c < 4; c++)
        #pragma unroll
        for (int j = 0; j < 4; j++) acc[c][j] = 0ull;

    float hreg[5], wreg[4];
    #pragma unroll
    for (int k = 0; k < 5; k++) hreg[k] = hval[k] ? __ldg(in + hoff[k]) : 0.f;
    #pragma unroll
    for (int k = 0; k < 4; k++) wreg[k] = wvalid[k] ? __ldg(w + wbase[k]) : 0.f;

    for (int ci = 0; ci < Cin; ci++) {
        #pragma unroll
        for (int k = 0; k < 5; k++) {
            int i = tid + k * 256;
            if (i < HALO) in_s[i] = hreg[k];
        }
        #pragma unroll
        for (int k = 0; k < 4; k++) {
            int idx = tid + k * 256;
            if (idx < WTOT) w_s2[idx] = make_float2(wreg[k], wreg[k]);
        }
        __syncthreads();

        if (ci + 1 < Cin) {
            const float* inp = in + (size_t)(ci + 1) * VOX;
            #pragma unroll
            for (int k = 0; k < 5; k++) hreg[k] = hval[k] ? __ldg(inp + hoff[k]) : 0.f;
            const float* wp_ = w + (size_t)(ci + 1) * wstride;
            #pragma unroll
            for (int k = 0; k < 4; k++) wreg[k] = wvalid[k] ? __ldg(wp_ + wbase[k]) : 0.f;
        }

        const float2* wp = &w_s2[cg * 4 * 27];
        #pragma unroll
        for (int dz = 0; dz < 3; dz++) {
            #pragma unroll
            for (int dy = 0; dy < 3; dy++) {
                const float* row = &in_s[(dz * 10 + ty + dy) * 36 + tx * 8];
                float4 a4 = *(const float4*)row;
                float4 b4 = *(const float4*)(row + 4);
                float2 c2 = *(const float2*)(row + 8);
                float v[10] = {a4.x, a4.y, a4.z, a4.w, b4.x, b4.y, b4.z, b4.w, c2.x, c2.y};
                u64 p[9];
                #pragma unroll
                for (int i = 0; i < 9; i++) p[i] = pk2(v[i], v[i + 1]);
                const int tb = dz * 9 + dy * 3;
                #pragma unroll
                for (int co = 0; co < 4; co++) {
                    const float2* wc = wp + co * 27 + tb;
                    u64 w0 = *(const u64*)(wc + 0);
                    fma2(acc[co][0], p[0], w0); fma2(acc[co][1], p[2], w0);
                    fma2(acc[co][2], p[4], w0); fma2(acc[co][3], p[6], w0);
                    u64 w1 = *(const u64*)(wc + 1);
                    fma2(acc[co][0], p[1], w1); fma2(acc[co][1], p[3], w1);
                    fma2(acc[co][2], p[5], w1); fma2(acc[co][3], p[7], w1);
                    u64 w2 = *(const u64*)(wc + 2);
                    fma2(acc[co][0], p[2], w2); fma2(acc[co][1], p[4], w2);
                    fma2(acc[co][2], p[6], w2); fma2(acc[co][3], p[8], w2);
                }
            }
        }
        __syncthreads();
    }

    const int xo = x0 + tx * 8;
    const size_t base = (size_t)zb * HW + (y0 + ty) * W_ + xo;
    #pragma unroll
    for (int co = 0; co < 4; co++) {
        int coG = coBase + cg * 4 + co;
        if (coG < Cout) {
            float2 q0 = unpk2(acc[co][0]);
            float2 q1 = unpk2(acc[co][1]);
            float2 q2 = unpk2(acc[co][2]);
            float2 q3 = unpk2(acc[co][3]);
            float* op = out + (size_t)coG * VOX + base;
            *(float4*)(op + 0) = make_float4(q0.x, q0.y, q1.x, q1.y);
            *(float4*)(op + 4) = make_float4(q2.x, q2.y, q3.x, q3.y);
        }
    }
}

// ============================ SRU kernels ============================
__global__ void si_sru_k(const float* __restrict__ g, float* __restrict__ out,
                         const float* __restrict__ add, int C, int rev)
{
    int tid = blockIdx.x * blockDim.x + threadIdx.x;
    int total = C * HW;
    if (tid >= total) return;
    int c  = tid / HW;
    int yx = tid - c * HW;

    const float* Wp = g + (size_t)(0 * C + c) * VOX + yx;
    const float* Fp = g + (size_t)(1 * C + c) * VOX + yx;
    const float* Rp = g + (size_t)(2 * C + c) * VOX + yx;
    const float* Xp = g + (size_t)(3 * C + c) * VOX + yx;
    float*       op = out + (size_t)c * VOX + yx;
    const float* ap = add ? add + (size_t)c * VOX + yx : nullptr;

    int off = rev ? (D_ - 1) * HW : 0;
    int zs  = rev ? -HW : HW;

    float f = sigm(Fp[off]);
    float Cc = 1.f - f;
    float r = sigm(Rp[off]);
    float h = r * Cc + (1.f - r) * tanhf(Xp[off]);
    op[off] = h + (ap ? ap[off] : 0.f);

    for (int t = 1; t < D_; t++) {
        off += zs;
        f  = sigm(Fp[off]);
        Cc = f * Cc + (1.f - f) * tanhf(Wp[off]);
        r  = sigm(Rp[off]);
        h  = r * Cc + (1.f - r) * tanhf(Xp[off]);
        op[off] = h + (ap ? ap[off] : 0.f);
    }
}

__global__ void do_sru_k(const float* __restrict__ g, float* __restrict__ out,
                         const float* __restrict__ add, int C)
{
    int tid = blockIdx.x * blockDim.x + threadIdx.x;
    int total = C * HW;
    if (tid >= total) return;
    int c  = tid / HW;
    int yx = tid - c * HW;

    const float* Wp = g + (size_t)(0 * C + c) * VOX + yx;
    const float* F1 = g + (size_t)(1 * C + c) * VOX + yx;
    const float* F2 = g + (size_t)(2 * C + c) * VOX + yx;
    const float* R1 = g + (size_t)(3 * C + c) * VOX + yx;
    const float* R2 = g + (size_t)(4 * C + c) * VOX + yx;
    const float* Xp = g + (size_t)(5 * C + c) * VOX + yx;
    float*       op = out + (size_t)c * VOX + yx;
    const float* ap = add ? add + (size_t)c * VOX + yx : nullptr;

    {
        float f = sigm(F1[0]);
        float Cc = 1.f - f;
        float r = sigm(R1[0]);
        op[0] = r * Cc + (1.f - r) * tanhf(Xp[0]);
        int off = 0;
        for (int t = 1; t < D_; t++) {
            off += HW;
            f  = sigm(F1[off]);
            Cc = f * Cc + (1.f - f) * tanhf(Wp[off]);
            r  = sigm(R1[off]);
            op[off] = r * Cc + (1.f - r) * tanhf(Xp[off]);
        }
    }
    {
        int off = (D_ - 1) * HW;
        float f = sigm(F2[off]);
        float Cc = 1.f - f;
        float r = sigm(R2[off]);
        float h = r * Cc + (1.f - r) * tanhf(Xp[off]);
        op[off] = op[off] + h + (ap ? ap[off] : 0.f);
        for (int t = 1; t < D_; t++) {
            off -= HW;
            f  = sigm(F2[off]);
            Cc = f * Cc + (1.f - f) * tanhf(Wp[off]);
            r  = sigm(R2[off]);
            h  = r * Cc + (1.f - r) * tanhf(Xp[off]);
            op[off] = op[off] + h + (ap ? ap[off] : 0.f);
        }
    }
}

// ============================ host ============================
static __nv_bfloat16 *s_Ahi, *s_Alo;

static inline void conv_tc(const float* in, const float* w, float* out,
                           int Cin, int Cout, int deconv)
{
    int Kpad = Cin * 32;
    int total = Cout * Kpad;
    prep_k<<<(total + 255) / 256, 256>>>(w, s_Ahi, s_Alo, Cin, Cout, Kpad, deconv, total);
    dim3 grid(D_ * 24, Cout / 64);
    conv_mma_k<<<grid, 256>>>(in, s_Ahi, s_Alo, out, Cin, Kpad, Cin * 2);
}

static inline void conv_scalar(const float* in, const float* w, float* out,
                               int Cin, int Cout, int deconv)
{
    dim3 grid(W_ / 32, (H_ / 8) * D_, (Cout + 31) / 32);
    conv3d_k<<<grid, 256>>>(in, w, out, Cin, Cout, deconv);
}

static inline void si_launch(const float* gbuf, float* out, const float* add, int C, int rev)
{
    int n = C * HW;
    si_sru_k<<<(n + 255) / 256, 256>>>(gbuf, out, add, C, rev);
}
static inline void do_launch(const float* gbuf, float* out, const float* add, int C)
{
    int n = C * HW;
    do_sru_k<<<(n + 255) / 256, 256>>>(gbuf, out, add, C);
}

extern "C" void kernel_launch(void* const* d_in, const int* in_sizes, int n_in,
                              void* d_out, int out_size)
{
    (void)in_sizes; (void)n_in; (void)out_size;
    const float* x      = (const float*)d_in[0];
    const float* w_head = (const float*)d_in[1];
    const float* w_e0   = (const float*)d_in[2];
    const float* w_e1   = (const float*)d_in[3];
    const float* w_d0   = (const float*)d_in[4];
    const float* w_d1   = (const float*)d_in[5];
    const float* w_tail = (const float*)d_in[6];
    float* out = (float*)d_out;

    float *gc, *gh, *ge0, *ge1, *gd0, *gd1;
    cudaGetSymbolAddress((void**)&gc,  g_conv);
    cudaGetSymbolAddress((void**)&gh,  g_h);
    cudaGetSymbolAddress((void**)&ge0, g_e0);
    cudaGetSymbolAddress((void**)&ge1, g_e1);
    cudaGetSymbolAddress((void**)&gd0, g_d0);
    cudaGetSymbolAddress((void**)&gd1, g_d1);
    cudaGetSymbolAddress((void**)&s_Ahi, g_Ahi);
    cudaGetSymbolAddress((void**)&s_Alo, g_Alo);

    // h = do_sru(x, w_head)          (scalar: Cin=1)
    conv_scalar(x, w_head, gc, 1, 96, 0);
    do_launch(gc, gh, nullptr, 16);
    // e0 = si_sru(h, w_e0, fwd)      (mma: 16 -> 128)
    conv_tc(gh, w_e0, gc, 16, 128, 0);
    si_launch(gc, ge0, nullptr, 32, 0);
    // e1 = si_sru(e0, w_e1, rev)     (mma: 32 -> 256)
    conv_tc(ge0, w_e1, gc, 32, 256, 0);
    si_launch(gc, ge1, nullptr, 64, 1);
    // d0 = si_sru(e1, w_d0, fwd, deconv) + e0   (mma: 64 -> 128)
    conv_tc(ge1, w_d0, gc, 64, 128, 1);
    si_launch(gc, gd0, ge0, 32, 0);
    // d1 = si_sru(d0, w_d1, rev, deconv) + h    (mma: 32 -> 64)
    conv_tc(gd0, w_d1, gc, 32, 64, 1);
    si_launch(gc, gd1, gh, 16, 1);
    // out = do_sru(d1, w_tail, deconv) + x      (scalar: Cout=6)
    conv_scalar(gd1, w_tail, gc, 16, 6, 1);
    do_launch(gc, out, x, 1);
}

// round 11
// speedup vs baseline: 1.1806x; 1.1806x over previous
#include <cuda_runtime.h>
#include <cuda_bf16.h>
#include <math.h>
#include <stdint.h>

#define D_ 31
#define H_ 96
#define W_ 96
#define HW (H_*W_)        // 9216
#define VOX (D_*HW)       // 285696

// ---- scratch (device globals; no allocation allowed) ----
__device__ float g_conv[256 * VOX];
__device__ float g_h  [16 * VOX];
__device__ float g_e0 [32 * VOX];
__device__ float g_e1 [64 * VOX];
__device__ float g_d0 [32 * VOX];
__device__ float g_d1 [16 * VOX];
__device__ __nv_bfloat16 g_Ahi[262144];   // weights bf16-hi, [M x Kpad]
__device__ __nv_bfloat16 g_Alo[262144];   // weights bf16-lo

__device__ __forceinline__ float sigm(float a) { return 1.0f / (1.0f + expf(-a)); }

typedef unsigned long long u64;
__device__ __forceinline__ void fma2(u64& d, u64 a, u64 b) {
    asm("fma.rn.f32x2 %0, %1, %2, %0;" : "+l"(d) : "l"(a), "l"(b));
}
__device__ __forceinline__ u64 pk2(float x, float y) {
    u64 r; asm("mov.b64 %0, {%1, %2};" : "=l"(r) : "f"(x), "f"(y)); return r;
}
__device__ __forceinline__ float2 unpk2(u64 a) {
    float x, y; asm("mov.b64 {%0, %1}, %2;" : "=f"(x), "=f"(y) : "l"(a));
    return make_float2(x, y);
}
__device__ __forceinline__ uint32_t smem_u32(const void* p) {
    uint32_t a;
    asm("{ .reg .u64 t; cvta.to.shared.u64 t, %1; cvt.u32.u64 %0, t; }" : "=r"(a) : "l"(p));
    return a;
}
__device__ __forceinline__ void ldsm4(uint32_t* r, uint32_t addr) {
    asm volatile("ldmatrix.sync.aligned.m8n8.x4.shared.b16 {%0,%1,%2,%3}, [%4];"
                 : "=r"(r[0]), "=r"(r[1]), "=r"(r[2]), "=r"(r[3]) : "r"(addr));
}
__device__ __forceinline__ void mma16816(float* c, const uint32_t* a, uint32_t b0, uint32_t b1) {
    asm volatile("mma.sync.aligned.m16n8k16.row.col.f32.bf16.bf16.f32 "
                 "{%0,%1,%2,%3},{%4,%5,%6,%7},{%8,%9},{%0,%1,%2,%3};"
                 : "+f"(c[0]), "+f"(c[1]), "+f"(c[2]), "+f"(c[3])
                 : "r"(a[0]), "r"(a[1]), "r"(a[2]), "r"(a[3]), "r"(b0), "r"(b1));
}
// pack truncated-hi bf16 of two floats: low half <- a, high half <- b
__device__ __forceinline__ uint32_t prmt_hi(float a, float b) {
    uint32_t r;
    asm("prmt.b32 %0, %1, %2, 0x7632;" : "=r"(r) : "r"(__float_as_uint(a)), "r"(__float_as_uint(b)));
    return r;
}
// pack rn bf16 of two floats: high half <- hi, low half <- lo
__device__ __forceinline__ uint32_t cvt_bf2(float hi, float lo) {
    uint32_t r;
    asm("cvt.rn.bf16x2.f32 %0, %1, %2;" : "=r"(r) : "f"(hi), "f"(lo));
    return r;
}
__device__ __forceinline__ float trunc16(float v) {
    return __uint_as_float(__float_as_uint(v) & 0xFFFF0000u);
}

// ============================================================================
// Weight prep: split fp32 weights into bf16 hi/lo, layout A[m][k], k=ci*32+t.
// ============================================================================
__global__ void prep_k(const float* __restrict__ w, __nv_bfloat16* __restrict__ Ahi,
                       __nv_bfloat16* __restrict__ Alo,
                       int Cin, int Cout, int Kpad, int deconv, int total)
{
    int i = blockIdx.x * 256 + threadIdx.x;
    if (i >= total) return;
    int m = i / Kpad, k = i - m * Kpad;
    int t = k & 31, ci = k >> 5;
    float v = 0.f;
    if (t < 27 && m < Cout && ci < Cin)
        v = deconv ? w[((size_t)ci * Cout + m) * 27 + (26 - t)]
                   : w[((size_t)m * Cin + ci) * 27 + t];
    __nv_bfloat16 h = __float2bfloat16(v);
    Ahi[i] = h;
    Alo[i] = __float2bfloat16(v - __bfloat162float(h));
}

// ============================================================================
// Tensor-core implicit-GEMM conv. Block tile: M=64 co, N=192 (96x * 2y).
// 8 warps, each full M=64 x 24 N. Barrier once per ci (K=32, 2 chunks of 16):
// chunk1's LDSM/build overlaps chunk0's MMA queue (no barrier between).
// A staged per-ci via 1 LDG.128 + 1 STS.128 per thread per array.
// ============================================================================
#define KS 40               // padded A row stride (elems); 80B rows, 16B aligned
#define ABUF (64*KS)        // elems per stage (5120 B)
#define RAW_E 1200          // 12 rows * 100
#define RAW_T 1328          // + 128 zero-pad floats

__global__ __launch_bounds__(256, 2)
void conv_mma_k(const float* __restrict__ in,
                const __nv_bfloat16* __restrict__ Ahi,
                const __nv_bfloat16* __restrict__ Alo,
                float* __restrict__ out,
                int Cin, int Kpad)
{
    __shared__ __align__(16) __nv_bfloat16 AsH[2][ABUF], AsL[2][ABUF];
    __shared__ __align__(16) float rawS[2][RAW_T];

    const int tid  = threadIdx.x;
    const int wid  = tid >> 5, lane = tid & 31;
    const int g    = lane >> 2, t4 = lane & 3;
    const int bx   = blockIdx.x, mb = blockIdx.y;
    const int z    = bx / 48, y0 = (bx - z * 48) * 2;

    const int yp = wid >> 2;           // warp-uniform y row (0/1)
    const int xw = (wid & 3) * 24;     // warp x base

    // ---- raw tile slot descriptors (loop-invariant) ----
    int  roff[5]; bool rvalid[5];
    #pragma unroll
    for (int k = 0; k < 5; k++) {
        int i = tid + k * 256;
        if (i < RAW_E) {
            int row = i / 100, col = i - row * 100;
            int zz = z + (row >> 2) - 1;
            int gy = y0 + (row & 3) - 1;
            int gx = col - 1;
            rvalid[k] = (col < 98) && ((unsigned)zz < D_) && ((unsigned)gy < H_) && ((unsigned)gx < W_);
            roff[k] = zz * HW + gy * 96 + gx;
        } else { rvalid[k] = false; roff[k] = 0; }
    }

    // ---- per-sub tap bases (loop-invariant; invalid -> zero pad) ----
    int tb[2][4];
    #pragma unroll
    for (int par = 0; par < 2; par++) {
        #pragma unroll
        for (int q = 0; q < 4; q++) {
            int t = par * 16 + 2 * t4 + (q & 1) + (q >> 1) * 8;
            if (t < 27) {
                int dz = t / 9, r9 = t - dz * 9;
                int dy = r9 / 3, dx = r9 - dy * 3;
                tb[par][q] = (dz * 4 + dy + yp) * 100 + xw + g + dx;
            } else {
                tb[par][q] = RAW_E + g;
            }
        }
    }

    // ---- A staging descriptors: thread = (row = tid>>2, koct = tid&3) ----
    const int arow = tid >> 2, akoct = tid & 3;
    const uint32_t offA = (uint32_t)(((lane & 7) + ((lane >> 3) & 1) * 8) * KS + (lane >> 4) * 8) * 2;
    const uint32_t baAH = smem_u32(AsH), baAL = smem_u32(AsL);

    float acc[4][3][4];
    #pragma unroll
    for (int mt = 0; mt < 4; mt++)
        #pragma unroll
        for (int nt = 0; nt < 3; nt++)
            #pragma unroll
            for (int j = 0; j < 4; j++) acc[mt][nt][j] = 0.f;

    uint4 a4h, a4l;
    float rreg[5];

    auto loadAci = [&](int ci) {
        const size_t ab = (size_t)(mb * 64 + arow) * Kpad + ci * 32 + akoct * 8;
        a4h = *(const uint4*)(Ahi + ab);
        a4l = *(const uint4*)(Alo + ab);
    };
    auto stsAci = [&](int buf) {
        *(uint4*)&AsH[buf][arow * KS + akoct * 8] = a4h;
        *(uint4*)&AsL[buf][arow * KS + akoct * 8] = a4l;
    };
    auto loadRaw = [&](int ci) {
        const float* inp = in + (size_t)ci * VOX;
        #pragma unroll
        for (int k = 0; k < 5; k++) rreg[k] = rvalid[k] ? __ldg(inp + roff[k]) : 0.f;
    };
    auto stsRaw = [&](int buf) {
        #pragma unroll
        for (int k = 0; k < 5; k++) {
            int i = tid + k * 256;
            if (i < RAW_E) rawS[buf][i] = rreg[k];
        }
    };

    // ---- prologue: zero pads, raw(0), A(0) ----
    if (tid < RAW_T - RAW_E) {
        rawS[0][RAW_E + tid] = 0.f;
        rawS[1][RAW_E + tid] = 0.f;
    }
    loadRaw(0); stsRaw(0);
    loadAci(0); stsAci(0);
    __syncthreads();

    for (int ci = 0; ci < Cin; ci++) {
        const int buf = ci & 1;
        const bool more = (ci + 1 < Cin);

        if (more) { loadRaw(ci + 1); loadAci(ci + 1); }

        const float* rp = rawS[buf];
        const uint32_t saH = baAH + buf * (ABUF * 2);
        const uint32_t saL = baAL + buf * (ABUF * 2);

        #pragma unroll
        for (int sub = 0; sub < 2; sub++) {
            // A fragments for this 16-k chunk
            uint32_t ah[4][4], al[4][4];
            #pragma unroll
            for (int mt = 0; mt < 4; mt++) {
                ldsm4(ah[mt], saH + (mt * 16) * (KS*2) + offA + sub * 32);
                ldsm4(al[mt], saL + (mt * 16) * (KS*2) + offA + sub * 32);
            }
            // B fragments + 36 MMAs
            const int* tq = tb[sub];
            #pragma unroll
            for (int nt = 0; nt < 3; nt++) {
                const int o = nt * 8;
                float vA = rp[tq[0] + o];
                float vB = rp[tq[1] + o];
                float vC = rp[tq[2] + o];
                float vD = rp[tq[3] + o];
                uint32_t b0h = prmt_hi(vA, vB);
                uint32_t b1h = prmt_hi(vC, vD);
                uint32_t b0l = cvt_bf2(vB - trunc16(vB), vA - trunc16(vA));
                uint32_t b1l = cvt_bf2(vD - trunc16(vD), vC - trunc16(vC));
                #pragma unroll
                for (int mt = 0; mt < 4; mt++) {
                    mma16816(acc[mt][nt], ah[mt], b0h, b1h);
                    mma16816(acc[mt][nt], al[mt], b0h, b1h);
                    mma16816(acc[mt][nt], ah[mt], b0l, b1l);
                }
            }
        }

        if (more) { stsRaw(1 - buf); stsAci(1 - buf); }
        __syncthreads();
    }

    // epilogue: Cout multiple of 64 for all mma layers
    const size_t zy = (size_t)z * HW + (size_t)(y0 + yp) * 96;
    #pragma unroll
    for (int mt = 0; mt < 4; mt++) {
        int co = mb * 64 + mt * 16 + g;
        #pragma unroll
        for (int nt = 0; nt < 3; nt++) {
            int x = xw + nt * 8 + t4 * 2;
            float* op = out + (size_t)co * VOX + zy + x;
            *(float2*)op = make_float2(acc[mt][nt][0], acc[mt][nt][1]);
            *(float2*)(op + (size_t)8 * VOX) = make_float2(acc[mt][nt][2], acc[mt][nt][3]);
        }
    }
}

// ============================================================================
// Scalar FFMA2 conv (head Cin=1 and tail Cout=6 layers).
// ============================================================================
#define HALO 1080
#define WTOT 864

__global__ __launch_bounds__(256, 2)
void conv3d_k(const float* __restrict__ in, const float* __restrict__ w,
              float* __restrict__ out, int Cin, int Cout, int deconv)
{
    __shared__ __align__(16) float  in_s[HALO];
    __shared__ __align__(8)  float2 w_s2[WTOT];

    const int tid = threadIdx.x;
    const int tx  = tid & 3;
    const int ty  = (tid >> 2) & 7;
    const int cg  = tid >> 5;

    const int x0 = blockIdx.x * 32;
    const int y0 = (blockIdx.y % 12) * 8;
    const int zb = blockIdx.y / 12;
    const int coBase = blockIdx.z * 32;

    int  hoff[5]; bool hval[5];
    #pragma unroll
    for (int k = 0; k < 5; k++) {
        int i = tid + k * 256;
        if (i < HALO) {
            int dz  = i / 360;
            int rem = i - dz * 360;
            int yy  = rem / 36;
            int xx  = rem - yy * 36;
            int z = zb + dz - 1, y = y0 + yy - 1, x = x0 + xx - 1;
            hval[k] = ((unsigned)z < D_) && ((unsigned)y < H_) && ((unsigned)x < W_) && (xx < 34);
            hoff[k] = z * HW + y * W_ + x;
        } else { hval[k] = false; hoff[k] = 0; }
    }
    int wbase[4]; bool wvalid[4];
    const int wstride = deconv ? Cout * 27 : 27;
    #pragma unroll
    for (int k = 0; k < 4; k++) {
        int idx = tid + k * 256;
        if (idx < WTOT) {
            int co = idx / 27, t = idx - co * 27;
            int coG = coBase + co;
            wvalid[k] = (coG < Cout);
            wbase[k]  = deconv ? (coG * 27 + (26 - t)) : (coG * Cin * 27 + t);
        } else { wvalid[k] = false; wbase[k] = 0; }
    }

    u64 acc[4][4];
    #pragma unroll
    for (int c = 0; c < 4; c++)
        #pragma unroll
        for (int j = 0; j < 4; j++) acc[c][j] = 0ull;

    float hreg[5], wreg[4];
    #pragma unroll
    for (int k = 0; k < 5; k++) hreg[k] = hval[k] ? __ldg(in + hoff[k]) : 0.f;
    #pragma unroll
    for (int k = 0; k < 4; k++) wreg[k] = wvalid[k] ? __ldg(w + wbase[k]) : 0.f;

    for (int ci = 0; ci < Cin; ci++) {
        #pragma unroll
        for (int k = 0; k < 5; k++) {
            int i = tid + k * 256;
            if (i < HALO) in_s[i] = hreg[k];
        }
        #pragma unroll
        for (int k = 0; k < 4; k++) {
            int idx = tid + k * 256;
            if (idx < WTOT) w_s2[idx] = make_float2(wreg[k], wreg[k]);
        }
        __syncthreads();

        if (ci + 1 < Cin) {
            const float* inp = in + (size_t)(ci + 1) * VOX;
            #pragma unroll
            for (int k = 0; k < 5; k++) hreg[k] = hval[k] ? __ldg(inp + hoff[k]) : 0.f;
            const float* wp_ = w + (size_t)(ci + 1) * wstride;
            #pragma unroll
            for (int k = 0; k < 4; k++) wreg[k] = wvalid[k] ? __ldg(wp_ + wbase[k]) : 0.f;
        }

        const float2* wp = &w_s2[cg * 4 * 27];
        #pragma unroll
        for (int dz = 0; dz < 3; dz++) {
            #pragma unroll
            for (int dy = 0; dy < 3; dy++) {
                const float* row = &in_s[(dz * 10 + ty + dy) * 36 + tx * 8];
                float4 a4 = *(const float4*)row;
                float4 b4 = *(const float4*)(row + 4);
                float2 c2 = *(const float2*)(row + 8);
                float v[10] = {a4.x, a4.y, a4.z, a4.w, b4.x, b4.y, b4.z, b4.w, c2.x, c2.y};
                u64 p[9];
                #pragma unroll
                for (int i = 0; i < 9; i++) p[i] = pk2(v[i], v[i + 1]);
                const int tb = dz * 9 + dy * 3;
                #pragma unroll
                for (int co = 0; co < 4; co++) {
                    const float2* wc = wp + co * 27 + tb;
                    u64 w0 = *(const u64*)(wc + 0);
                    fma2(acc[co][0], p[0], w0); fma2(acc[co][1], p[2], w0);
                    fma2(acc[co][2], p[4], w0); fma2(acc[co][3], p[6], w0);
                    u64 w1 = *(const u64*)(wc + 1);
                    fma2(acc[co][0], p[1], w1); fma2(acc[co][1], p[3], w1);
                    fma2(acc[co][2], p[5], w1); fma2(acc[co][3], p[7], w1);
                    u64 w2 = *(const u64*)(wc + 2);
                    fma2(acc[co][0], p[2], w2); fma2(acc[co][1], p[4], w2);
                    fma2(acc[co][2], p[6], w2); fma2(acc[co][3], p[8], w2);
                }
            }
        }
        __syncthreads();
    }

    const int xo = x0 + tx * 8;
    const size_t base = (size_t)zb * HW + (y0 + ty) * W_ + xo;
    #pragma unroll
    for (int co = 0; co < 4; co++) {
        int coG = coBase + cg * 4 + co;
        if (coG < Cout) {
            float2 q0 = unpk2(acc[co][0]);
            float2 q1 = unpk2(acc[co][1]);
            float2 q2 = unpk2(acc[co][2]);
            float2 q3 = unpk2(acc[co][3]);
            float* op = out + (size_t)coG * VOX + base;
            *(float4*)(op + 0) = make_float4(q0.x, q0.y, q1.x, q1.y);
            *(float4*)(op + 4) = make_float4(q2.x, q2.y, q3.x, q3.y);
        }
    }
}

// ============================ SRU kernels ============================
__global__ void si_sru_k(const float* __restrict__ g, float* __restrict__ out,
                         const float* __restrict__ add, int C, int rev)
{
    int tid = blockIdx.x * blockDim.x + threadIdx.x;
    int total = C * HW;
    if (tid >= total) return;
    int c  = tid / HW;
    int yx = tid - c * HW;

    const float* Wp = g + (size_t)(0 * C + c) * VOX + yx;
    const float* Fp = g + (size_t)(1 * C + c) * VOX + yx;
    const float* Rp = g + (size_t)(2 * C + c) * VOX + yx;
    const float* Xp = g + (size_t)(3 * C + c) * VOX + yx;
    float*       op = out + (size_t)c * VOX + yx;
    const float* ap = add ? add + (size_t)c * VOX + yx : nullptr;

    int off = rev ? (D_ - 1) * HW : 0;
    int zs  = rev ? -HW : HW;

    float f = sigm(Fp[off]);
    float Cc = 1.f - f;
    float r = sigm(Rp[off]);
    float h = r * Cc + (1.f - r) * tanhf(Xp[off]);
    op[off] = h + (ap ? ap[off] : 0.f);

    for (int t = 1; t < D_; t++) {
        off += zs;
        f  = sigm(Fp[off]);
        Cc = f * Cc + (1.f - f) * tanhf(Wp[off]);
        r  = sigm(Rp[off]);
        h  = r * Cc + (1.f - r) * tanhf(Xp[off]);
        op[off] = h + (ap ? ap[off] : 0.f);
    }
}

__global__ void do_sru_k(const float* __restrict__ g, float* __restrict__ out,
                         const float* __restrict__ add, int C)
{
    int tid = blockIdx.x * blockDim.x + threadIdx.x;
    int total = C * HW;
    if (tid >= total) return;
    int c  = tid / HW;
    int yx = tid - c * HW;

    const float* Wp = g + (size_t)(0 * C + c) * VOX + yx;
    const float* F1 = g + (size_t)(1 * C + c) * VOX + yx;
    const float* F2 = g + (size_t)(2 * C + c) * VOX + yx;
    const float* R1 = g + (size_t)(3 * C + c) * VOX + yx;
    const float* R2 = g + (size_t)(4 * C + c) * VOX + yx;
    const float* Xp = g + (size_t)(5 * C + c) * VOX + yx;
    float*       op = out + (size_t)c * VOX + yx;
    const float* ap = add ? add + (size_t)c * VOX + yx : nullptr;

    {
        float f = sigm(F1[0]);
        float Cc = 1.f - f;
        float r = sigm(R1[0]);
        op[0] = r * Cc + (1.f - r) * tanhf(Xp[0]);
        int off = 0;
        for (int t = 1; t < D_; t++) {
            off += HW;
            f  = sigm(F1[off]);
            Cc = f * Cc + (1.f - f) * tanhf(Wp[off]);
            r  = sigm(R1[off]);
            op[off] = r * Cc + (1.f - r) * tanhf(Xp[off]);
        }
    }
    {
        int off = (D_ - 1) * HW;
        float f = sigm(F2[off]);
        float Cc = 1.f - f;
        float r = sigm(R2[off]);
        float h = r * Cc + (1.f - r) * tanhf(Xp[off]);
        op[off] = op[off] + h + (ap ? ap[off] : 0.f);
        for (int t = 1; t < D_; t++) {
            off -= HW;
            f  = sigm(F2[off]);
            Cc = f * Cc + (1.f - f) * tanhf(Wp[off]);
            r  = sigm(R2[off]);
            h  = r * Cc + (1.f - r) * tanhf(Xp[off]);
            op[off] = op[off] + h + (ap ? ap[off] : 0.f);
        }
    }
}

// ============================ host ============================
static __nv_bfloat16 *s_Ahi, *s_Alo;

static inline void conv_tc(const float* in, const float* w, float* out,
                           int Cin, int Cout, int deconv)
{
    int Kpad = Cin * 32;
    int total = Cout * Kpad;
    prep_k<<<(total + 255) / 256, 256>>>(w, s_Ahi, s_Alo, Cin, Cout, Kpad, deconv, total);
    dim3 grid(D_ * 48, Cout / 64);
    conv_mma_k<<<grid, 256>>>(in, s_Ahi, s_Alo, out, Cin, Kpad);
}

static inline void conv_scalar(const float* in, const float* w, float* out,
                               int Cin, int Cout, int deconv)
{
    dim3 grid(W_ / 32, (H_ / 8) * D_, (Cout + 31) / 32);
    conv3d_k<<<grid, 256>>>(in, w, out, Cin, Cout, deconv);
}

static inline void si_launch(const float* gbuf, float* out, const float* add, int C, int rev)
{
    int n = C * HW;
    si_sru_k<<<(n + 255) / 256, 256>>>(gbuf, out, add, C, rev);
}
static inline void do_launch(const float* gbuf, float* out, const float* add, int C)
{
    int n = C * HW;
    do_sru_k<<<(n + 255) / 256, 256>>>(gbuf, out, add, C);
}

extern "C" void kernel_launch(void* const* d_in, const int* in_sizes, int n_in,
                              void* d_out, int out_size)
{
    (void)in_sizes; (void)n_in; (void)out_size;
    const float* x      = (const float*)d_in[0];
    const float* w_head = (const float*)d_in[1];
    const float* w_e0   = (const float*)d_in[2];
    const float* w_e1   = (const float*)d_in[3];
    const float* w_d0   = (const float*)d_in[4];
    const float* w_d1   = (const float*)d_in[5];
    const float* w_tail = (const float*)d_in[6];
    float* out = (float*)d_out;

    float *gc, *gh, *ge0, *ge1, *gd0, *gd1;
    cudaGetSymbolAddress((void**)&gc,  g_conv);
    cudaGetSymbolAddress((void**)&gh,  g_h);
    cudaGetSymbolAddress((void**)&ge0, g_e0);
    cudaGetSymbolAddress((void**)&ge1, g_e1);
    cudaGetSymbolAddress((void**)&gd0, g_d0);
    cudaGetSymbolAddress((void**)&gd1, g_d1);
    cudaGetSymbolAddress((void**)&s_Ahi, g_Ahi);
    cudaGetSymbolAddress((void**)&s_Alo, g_Alo);

    // h = do_sru(x, w_head)          (scalar: Cin=1)
    conv_scalar(x, w_head, gc, 1, 96, 0);
    do_launch(gc, gh, nullptr, 16);
    // e0 = si_sru(h, w_e0, fwd)      (mma: 16 -> 128)
    conv_tc(gh, w_e0, gc, 16, 128, 0);
    si_launch(gc, ge0, nullptr, 32, 0);
    // e1 = si_sru(e0, w_e1, rev)     (mma: 32 -> 256)
    conv_tc(ge0, w_e1, gc, 32, 256, 0);
    si_launch(gc, ge1, nullptr, 64, 1);
    // d0 = si_sru(e1, w_d0, fwd, deconv) + e0   (mma: 64 -> 128)
    conv_tc(ge1, w_d0, gc, 64, 128, 1);
    si_launch(gc, gd0, ge0, 32, 0);
    // d1 = si_sru(d0, w_d1, rev, deconv) + h    (mma: 32 -> 64)
    conv_tc(gd0, w_d1, gc, 32, 64, 1);
    si_launch(gc, gd1, gh, 16, 1);
    // out = do_sru(d1, w_tail, deconv) + x      (scalar: Cout=6)
    conv_scalar(gd1, w_tail, gc, 16, 6, 1);
    do_launch(gc, out, x, 1);
}

// round 12
// speedup vs baseline: 1.4819x; 1.2552x over previous
#include <cuda_runtime.h>
#include <cuda_fp16.h>
#include <math.h>
#include <stdint.h>

#define D_ 31
#define H_ 96
#define W_ 96
#define HW (H_*W_)        // 9216
#define VOX (D_*HW)       // 285696

// ---- scratch (device globals; no allocation allowed) ----
__device__ float g_conv[256 * VOX];
__device__ float g_h  [16 * VOX];
__device__ float g_e0 [32 * VOX];
__device__ float g_e1 [64 * VOX];
__device__ float g_d0 [32 * VOX];
__device__ float g_d1 [16 * VOX];
__device__ __half g_Ahi[262144];   // weights fp16, [M x Kpad]

__device__ __forceinline__ float sigm(float a) { return 1.0f / (1.0f + expf(-a)); }

typedef unsigned long long u64;
__device__ __forceinline__ void fma2(u64& d, u64 a, u64 b) {
    asm("fma.rn.f32x2 %0, %1, %2, %0;" : "+l"(d) : "l"(a), "l"(b));
}
__device__ __forceinline__ u64 pk2(float x, float y) {
    u64 r; asm("mov.b64 %0, {%1, %2};" : "=l"(r) : "f"(x), "f"(y)); return r;
}
__device__ __forceinline__ float2 unpk2(u64 a) {
    float x, y; asm("mov.b64 {%0, %1}, %2;" : "=f"(x), "=f"(y) : "l"(a));
    return make_float2(x, y);
}
__device__ __forceinline__ uint32_t smem_u32(const void* p) {
    uint32_t a;
    asm("{ .reg .u64 t; cvta.to.shared.u64 t, %1; cvt.u32.u64 %0, t; }" : "=r"(a) : "l"(p));
    return a;
}
__device__ __forceinline__ void ldsm4(uint32_t* r, uint32_t addr) {
    asm volatile("ldmatrix.sync.aligned.m8n8.x4.shared.b16 {%0,%1,%2,%3}, [%4];"
                 : "=r"(r[0]), "=r"(r[1]), "=r"(r[2]), "=r"(r[3]) : "r"(addr));
}
__device__ __forceinline__ void mma16816(float* c, const uint32_t* a, uint32_t b0, uint32_t b1) {
    asm volatile("mma.sync.aligned.m16n8k16.row.col.f32.f16.f16.f32 "
                 "{%0,%1,%2,%3},{%4,%5,%6,%7},{%8,%9},{%0,%1,%2,%3};"
                 : "+f"(c[0]), "+f"(c[1]), "+f"(c[2]), "+f"(c[3])
                 : "r"(a[0]), "r"(a[1]), "r"(a[2]), "r"(a[3]), "r"(b0), "r"(b1));
}
// pack rn fp16 of two floats: high half <- hi, low half <- lo
__device__ __forceinline__ uint32_t cvt_f16x2(float hi, float lo) {
    uint32_t r;
    asm("cvt.rn.f16x2.f32 %0, %1, %2;" : "=r"(r) : "f"(hi), "f"(lo));
    return r;
}

// ============================================================================
// Weight prep: fp16 weights, layout A[m][k], k=ci*32+t (27 taps zero-padded).
// ============================================================================
__global__ void prep_k(const float* __restrict__ w, __half* __restrict__ Ahi,
                       int Cin, int Cout, int Kpad, int deconv, int total)
{
    int i = blockIdx.x * 256 + threadIdx.x;
    if (i >= total) return;
    int m = i / Kpad, k = i - m * Kpad;
    int t = k & 31, ci = k >> 5;
    float v = 0.f;
    if (t < 27 && m < Cout && ci < Cin)
        v = deconv ? w[((size_t)ci * Cout + m) * 27 + (26 - t)]
                   : w[((size_t)m * Cin + ci) * 27 + t];
    Ahi[i] = __float2half(v);
}

// ============================================================================
// Tensor-core implicit-GEMM conv, fp16 2-MMA scheme: D = Ahi*(Bhi + Blo).
// Block tile: M=64 co, N=192 (96x * 2y). 8 warps, each full M=64 x 24 N.
// Barrier once per ci (K=32, 2 chunks of 16); chunk1 LDSM/build overlaps
// chunk0 MMA queue. A staged per-ci via LDG.128 + STS.128.
// ============================================================================
#define KS 40               // padded A row stride (elems); 80B rows
#define ABUF (64*KS)
#define RAW_E 1200          // 12 rows * 100
#define RAW_T 1328          // + 128 zero-pad floats

__global__ __launch_bounds__(256, 2)
void conv_mma_k(const float* __restrict__ in,
                const __half* __restrict__ Ahi,
                float* __restrict__ out,
                int Cin, int Kpad)
{
    __shared__ __align__(16) __half AsH[2][ABUF];
    __shared__ __align__(16) float rawS[2][RAW_T];

    const int tid  = threadIdx.x;
    const int wid  = tid >> 5, lane = tid & 31;
    const int g    = lane >> 2, t4 = lane & 3;
    const int bx   = blockIdx.x, mb = blockIdx.y;
    const int z    = bx / 48, y0 = (bx - z * 48) * 2;

    const int yp = wid >> 2;           // warp-uniform y row (0/1)
    const int xw = (wid & 3) * 24;     // warp x base

    // ---- raw tile slot descriptors (loop-invariant) ----
    int  roff[5]; bool rvalid[5];
    #pragma unroll
    for (int k = 0; k < 5; k++) {
        int i = tid + k * 256;
        if (i < RAW_E) {
            int row = i / 100, col = i - row * 100;
            int zz = z + (row >> 2) - 1;
            int gy = y0 + (row & 3) - 1;
            int gx = col - 1;
            rvalid[k] = (col < 98) && ((unsigned)zz < D_) && ((unsigned)gy < H_) && ((unsigned)gx < W_);
            roff[k] = zz * HW + gy * 96 + gx;
        } else { rvalid[k] = false; roff[k] = 0; }
    }

    // ---- per-sub tap bases (loop-invariant; invalid -> zero pad) ----
    int tb[2][4];
    #pragma unroll
    for (int par = 0; par < 2; par++) {
        #pragma unroll
        for (int q = 0; q < 4; q++) {
            int t = par * 16 + 2 * t4 + (q & 1) + (q >> 1) * 8;
            if (t < 27) {
                int dz = t / 9, r9 = t - dz * 9;
                int dy = r9 / 3, dx = r9 - dy * 3;
                tb[par][q] = (dz * 4 + dy + yp) * 100 + xw + g + dx;
            } else {
                tb[par][q] = RAW_E + g;
            }
        }
    }

    // ---- A staging descriptors: thread = (row = tid>>2, koct = tid&3) ----
    const int arow = tid >> 2, akoct = tid & 3;
    const uint32_t offA = (uint32_t)(((lane & 7) + ((lane >> 3) & 1) * 8) * KS + (lane >> 4) * 8) * 2;
    const uint32_t baAH = smem_u32(AsH);

    float acc[4][3][4];
    #pragma unroll
    for (int mt = 0; mt < 4; mt++)
        #pragma unroll
        for (int nt = 0; nt < 3; nt++)
            #pragma unroll
            for (int j = 0; j < 4; j++) acc[mt][nt][j] = 0.f;

    uint4 a4h;
    float rreg[5];

    auto loadAci = [&](int ci) {
        const size_t ab = (size_t)(mb * 64 + arow) * Kpad + ci * 32 + akoct * 8;
        a4h = *(const uint4*)(Ahi + ab);
    };
    auto stsAci = [&](int buf) {
        *(uint4*)&AsH[buf][arow * KS + akoct * 8] = a4h;
    };
    auto loadRaw = [&](int ci) {
        const float* inp = in + (size_t)ci * VOX;
        #pragma unroll
        for (int k = 0; k < 5; k++) rreg[k] = rvalid[k] ? __ldg(inp + roff[k]) : 0.f;
    };
    auto stsRaw = [&](int buf) {
        #pragma unroll
        for (int k = 0; k < 5; k++) {
            int i = tid + k * 256;
            if (i < RAW_E) rawS[buf][i] = rreg[k];
        }
    };

    // ---- prologue: zero pads, raw(0), A(0) ----
    if (tid < RAW_T - RAW_E) {
        rawS[0][RAW_E + tid] = 0.f;
        rawS[1][RAW_E + tid] = 0.f;
    }
    loadRaw(0); stsRaw(0);
    loadAci(0); stsAci(0);
    __syncthreads();

    for (int ci = 0; ci < Cin; ci++) {
        const int buf = ci & 1;
        const bool more = (ci + 1 < Cin);

        if (more) { loadRaw(ci + 1); loadAci(ci + 1); }

        const float* rp = rawS[buf];
        const uint32_t saH = baAH + buf * (ABUF * 2);

        #pragma unroll
        for (int sub = 0; sub < 2; sub++) {
            // A fragments for this 16-k chunk
            uint32_t ah[4][4];
            #pragma unroll
            for (int mt = 0; mt < 4; mt++)
                ldsm4(ah[mt], saH + (mt * 16) * (KS*2) + offA + sub * 32);

            // B fragments (fp16 hi + residual lo) + 24 MMAs
            const int* tq = tb[sub];
            #pragma unroll
            for (int nt = 0; nt < 3; nt++) {
                const int o = nt * 8;
                float vA = rp[tq[0] + o];
                float vB = rp[tq[1] + o];
                float vC = rp[tq[2] + o];
                float vD = rp[tq[3] + o];
                uint32_t b0h = cvt_f16x2(vB, vA);
                uint32_t b1h = cvt_f16x2(vD, vC);
                half2 h0 = *(half2*)&b0h, h1 = *(half2*)&b1h;
                uint32_t b0l = cvt_f16x2(vB - __high2float(h0), vA - __low2float(h0));
                uint32_t b1l = cvt_f16x2(vD - __high2float(h1), vC - __low2float(h1));
                #pragma unroll
                for (int mt = 0; mt < 4; mt++) {
                    mma16816(acc[mt][nt], ah[mt], b0h, b1h);
                    mma16816(acc[mt][nt], ah[mt], b0l, b1l);
                }
            }
        }

        if (more) { stsRaw(1 - buf); stsAci(1 - buf); }
        __syncthreads();
    }

    // epilogue: Cout multiple of 64 for all mma layers
    const size_t zy = (size_t)z * HW + (size_t)(y0 + yp) * 96;
    #pragma unroll
    for (int mt = 0; mt < 4; mt++) {
        int co = mb * 64 + mt * 16 + g;
        #pragma unroll
        for (int nt = 0; nt < 3; nt++) {
            int x = xw + nt * 8 + t4 * 2;
            float* op = out + (size_t)co * VOX + zy + x;
            *(float2*)op = make_float2(acc[mt][nt][0], acc[mt][nt][1]);
            *(float2*)(op + (size_t)8 * VOX) = make_float2(acc[mt][nt][2], acc[mt][nt][3]);
        }
    }
}

// ============================================================================
// Scalar FFMA2 conv (head Cin=1 and tail Cout=6 layers).
// ============================================================================
#define HALO 1080
#define WTOT 864

__global__ __launch_bounds__(256, 2)
void conv3d_k(const float* __restrict__ in, const float* __restrict__ w,
              float* __restrict__ out, int Cin, int Cout, int deconv)
{
    __shared__ __align__(16) float  in_s[HALO];
    __shared__ __align__(8)  float2 w_s2[WTOT];

    const int tid = threadIdx.x;
    const int tx  = tid & 3;
    const int ty  = (tid >> 2) & 7;
    const int cg  = tid >> 5;

    const int x0 = blockIdx.x * 32;
    const int y0 = (blockIdx.y % 12) * 8;
    const int zb = blockIdx.y / 12;
    const int coBase = blockIdx.z * 32;

    int  hoff[5]; bool hval[5];
    #pragma unroll
    for (int k = 0; k < 5; k++) {
        int i = tid + k * 256;
        if (i < HALO) {
            int dz  = i / 360;
            int rem = i - dz * 360;
            int yy  = rem / 36;
            int xx  = rem - yy * 36;
            int z = zb + dz - 1, y = y0 + yy - 1, x = x0 + xx - 1;
            hval[k] = ((unsigned)z < D_) && ((unsigned)y < H_) && ((unsigned)x < W_) && (xx < 34);
            hoff[k] = z * HW + y * W_ + x;
        } else { hval[k] = false; hoff[k] = 0; }
    }
    int wbase[4]; bool wvalid[4];
    const int wstride = deconv ? Cout * 27 : 27;
    #pragma unroll
    for (int k = 0; k < 4; k++) {
        int idx = tid + k * 256;
        if (idx < WTOT) {
            int co = idx / 27, t = idx - co * 27;
            int coG = coBase + co;
            wvalid[k] = (coG < Cout);
            wbase[k]  = deconv ? (coG * 27 + (26 - t)) : (coG * Cin * 27 + t);
        } else { wvalid[k] = false; wbase[k] = 0; }
    }

    u64 acc[4][4];
    #pragma unroll
    for (int c = 0; c < 4; c++)
        #pragma unroll
        for (int j = 0; j < 4; j++) acc[c][j] = 0ull;

    float hreg[5], wreg[4];
    #pragma unroll
    for (int k = 0; k < 5; k++) hreg[k] = hval[k] ? __ldg(in + hoff[k]) : 0.f;
    #pragma unroll
    for (int k = 0; k < 4; k++) wreg[k] = wvalid[k] ? __ldg(w + wbase[k]) : 0.f;

    for (int ci = 0; ci < Cin; ci++) {
        #pragma unroll
        for (int k = 0; k < 5; k++) {
            int i = tid + k * 256;
            if (i < HALO) in_s[i] = hreg[k];
        }
        #pragma unroll
        for (int k = 0; k < 4; k++) {
            int idx = tid + k * 256;
            if (idx < WTOT) w_s2[idx] = make_float2(wreg[k], wreg[k]);
        }
        __syncthreads();

        if (ci + 1 < Cin) {
            const float* inp = in + (size_t)(ci + 1) * VOX;
            #pragma unroll
            for (int k = 0; k < 5; k++) hreg[k] = hval[k] ? __ldg(inp + hoff[k]) : 0.f;
            const float* wp_ = w + (size_t)(ci + 1) * wstride;
            #pragma unroll
            for (int k = 0; k < 4; k++) wreg[k] = wvalid[k] ? __ldg(wp_ + wbase[k]) : 0.f;
        }

        const float2* wp = &w_s2[cg * 4 * 27];
        #pragma unroll
        for (int dz = 0; dz < 3; dz++) {
            #pragma unroll
            for (int dy = 0; dy < 3; dy++) {
                const float* row = &in_s[(dz * 10 + ty + dy) * 36 + tx * 8];
                float4 a4 = *(const float4*)row;
                float4 b4 = *(const float4*)(row + 4);
                float2 c2 = *(const float2*)(row + 8);
                float v[10] = {a4.x, a4.y, a4.z, a4.w, b4.x, b4.y, b4.z, b4.w, c2.x, c2.y};
                u64 p[9];
                #pragma unroll
                for (int i = 0; i < 9; i++) p[i] = pk2(v[i], v[i + 1]);
                const int tb = dz * 9 + dy * 3;
                #pragma unroll
                for (int co = 0; co < 4; co++) {
                    const float2* wc = wp + co * 27 + tb;
                    u64 w0 = *(const u64*)(wc + 0);
                    fma2(acc[co][0], p[0], w0); fma2(acc[co][1], p[2], w0);
                    fma2(acc[co][2], p[4], w0); fma2(acc[co][3], p[6], w0);
                    u64 w1 = *(const u64*)(wc + 1);
                    fma2(acc[co][0], p[1], w1); fma2(acc[co][1], p[3], w1);
                    fma2(acc[co][2], p[5], w1); fma2(acc[co][3], p[7], w1);
                    u64 w2 = *(const u64*)(wc + 2);
                    fma2(acc[co][0], p[2], w2); fma2(acc[co][1], p[4], w2);
                    fma2(acc[co][2], p[6], w2); fma2(acc[co][3], p[8], w2);
                }
            }
        }
        __syncthreads();
    }

    const int xo = x0 + tx * 8;
    const size_t base = (size_t)zb * HW + (y0 + ty) * W_ + xo;
    #pragma unroll
    for (int co = 0; co < 4; co++) {
        int coG = coBase + cg * 4 + co;
        if (coG < Cout) {
            float2 q0 = unpk2(acc[co][0]);
            float2 q1 = unpk2(acc[co][1]);
            float2 q2 = unpk2(acc[co][2]);
            float2 q3 = unpk2(acc[co][3]);
            float* op = out + (size_t)coG * VOX + base;
            *(float4*)(op + 0) = make_float4(q0.x, q0.y, q1.x, q1.y);
            *(float4*)(op + 4) = make_float4(q2.x, q2.y, q3.x, q3.y);
        }
    }
}

// ============================ SRU kernels ============================
__global__ void si_sru_k(const float* __restrict__ g, float* __restrict__ out,
                         const float* __restrict__ add, int C, int rev)
{
    int tid = blockIdx.x * blockDim.x + threadIdx.x;
    int total = C * HW;
    if (tid >= total) return;
    int c  = tid / HW;
    int yx = tid - c * HW;

    const float* Wp = g + (size_t)(0 * C + c) * VOX + yx;
    const float* Fp = g + (size_t)(1 * C + c) * VOX + yx;
    const float* Rp = g + (size_t)(2 * C + c) * VOX + yx;
    const float* Xp = g + (size_t)(3 * C + c) * VOX + yx;
    float*       op = out + (size_t)c * VOX + yx;
    const float* ap = add ? add + (size_t)c * VOX + yx : nullptr;

    int off = rev ? (D_ - 1) * HW : 0;
    int zs  = rev ? -HW : HW;

    float f = sigm(Fp[off]);
    float Cc = 1.f - f;
    float r = sigm(Rp[off]);
    float h = r * Cc + (1.f - r) * tanhf(Xp[off]);
    op[off] = h + (ap ? ap[off] : 0.f);

    for (int t = 1; t < D_; t++) {
        off += zs;
        f  = sigm(Fp[off]);
        Cc = f * Cc + (1.f - f) * tanhf(Wp[off]);
        r  = sigm(Rp[off]);
        h  = r * Cc + (1.f - r) * tanhf(Xp[off]);
        op[off] = h + (ap ? ap[off] : 0.f);
    }
}

__global__ void do_sru_k(const float* __restrict__ g, float* __restrict__ out,
                         const float* __restrict__ add, int C)
{
    int tid = blockIdx.x * blockDim.x + threadIdx.x;
    int total = C * HW;
    if (tid >= total) return;
    int c  = tid / HW;
    int yx = tid - c * HW;

    const float* Wp = g + (size_t)(0 * C + c) * VOX + yx;
    const float* F1 = g + (size_t)(1 * C + c) * VOX + yx;
    const float* F2 = g + (size_t)(2 * C + c) * VOX + yx;
    const float* R1 = g + (size_t)(3 * C + c) * VOX + yx;
    const float* R2 = g + (size_t)(4 * C + c) * VOX + yx;
    const float* Xp = g + (size_t)(5 * C + c) * VOX + yx;
    float*       op = out + (size_t)c * VOX + yx;
    const float* ap = add ? add + (size_t)c * VOX + yx : nullptr;

    {
        float f = sigm(F1[0]);
        float Cc = 1.f - f;
        float r = sigm(R1[0]);
        op[0] = r * Cc + (1.f - r) * tanhf(Xp[0]);
        int off = 0;
        for (int t = 1; t < D_; t++) {
            off += HW;
            f  = sigm(F1[off]);
            Cc = f * Cc + (1.f - f) * tanhf(Wp[off]);
            r  = sigm(R1[off]);
            op[off] = r * Cc + (1.f - r) * tanhf(Xp[off]);
        }
    }
    {
        int off = (D_ - 1) * HW;
        float f = sigm(F2[off]);
        float Cc = 1.f - f;
        float r = sigm(R2[off]);
        float h = r * Cc + (1.f - r) * tanhf(Xp[off]);
        op[off] = op[off] + h + (ap ? ap[off] : 0.f);
        for (int t = 1; t < D_; t++) {
            off -= HW;
            f  = sigm(F2[off]);
            Cc = f * Cc + (1.f - f) * tanhf(Wp[off]);
            r  = sigm(R2[off]);
            h  = r * Cc + (1.f - r) * tanhf(Xp[off]);
            op[off] = op[off] + h + (ap ? ap[off] : 0.f);
        }
    }
}

// ============================ host ============================
static __half* s_Ahi;

static inline void conv_tc(const float* in, const float* w, float* out,
                           int Cin, int Cout, int deconv)
{
    int Kpad = Cin * 32;
    int total = Cout * Kpad;
    prep_k<<<(total + 255) / 256, 256>>>(w, s_Ahi, Cin, Cout, Kpad, deconv, total);
    dim3 grid(D_ * 48, Cout / 64);
    conv_mma_k<<<grid, 256>>>(in, s_Ahi, out, Cin, Kpad);
}

static inline void conv_scalar(const float* in, const float* w, float* out,
                               int Cin, int Cout, int deconv)
{
    dim3 grid(W_ / 32, (H_ / 8) * D_, (Cout + 31) / 32);
    conv3d_k<<<grid, 256>>>(in, w, out, Cin, Cout, deconv);
}

static inline void si_launch(const float* gbuf, float* out, const float* add, int C, int rev)
{
    int n = C * HW;
    si_sru_k<<<(n + 255) / 256, 256>>>(gbuf, out, add, C, rev);
}
static inline void do_launch(const float* gbuf, float* out, const float* add, int C)
{
    int n = C * HW;
    do_sru_k<<<(n + 255) / 256, 256>>>(gbuf, out, add, C);
}

extern "C" void kernel_launch(void* const* d_in, const int* in_sizes, int n_in,
                              void* d_out, int out_size)
{
    (void)in_sizes; (void)n_in; (void)out_size;
    const float* x      = (const float*)d_in[0];
    const float* w_head = (const float*)d_in[1];
    const float* w_e0   = (const float*)d_in[2];
    const float* w_e1   = (const float*)d_in[3];
    const float* w_d0   = (const float*)d_in[4];
    const float* w_d1   = (const float*)d_in[5];
    const float* w_tail = (const float*)d_in[6];
    float* out = (float*)d_out;

    float *gc, *gh, *ge0, *ge1, *gd0, *gd1;
    cudaGetSymbolAddress((void**)&gc,  g_conv);
    cudaGetSymbolAddress((void**)&gh,  g_h);
    cudaGetSymbolAddress((void**)&ge0, g_e0);
    cudaGetSymbolAddress((void**)&ge1, g_e1);
    cudaGetSymbolAddress((void**)&gd0, g_d0);
    cudaGetSymbolAddress((void**)&gd1, g_d1);
    cudaGetSymbolAddress((void**)&s_Ahi, g_Ahi);

    // h = do_sru(x, w_head)          (scalar: Cin=1)
    conv_scalar(x, w_head, gc, 1, 96, 0);
    do_launch(gc, gh, nullptr, 16);
    // e0 = si_sru(h, w_e0, fwd)      (mma: 16 -> 128)
    conv_tc(gh, w_e0, gc, 16, 128, 0);
    si_launch(gc, ge0, nullptr, 32, 0);
    // e1 = si_sru(e0, w_e1, rev)     (mma: 32 -> 256)
    conv_tc(ge0, w_e1, gc, 32, 256, 0);
    si_launch(gc, ge1, nullptr, 64, 1);
    // d0 = si_sru(e1, w_d0, fwd, deconv) + e0   (mma: 64 -> 128)
    conv_tc(ge1, w_d0, gc, 64, 128, 1);
    si_launch(gc, gd0, ge0, 32, 0);
    // d1 = si_sru(d0, w_d1, rev, deconv) + h    (mma: 32 -> 64)
    conv_tc(gd0, w_d1, gc, 32, 64, 1);
    si_launch(gc, gd1, gh, 16, 1);
    // out = do_sru(d1, w_tail, deconv) + x      (scalar: Cout=6)
    conv_scalar(gd1, w_tail, gc, 16, 6, 1);
    do_launch(gc, out, x, 1);
}

// round 13
// speedup vs baseline: 1.5459x; 1.0432x over previous
#include <cuda_runtime.h>
#include <cuda_fp16.h>
#include <math.h>
#include <stdint.h>

#define D_ 31
#define H_ 96
#define W_ 96
#define HW (H_*W_)        // 9216
#define HW2 (HW/2)
#define VOX (D_*HW)       // 285696

// ---- scratch (device globals; no allocation allowed) ----
__device__ float g_conv[256 * VOX];
__device__ float g_h  [16 * VOX];
__device__ float g_e0 [32 * VOX];
__device__ float g_e1 [64 * VOX];
__device__ float g_d0 [32 * VOX];
__device__ float g_d1 [16 * VOX];
__device__ __half g_Ahi[262144];   // weights fp16, [M x Kpad]

// ---- fast activations: ex2.approx + rcp.approx (rel err ~1e-6) ----
#define L2E 1.442695041f
__device__ __forceinline__ float ex2f(float a) {
    float r; asm("ex2.approx.f32 %0, %1;" : "=f"(r) : "f"(a)); return r;
}
__device__ __forceinline__ float rcpf(float a) {
    float r; asm("rcp.approx.f32 %0, %1;" : "=f"(r) : "f"(a)); return r;
}
__device__ __forceinline__ float sigm(float x) {
    return rcpf(1.f + ex2f(-L2E * x));
}
__device__ __forceinline__ float tanhx(float x) {
    return 1.f - 2.f * rcpf(1.f + ex2f(2.f * L2E * x));
}

typedef unsigned long long u64;
__device__ __forceinline__ void fma2(u64& d, u64 a, u64 b) {
    asm("fma.rn.f32x2 %0, %1, %2, %0;" : "+l"(d) : "l"(a), "l"(b));
}
__device__ __forceinline__ u64 pk2(float x, float y) {
    u64 r; asm("mov.b64 %0, {%1, %2};" : "=l"(r) : "f"(x), "f"(y)); return r;
}
__device__ __forceinline__ float2 unpk2(u64 a) {
    float x, y; asm("mov.b64 {%0, %1}, %2;" : "=f"(x), "=f"(y) : "l"(a));
    return make_float2(x, y);
}
__device__ __forceinline__ uint32_t smem_u32(const void* p) {
    uint32_t a;
    asm("{ .reg .u64 t; cvta.to.shared.u64 t, %1; cvt.u32.u64 %0, t; }" : "=r"(a) : "l"(p));
    return a;
}
__device__ __forceinline__ void ldsm4(uint32_t* r, uint32_t addr) {
    asm volatile("ldmatrix.sync.aligned.m8n8.x4.shared.b16 {%0,%1,%2,%3}, [%4];"
                 : "=r"(r[0]), "=r"(r[1]), "=r"(r[2]), "=r"(r[3]) : "r"(addr));
}
__device__ __forceinline__ void mma16816(float* c, const uint32_t* a, uint32_t b0, uint32_t b1) {
    asm volatile("mma.sync.aligned.m16n8k16.row.col.f32.f16.f16.f32 "
                 "{%0,%1,%2,%3},{%4,%5,%6,%7},{%8,%9},{%0,%1,%2,%3};"
                 : "+f"(c[0]), "+f"(c[1]), "+f"(c[2]), "+f"(c[3])
                 : "r"(a[0]), "r"(a[1]), "r"(a[2]), "r"(a[3]), "r"(b0), "r"(b1));
}
__device__ __forceinline__ uint32_t cvt_f16x2(float hi, float lo) {
    uint32_t r;
    asm("cvt.rn.f16x2.f32 %0, %1, %2;" : "=r"(r) : "f"(hi), "f"(lo));
    return r;
}

// ============================================================================
// Weight prep: fp16 weights, layout A[m][k], k=ci*32+t (27 taps zero-padded).
// ============================================================================
__global__ void prep_k(const float* __restrict__ w, __half* __restrict__ Ahi,
                       int Cin, int Cout, int Kpad, int deconv, int total)
{
    int i = blockIdx.x * 256 + threadIdx.x;
    if (i >= total) return;
    int m = i / Kpad, k = i - m * Kpad;
    int t = k & 31, ci = k >> 5;
    float v = 0.f;
    if (t < 27 && m < Cout && ci < Cin)
        v = deconv ? w[((size_t)ci * Cout + m) * 27 + (26 - t)]
                   : w[((size_t)m * Cin + ci) * 27 + t];
    Ahi[i] = __float2half(v);
}

// ============================================================================
// Tensor-core implicit-GEMM conv, fp16 2-MMA scheme: D = Ahi*(Bhi + Blo).
// Block tile: M=64 co, N=192 (96x * 2y). 8 warps, each full M=64 x 24 N.
// Barrier once per ci; odd warps process sub-chunks in reverse order to
// de-phase the post-barrier LDSM burst from the MMA burst.
// ============================================================================
#define KS 40
#define ABUF (64*KS)
#define RAW_E 1200          // 12 rows * 100
#define RAW_T 1328

__global__ __launch_bounds__(256, 2)
void conv_mma_k(const float* __restrict__ in,
                const __half* __restrict__ Ahi,
                float* __restrict__ out,
                int Cin, int Kpad)
{
    __shared__ __align__(16) __half AsH[2][ABUF];
    __shared__ __align__(16) float rawS[2][RAW_T];

    const int tid  = threadIdx.x;
    const int wid  = tid >> 5, lane = tid & 31;
    const int g    = lane >> 2, t4 = lane & 3;
    const int bx   = blockIdx.x, mb = blockIdx.y;
    const int z    = bx / 48, y0 = (bx - z * 48) * 2;

    const int yp = wid >> 2;
    const int xw = (wid & 3) * 24;

    int  roff[5]; bool rvalid[5];
    #pragma unroll
    for (int k = 0; k < 5; k++) {
        int i = tid + k * 256;
        if (i < RAW_E) {
            int row = i / 100, col = i - row * 100;
            int zz = z + (row >> 2) - 1;
            int gy = y0 + (row & 3) - 1;
            int gx = col - 1;
            rvalid[k] = (col < 98) && ((unsigned)zz < D_) && ((unsigned)gy < H_) && ((unsigned)gx < W_);
            roff[k] = zz * HW + gy * 96 + gx;
        } else { rvalid[k] = false; roff[k] = 0; }
    }

    int tb[2][4];
    #pragma unroll
    for (int par = 0; par < 2; par++) {
        #pragma unroll
        for (int q = 0; q < 4; q++) {
            int t = par * 16 + 2 * t4 + (q & 1) + (q >> 1) * 8;
            if (t < 27) {
                int dz = t / 9, r9 = t - dz * 9;
                int dy = r9 / 3, dx = r9 - dy * 3;
                tb[par][q] = (dz * 4 + dy + yp) * 100 + xw + g + dx;
            } else {
                tb[par][q] = RAW_E + g;
            }
        }
    }

    const int arow = tid >> 2, akoct = tid & 3;
    const uint32_t offA = (uint32_t)(((lane & 7) + ((lane >> 3) & 1) * 8) * KS + (lane >> 4) * 8) * 2;
    const uint32_t baAH = smem_u32(AsH);

    float acc[4][3][4];
    #pragma unroll
    for (int mt = 0; mt < 4; mt++)
        #pragma unroll
        for (int nt = 0; nt < 3; nt++)
            #pragma unroll
            for (int j = 0; j < 4; j++) acc[mt][nt][j] = 0.f;

    uint4 a4h;
    float rreg[5];

    auto loadAci = [&](int ci) {
        const size_t ab = (size_t)(mb * 64 + arow) * Kpad + ci * 32 + akoct * 8;
        a4h = *(const uint4*)(Ahi + ab);
    };
    auto stsAci = [&](int buf) {
        *(uint4*)&AsH[buf][arow * KS + akoct * 8] = a4h;
    };
    auto loadRaw = [&](int ci) {
        const float* inp = in + (size_t)ci * VOX;
        #pragma unroll
        for (int k = 0; k < 5; k++) rreg[k] = rvalid[k] ? __ldg(inp + roff[k]) : 0.f;
    };
    auto stsRaw = [&](int buf) {
        #pragma unroll
        for (int k = 0; k < 5; k++) {
            int i = tid + k * 256;
            if (i < RAW_E) rawS[buf][i] = rreg[k];
        }
    };

    if (tid < RAW_T - RAW_E) {
        rawS[0][RAW_E + tid] = 0.f;
        rawS[1][RAW_E + tid] = 0.f;
    }
    loadRaw(0); stsRaw(0);
    loadAci(0); stsAci(0);
    __syncthreads();

    const int sflip = wid & 1;   // odd warps reverse sub order
    for (int ci = 0; ci < Cin; ci++) {
        const int buf = ci & 1;
        const bool more = (ci + 1 < Cin);

        if (more) { loadRaw(ci + 1); loadAci(ci + 1); }

        const float* rp = rawS[buf];
        const uint32_t saH = baAH + buf * (ABUF * 2);

        #pragma unroll
        for (int s2 = 0; s2 < 2; s2++) {
            const int sub = sflip ? (1 - s2) : s2;
            uint32_t ah[4][4];
            #pragma unroll
            for (int mt = 0; mt < 4; mt++)
                ldsm4(ah[mt], saH + (mt * 16) * (KS*2) + offA + sub * 32);

            const int* tq = tb[sub];
            #pragma unroll
            for (int nt = 0; nt < 3; nt++) {
                const int o = nt * 8;
                float vA = rp[tq[0] + o];
                float vB = rp[tq[1] + o];
                float vC = rp[tq[2] + o];
                float vD = rp[tq[3] + o];
                uint32_t b0h = cvt_f16x2(vB, vA);
                uint32_t b1h = cvt_f16x2(vD, vC);
                half2 h0 = *(half2*)&b0h, h1 = *(half2*)&b1h;
                uint32_t b0l = cvt_f16x2(vB - __high2float(h0), vA - __low2float(h0));
                uint32_t b1l = cvt_f16x2(vD - __high2float(h1), vC - __low2float(h1));
                #pragma unroll
                for (int mt = 0; mt < 4; mt++) {
                    mma16816(acc[mt][nt], ah[mt], b0h, b1h);
                    mma16816(acc[mt][nt], ah[mt], b0l, b1l);
                }
            }
        }

        if (more) { stsRaw(1 - buf); stsAci(1 - buf); }
        __syncthreads();
    }

    const size_t zy = (size_t)z * HW + (size_t)(y0 + yp) * 96;
    #pragma unroll
    for (int mt = 0; mt < 4; mt++) {
        int co = mb * 64 + mt * 16 + g;
        #pragma unroll
        for (int nt = 0; nt < 3; nt++) {
            int x = xw + nt * 8 + t4 * 2;
            float* op = out + (size_t)co * VOX + zy + x;
            *(float2*)op = make_float2(acc[mt][nt][0], acc[mt][nt][1]);
            *(float2*)(op + (size_t)8 * VOX) = make_float2(acc[mt][nt][2], acc[mt][nt][3]);
        }
    }
}

// ============================================================================
// Scalar FFMA2 conv (head Cin=1 and tail Cout=6 layers).
// ============================================================================
#define HALO 1080
#define WTOT 864

__global__ __launch_bounds__(256, 2)
void conv3d_k(const float* __restrict__ in, const float* __restrict__ w,
              float* __restrict__ out, int Cin, int Cout, int deconv)
{
    __shared__ __align__(16) float  in_s[HALO];
    __shared__ __align__(8)  float2 w_s2[WTOT];

    const int tid = threadIdx.x;
    const int tx  = tid & 3;
    const int ty  = (tid >> 2) & 7;
    const int cg  = tid >> 5;

    const int x0 = blockIdx.x * 32;
    const int y0 = (blockIdx.y % 12) * 8;
    const int zb = blockIdx.y / 12;
    const int coBase = blockIdx.z * 32;

    int  hoff[5]; bool hval[5];
    #pragma unroll
    for (int k = 0; k < 5; k++) {
        int i = tid + k * 256;
        if (i < HALO) {
            int dz  = i / 360;
            int rem = i - dz * 360;
            int yy  = rem / 36;
            int xx  = rem - yy * 36;
            int z = zb + dz - 1, y = y0 + yy - 1, x = x0 + xx - 1;
            hval[k] = ((unsigned)z < D_) && ((unsigned)y < H_) && ((unsigned)x < W_) && (xx < 34);
            hoff[k] = z * HW + y * W_ + x;
        } else { hval[k] = false; hoff[k] = 0; }
    }
    int wbase[4]; bool wvalid[4];
    const int wstride = deconv ? Cout * 27 : 27;
    #pragma unroll
    for (int k = 0; k < 4; k++) {
        int idx = tid + k * 256;
        if (idx < WTOT) {
            int co = idx / 27, t = idx - co * 27;
            int coG = coBase + co;
            wvalid[k] = (coG < Cout);
            wbase[k]  = deconv ? (coG * 27 + (26 - t)) : (coG * Cin * 27 + t);
        } else { wvalid[k] = false; wbase[k] = 0; }
    }

    u64 acc[4][4];
    #pragma unroll
    for (int c = 0; c < 4; c++)
        #pragma unroll
        for (int j = 0; j < 4; j++) acc[c][j] = 0ull;

    float hreg[5], wreg[4];
    #pragma unroll
    for (int k = 0; k < 5; k++) hreg[k] = hval[k] ? __ldg(in + hoff[k]) : 0.f;
    #pragma unroll
    for (int k = 0; k < 4; k++) wreg[k] = wvalid[k] ? __ldg(w + wbase[k]) : 0.f;

    for (int ci = 0; ci < Cin; ci++) {
        #pragma unroll
        for (int k = 0; k < 5; k++) {
            int i = tid + k * 256;
            if (i < HALO) in_s[i] = hreg[k];
        }
        #pragma unroll
        for (int k = 0; k < 4; k++) {
            int idx = tid + k * 256;
            if (idx < WTOT) w_s2[idx] = make_float2(wreg[k], wreg[k]);
        }
        __syncthreads();

        if (ci + 1 < Cin) {
            const float* inp = in + (size_t)(ci + 1) * VOX;
            #pragma unroll
            for (int k = 0; k < 5; k++) hreg[k] = hval[k] ? __ldg(inp + hoff[k]) : 0.f;
            const float* wp_ = w + (size_t)(ci + 1) * wstride;
            #pragma unroll
            for (int k = 0; k < 4; k++) wreg[k] = wvalid[k] ? __ldg(wp_ + wbase[k]) : 0.f;
        }

        const float2* wp = &w_s2[cg * 4 * 27];
        #pragma unroll
        for (int dz = 0; dz < 3; dz++) {
            #pragma unroll
            for (int dy = 0; dy < 3; dy++) {
                const float* row = &in_s[(dz * 10 + ty + dy) * 36 + tx * 8];
                float4 a4 = *(const float4*)row;
                float4 b4 = *(const float4*)(row + 4);
                float2 c2 = *(const float2*)(row + 8);
                float v[10] = {a4.x, a4.y, a4.z, a4.w, b4.x, b4.y, b4.z, b4.w, c2.x, c2.y};
                u64 p[9];
                #pragma unroll
                for (int i = 0; i < 9; i++) p[i] = pk2(v[i], v[i + 1]);
                const int tb = dz * 9 + dy * 3;
                #pragma unroll
                for (int co = 0; co < 4; co++) {
                    const float2* wc = wp + co * 27 + tb;
                    u64 w0 = *(const u64*)(wc + 0);
                    fma2(acc[co][0], p[0], w0); fma2(acc[co][1], p[2], w0);
                    fma2(acc[co][2], p[4], w0); fma2(acc[co][3], p[6], w0);
                    u64 w1 = *(const u64*)(wc + 1);
                    fma2(acc[co][0], p[1], w1); fma2(acc[co][1], p[3], w1);
                    fma2(acc[co][2], p[5], w1); fma2(acc[co][3], p[7], w1);
                    u64 w2 = *(const u64*)(wc + 2);
                    fma2(acc[co][0], p[2], w2); fma2(acc[co][1], p[4], w2);
                    fma2(acc[co][2], p[6], w2); fma2(acc[co][3], p[8], w2);
                }
            }
        }
        __syncthreads();
    }

    const int xo = x0 + tx * 8;
    const size_t base = (size_t)zb * HW + (y0 + ty) * W_ + xo;
    #pragma unroll
    for (int co = 0; co < 4; co++) {
        int coG = coBase + cg * 4 + co;
        if (coG < Cout) {
            float2 q0 = unpk2(acc[co][0]);
            float2 q1 = unpk2(acc[co][1]);
            float2 q2 = unpk2(acc[co][2]);
            float2 q3 = unpk2(acc[co][3]);
            float* op = out + (size_t)coG * VOX + base;
            *(float4*)(op + 0) = make_float4(q0.x, q0.y, q1.x, q1.y);
            *(float4*)(op + 4) = make_float4(q2.x, q2.y, q3.x, q3.y);
        }
    }
}

// ============================ SRU kernels (float2, fast activations) ============
__global__ void si_sru_k(const float* __restrict__ g, float* __restrict__ out,
                         const float* __restrict__ add, int C, int rev)
{
    int tid = blockIdx.x * blockDim.x + threadIdx.x;
    int total = C * HW2;
    if (tid >= total) return;
    int c  = tid / HW2;
    int yx = (tid - c * HW2) * 2;

    const float2* Wp = (const float2*)(g + (size_t)(0 * C + c) * VOX + yx);
    const float2* Fp = (const float2*)(g + (size_t)(1 * C + c) * VOX + yx);
    const float2* Rp = (const float2*)(g + (size_t)(2 * C + c) * VOX + yx);
    const float2* Xp = (const float2*)(g + (size_t)(3 * C + c) * VOX + yx);
    float2*       op = (float2*)(out + (size_t)c * VOX + yx);
    const float2* ap = add ? (const float2*)(add + (size_t)c * VOX + yx) : nullptr;

    int off = rev ? (D_ - 1) * HW2 : 0;
    int zs  = rev ? -HW2 : HW2;

    float2 f = Fp[off], r = Rp[off], xv = Xp[off];
    float fx = sigm(f.x), fy = sigm(f.y);
    float Cx = 1.f - fx, Cy = 1.f - fy;
    float rx = sigm(r.x), ry = sigm(r.y);
    float hx = rx * Cx + (1.f - rx) * tanhx(xv.x);
    float hy = ry * Cy + (1.f - ry) * tanhx(xv.y);
    float2 av = ap ? ap[off] : make_float2(0.f, 0.f);
    op[off] = make_float2(hx + av.x, hy + av.y);

    for (int t = 1; t < D_; t++) {
        off += zs;
        f = Fp[off]; r = Rp[off]; xv = Xp[off];
        float2 wv = Wp[off];
        fx = sigm(f.x); fy = sigm(f.y);
        Cx = fx * Cx + (1.f - fx) * tanhx(wv.x);
        Cy = fy * Cy + (1.f - fy) * tanhx(wv.y);
        rx = sigm(r.x); ry = sigm(r.y);
        hx = rx * Cx + (1.f - rx) * tanhx(xv.x);
        hy = ry * Cy + (1.f - ry) * tanhx(xv.y);
        av = ap ? ap[off] : make_float2(0.f, 0.f);
        op[off] = make_float2(hx + av.x, hy + av.y);
    }
}

__global__ void do_sru_k(const float* __restrict__ g, float* __restrict__ out,
                         const float* __restrict__ add, int C)
{
    int tid = blockIdx.x * blockDim.x + threadIdx.x;
    int total = C * HW2;
    if (tid >= total) return;
    int c  = tid / HW2;
    int yx = (tid - c * HW2) * 2;

    const float2* Wp = (const float2*)(g + (size_t)(0 * C + c) * VOX + yx);
    const float2* F1 = (const float2*)(g + (size_t)(1 * C + c) * VOX + yx);
    const float2* F2 = (const float2*)(g + (size_t)(2 * C + c) * VOX + yx);
    const float2* R1 = (const float2*)(g + (size_t)(3 * C + c) * VOX + yx);
    const float2* R2 = (const float2*)(g + (size_t)(4 * C + c) * VOX + yx);
    const float2* Xp = (const float2*)(g + (size_t)(5 * C + c) * VOX + yx);
    float2*       op = (float2*)(out + (size_t)c * VOX + yx);
    const float2* ap = add ? (const float2*)(add + (size_t)c * VOX + yx) : nullptr;

    // forward pass
    {
        float2 f = F1[0], r = R1[0], xv = Xp[0];
        float fx = sigm(f.x), fy = sigm(f.y);
        float Cx = 1.f - fx, Cy = 1.f - fy;
        float rx = sigm(r.x), ry = sigm(r.y);
        op[0] = make_float2(rx * Cx + (1.f - rx) * tanhx(xv.x),
                            ry * Cy + (1.f - ry) * tanhx(xv.y));
        int off = 0;
        for (int t = 1; t < D_; t++) {
            off += HW2;
            f = F1[off]; r = R1[off]; xv = Xp[off];
            float2 wv = Wp[off];
            fx = sigm(f.x); fy = sigm(f.y);
            Cx = fx * Cx + (1.f - fx) * tanhx(wv.x);
            Cy = fy * Cy + (1.f - fy) * tanhx(wv.y);
            rx = sigm(r.x); ry = sigm(r.y);
            op[off] = make_float2(rx * Cx + (1.f - rx) * tanhx(xv.x),
                                  ry * Cy + (1.f - ry) * tanhx(xv.y));
        }
    }
    // reverse pass (accumulate + skip)
    {
        int off = (D_ - 1) * HW2;
        float2 f = F2[off], r = R2[off], xv = Xp[off];
        float fx = sigm(f.x), fy = sigm(f.y);
        float Cx = 1.f - fx, Cy = 1.f - fy;
        float rx = sigm(r.x), ry = sigm(r.y);
        float hx = rx * Cx + (1.f - rx) * tanhx(xv.x);
        float hy = ry * Cy + (1.f - ry) * tanhx(xv.y);
        float2 prev = op[off];
        float2 av = ap ? ap[off] : make_float2(0.f, 0.f);
        op[off] = make_float2(prev.x + hx + av.x, prev.y + hy + av.y);
        for (int t = 1; t < D_; t++) {
            off -= HW2;
            f = F2[off]; r = R2[off]; xv = Xp[off];
            float2 wv = Wp[off];
            fx = sigm(f.x); fy = sigm(f.y);
            Cx = fx * Cx + (1.f - fx) * tanhx(wv.x);
            Cy = fy * Cy + (1.f - fy) * tanhx(wv.y);
            rx = sigm(r.x); ry = sigm(r.y);
            hx = rx * Cx + (1.f - rx) * tanhx(xv.x);
            hy = ry * Cy + (1.f - ry) * tanhx(xv.y);
            prev = op[off];
            av = ap ? ap[off] : make_float2(0.f, 0.f);
            op[off] = make_float2(prev.x + hx + av.x, prev.y + hy + av.y);
        }
    }
}

// ============================ host ============================
static __half* s_Ahi;

static inline void conv_tc(const float* in, const float* w, float* out,
                           int Cin, int Cout, int deconv)
{
    int Kpad = Cin * 32;
    int total = Cout * Kpad;
    prep_k<<<(total + 255) / 256, 256>>>(w, s_Ahi, Cin, Cout, Kpad, deconv, total);
    dim3 grid(D_ * 48, Cout / 64);
    conv_mma_k<<<grid, 256>>>(in, s_Ahi, out, Cin, Kpad);
}

static inline void conv_scalar(const float* in, const float* w, float* out,
                               int Cin, int Cout, int deconv)
{
    dim3 grid(W_ / 32, (H_ / 8) * D_, (Cout + 31) / 32);
    conv3d_k<<<grid, 256>>>(in, w, out, Cin, Cout, deconv);
}

static inline void si_launch(const float* gbuf, float* out, const float* add, int C, int rev)
{
    int n = C * HW2;
    si_sru_k<<<(n + 255) / 256, 256>>>(gbuf, out, add, C, rev);
}
static inline void do_launch(const float* gbuf, float* out, const float* add, int C)
{
    int n = C * HW2;
    do_sru_k<<<(n + 255) / 256, 256>>>(gbuf, out, add, C);
}

extern "C" void kernel_launch(void* const* d_in, const int* in_sizes, int n_in,
                              void* d_out, int out_size)
{
    (void)in_sizes; (void)n_in; (void)out_size;
    const float* x      = (const float*)d_in[0];
    const float* w_head = (const float*)d_in[1];
    const float* w_e0   = (const float*)d_in[2];
    const float* w_e1   = (const float*)d_in[3];
    const float* w_d0   = (const float*)d_in[4];
    const float* w_d1   = (const float*)d_in[5];
    const float* w_tail = (const float*)d_in[6];
    float* out = (float*)d_out;

    float *gc, *gh, *ge0, *ge1, *gd0, *gd1;
    cudaGetSymbolAddress((void**)&gc,  g_conv);
    cudaGetSymbolAddress((void**)&gh,  g_h);
    cudaGetSymbolAddress((void**)&ge0, g_e0);
    cudaGetSymbolAddress((void**)&ge1, g_e1);
    cudaGetSymbolAddress((void**)&gd0, g_d0);
    cudaGetSymbolAddress((void**)&gd1, g_d1);
    cudaGetSymbolAddress((void**)&s_Ahi, g_Ahi);

    // h = do_sru(x, w_head)          (scalar: Cin=1)
    conv_scalar(x, w_head, gc, 1, 96, 0);
    do_launch(gc, gh, nullptr, 16);
    // e0 = si_sru(h, w_e0, fwd)      (mma: 16 -> 128)
    conv_tc(gh, w_e0, gc, 16, 128, 0);
    si_launch(gc, ge0, nullptr, 32, 0);
    // e1 = si_sru(e0, w_e1, rev)     (mma: 32 -> 256)
    conv_tc(ge0, w_e1, gc, 32, 256, 0);
    si_launch(gc, ge1, nullptr, 64, 1);
    // d0 = si_sru(e1, w_d0, fwd, deconv) + e0   (mma: 64 -> 128)
    conv_tc(ge1, w_d0, gc, 64, 128, 1);
    si_launch(gc, gd0, ge0, 32, 0);
    // d1 = si_sru(d0, w_d1, rev, deconv) + h    (mma: 32 -> 64)
    conv_tc(gd0, w_d1, gc, 32, 64, 1);
    si_launch(gc, gd1, gh, 16, 1);
    // out = do_sru(d1, w_tail, deconv) + x      (scalar: Cout=6)
    conv_scalar(gd1, w_tail, gc, 16, 6, 1);
    do_launch(gc, out, x, 1);
}

// round 14
// speedup vs baseline: 1.6434x; 1.0630x over previous
#include <cuda_runtime.h>
#include <cuda_fp16.h>
#include <math.h>
#include <stdint.h>

#define D_ 31
#define H_ 96
#define W_ 96
#define HW (H_*W_)        // 9216
#define HW2 (HW/2)
#define VOX (D_*HW)       // 285696

// ---- scratch (device globals; no allocation allowed) ----
__device__ float g_conv[256 * VOX];
__device__ float g_h  [16 * VOX];
__device__ float g_e0 [32 * VOX];
__device__ float g_e1 [64 * VOX];
__device__ float g_d0 [32 * VOX];
__device__ float g_d1 [16 * VOX];
__device__ __half g_Ahi[262144];   // weights fp16, [M x Kpad]

// ---- fast activations: ex2.approx + rcp.approx (rel err ~1e-6) ----
#define L2E 1.442695041f
__device__ __forceinline__ float ex2f(float a) {
    float r; asm("ex2.approx.f32 %0, %1;" : "=f"(r) : "f"(a)); return r;
}
__device__ __forceinline__ float rcpf(float a) {
    float r; asm("rcp.approx.f32 %0, %1;" : "=f"(r) : "f"(a)); return r;
}
__device__ __forceinline__ float sigm(float x) {
    return rcpf(1.f + ex2f(-L2E * x));
}
__device__ __forceinline__ float tanhx(float x) {
    return 1.f - 2.f * rcpf(1.f + ex2f(2.f * L2E * x));
}

typedef unsigned long long u64;
__device__ __forceinline__ void fma2(u64& d, u64 a, u64 b) {
    asm("fma.rn.f32x2 %0, %1, %2, %0;" : "+l"(d) : "l"(a), "l"(b));
}
__device__ __forceinline__ u64 pk2(float x, float y) {
    u64 r; asm("mov.b64 %0, {%1, %2};" : "=l"(r) : "f"(x), "f"(y)); return r;
}
__device__ __forceinline__ float2 unpk2(u64 a) {
    float x, y; asm("mov.b64 {%0, %1}, %2;" : "=f"(x), "=f"(y) : "l"(a));
    return make_float2(x, y);
}
__device__ __forceinline__ uint32_t smem_u32(const void* p) {
    uint32_t a;
    asm("{ .reg .u64 t; cvta.to.shared.u64 t, %1; cvt.u32.u64 %0, t; }" : "=r"(a) : "l"(p));
    return a;
}
__device__ __forceinline__ void ldsm4(uint32_t* r, uint32_t addr) {
    asm volatile("ldmatrix.sync.aligned.m8n8.x4.shared.b16 {%0,%1,%2,%3}, [%4];"
                 : "=r"(r[0]), "=r"(r[1]), "=r"(r[2]), "=r"(r[3]) : "r"(addr));
}
__device__ __forceinline__ void mma16816(float* c, const uint32_t* a, uint32_t b0, uint32_t b1) {
    asm volatile("mma.sync.aligned.m16n8k16.row.col.f32.f16.f16.f32 "
                 "{%0,%1,%2,%3},{%4,%5,%6,%7},{%8,%9},{%0,%1,%2,%3};"
                 : "+f"(c[0]), "+f"(c[1]), "+f"(c[2]), "+f"(c[3])
                 : "r"(a[0]), "r"(a[1]), "r"(a[2]), "r"(a[3]), "r"(b0), "r"(b1));
}
__device__ __forceinline__ uint32_t cvt_f16x2(float hi, float lo) {
    uint32_t r;
    asm("cvt.rn.f16x2.f32 %0, %1, %2;" : "=r"(r) : "f"(hi), "f"(lo));
    return r;
}
// cp.async 4B with zero-fill when szz==0
__device__ __forceinline__ void cpa4(uint32_t dst, const void* src, uint32_t szz) {
    asm volatile("cp.async.ca.shared.global [%0], [%1], 4, %2;"
                 :: "r"(dst), "l"(src), "r"(szz) : "memory");
}
__device__ __forceinline__ void cpa16(uint32_t dst, const void* src) {
    asm volatile("cp.async.cg.shared.global [%0], [%1], 16;"
                 :: "r"(dst), "l"(src) : "memory");
}
#define CP_COMMIT() asm volatile("cp.async.commit_group;" ::: "memory")
#define CP_WAIT0()  asm volatile("cp.async.wait_group 0;" ::: "memory")

// ============================================================================
// Weight prep: fp16 weights, layout A[m][k], k=ci*32+t (27 taps zero-padded).
// ============================================================================
__global__ void prep_k(const float* __restrict__ w, __half* __restrict__ Ahi,
                       int Cin, int Cout, int Kpad, int deconv, int total)
{
    int i = blockIdx.x * 256 + threadIdx.x;
    if (i >= total) return;
    int m = i / Kpad, k = i - m * Kpad;
    int t = k & 31, ci = k >> 5;
    float v = 0.f;
    if (t < 27 && m < Cout && ci < Cin)
        v = deconv ? w[((size_t)ci * Cout + m) * 27 + (26 - t)]
                   : w[((size_t)m * Cin + ci) * 27 + t];
    Ahi[i] = __float2half(v);
}

// ============================================================================
// Tensor-core implicit-GEMM conv, fp16 2-MMA scheme: D = Ahi*(Bhi + Blo).
// Block tile: M=64 co, N=192 (96x * 2y). 8 warps, each full M=64 x 24 N.
// Double-buffered via cp.async (zfill for OOB); one barrier per ci.
// ============================================================================
#define KS 40
#define ABUF (64*KS)
#define RAW_E 1200          // 12 rows * 100
#define RAW_T 1328

__global__ __launch_bounds__(256, 2)
void conv_mma_k(const float* __restrict__ in,
                const __half* __restrict__ Ahi,
                float* __restrict__ out,
                int Cin, int Kpad)
{
    __shared__ __align__(16) __half AsH[2][ABUF];
    __shared__ __align__(16) float rawS[2][RAW_T];

    const int tid  = threadIdx.x;
    const int wid  = tid >> 5, lane = tid & 31;
    const int g    = lane >> 2, t4 = lane & 3;
    const int bx   = blockIdx.x, mb = blockIdx.y;
    const int z    = bx / 48, y0 = (bx - z * 48) * 2;

    const int yp = wid >> 2;
    const int xw = (wid & 3) * 24;

    // ---- raw tile slot descriptors (loop-invariant) ----
    int  roff[5]; uint32_t rsz[5]; bool rin[5];
    #pragma unroll
    for (int k = 0; k < 5; k++) {
        int i = tid + k * 256;
        if (i < RAW_E) {
            int row = i / 100, col = i - row * 100;
            int zz = z + (row >> 2) - 1;
            int gy = y0 + (row & 3) - 1;
            int gx = col - 1;
            bool v = (col < 98) && ((unsigned)zz < D_) && ((unsigned)gy < H_) && ((unsigned)gx < W_);
            rin[k] = true; rsz[k] = v ? 4u : 0u;
            roff[k] = v ? (zz * HW + gy * 96 + gx) : 0;
        } else { rin[k] = false; rsz[k] = 0; roff[k] = 0; }
    }

    // ---- per-sub tap bases (loop-invariant; invalid -> zero pad) ----
    int tb[2][4];
    #pragma unroll
    for (int par = 0; par < 2; par++) {
        #pragma unroll
        for (int q = 0; q < 4; q++) {
            int t = par * 16 + 2 * t4 + (q & 1) + (q >> 1) * 8;
            if (t < 27) {
                int dz = t / 9, r9 = t - dz * 9;
                int dy = r9 / 3, dx = r9 - dy * 3;
                tb[par][q] = (dz * 4 + dy + yp) * 100 + xw + g + dx;
            } else {
                tb[par][q] = RAW_E + g;
            }
        }
    }

    const int arow = tid >> 2, akoct = tid & 3;
    const uint32_t offA = (uint32_t)(((lane & 7) + ((lane >> 3) & 1) * 8) * KS + (lane >> 4) * 8) * 2;
    const uint32_t baAH = smem_u32(AsH);
    const uint32_t baRaw = smem_u32(rawS);
    const uint32_t aDst = baAH + (uint32_t)(arow * KS + akoct * 8) * 2;

    float acc[4][3][4];
    #pragma unroll
    for (int mt = 0; mt < 4; mt++)
        #pragma unroll
        for (int nt = 0; nt < 3; nt++)
            #pragma unroll
            for (int j = 0; j < 4; j++) acc[mt][nt][j] = 0.f;

    auto cpStage = [&](int ci, int buf) {
        const float* inp = in + (size_t)ci * VOX;
        const uint32_t rb = baRaw + buf * (RAW_T * 4);
        #pragma unroll
        for (int k = 0; k < 5; k++) {
            int i = tid + k * 256;
            if (rin[k]) cpa4(rb + i * 4, inp + roff[k], rsz[k]);
        }
        const __half* ap = Ahi + (size_t)(mb * 64 + arow) * Kpad + ci * 32 + akoct * 8;
        cpa16(aDst + buf * (ABUF * 2), ap);
        CP_COMMIT();
    };

    // ---- prologue: zero pads, stage ci=0 ----
    if (tid < RAW_T - RAW_E) {
        rawS[0][RAW_E + tid] = 0.f;
        rawS[1][RAW_E + tid] = 0.f;
    }
    cpStage(0, 0);
    CP_WAIT0();
    __syncthreads();

    for (int ci = 0; ci < Cin; ci++) {
        const int buf = ci & 1;
        const bool more = (ci + 1 < Cin);

        if (more) cpStage(ci + 1, 1 - buf);

        const float* rp = rawS[buf];
        const uint32_t saH = baAH + buf * (ABUF * 2);

        #pragma unroll
        for (int sub = 0; sub < 2; sub++) {
            uint32_t ah[4][4];
            #pragma unroll
            for (int mt = 0; mt < 4; mt++)
                ldsm4(ah[mt], saH + (mt * 16) * (KS*2) + offA + sub * 32);

            const int* tq = tb[sub];
            #pragma unroll
            for (int nt = 0; nt < 3; nt++) {
                const int o = nt * 8;
                float vA = rp[tq[0] + o];
                float vB = rp[tq[1] + o];
                float vC = rp[tq[2] + o];
                float vD = rp[tq[3] + o];
                uint32_t b0h = cvt_f16x2(vB, vA);
                uint32_t b1h = cvt_f16x2(vD, vC);
                half2 h0 = *(half2*)&b0h, h1 = *(half2*)&b1h;
                uint32_t b0l = cvt_f16x2(vB - __high2float(h0), vA - __low2float(h0));
                uint32_t b1l = cvt_f16x2(vD - __high2float(h1), vC - __low2float(h1));
                #pragma unroll
                for (int mt = 0; mt < 4; mt++) {
                    mma16816(acc[mt][nt], ah[mt], b0h, b1h);
                    mma16816(acc[mt][nt], ah[mt], b0l, b1l);
                }
            }
        }

        if (more) CP_WAIT0();
        __syncthreads();
    }

    // epilogue: Cout multiple of 64 for all mma layers
    const size_t zy = (size_t)z * HW + (size_t)(y0 + yp) * 96;
    #pragma unroll
    for (int mt = 0; mt < 4; mt++) {
        int co = mb * 64 + mt * 16 + g;
        #pragma unroll
        for (int nt = 0; nt < 3; nt++) {
            int x = xw + nt * 8 + t4 * 2;
            float* op = out + (size_t)co * VOX + zy + x;
            *(float2*)op = make_float2(acc[mt][nt][0], acc[mt][nt][1]);
            *(float2*)(op + (size_t)8 * VOX) = make_float2(acc[mt][nt][2], acc[mt][nt][3]);
        }
    }
}

// ============================================================================
// Scalar FFMA2 conv (head Cin=1 and tail Cout=6 layers).
// ============================================================================
#define HALO 1080
#define WTOT 864

__global__ __launch_bounds__(256, 2)
void conv3d_k(const float* __restrict__ in, const float* __restrict__ w,
              float* __restrict__ out, int Cin, int Cout, int deconv)
{
    __shared__ __align__(16) float  in_s[HALO];
    __shared__ __align__(8)  float2 w_s2[WTOT];

    const int tid = threadIdx.x;
    const int tx  = tid & 3;
    const int ty  = (tid >> 2) & 7;
    const int cg  = tid >> 5;

    const int x0 = blockIdx.x * 32;
    const int y0 = (blockIdx.y % 12) * 8;
    const int zb = blockIdx.y / 12;
    const int coBase = blockIdx.z * 32;

    int  hoff[5]; bool hval[5];
    #pragma unroll
    for (int k = 0; k < 5; k++) {
        int i = tid + k * 256;
        if (i < HALO) {
            int dz  = i / 360;
            int rem = i - dz * 360;
            int yy  = rem / 36;
            int xx  = rem - yy * 36;
            int z = zb + dz - 1, y = y0 + yy - 1, x = x0 + xx - 1;
            hval[k] = ((unsigned)z < D_) && ((unsigned)y < H_) && ((unsigned)x < W_) && (xx < 34);
            hoff[k] = z * HW + y * W_ + x;
        } else { hval[k] = false; hoff[k] = 0; }
    }
    int wbase[4]; bool wvalid[4];
    const int wstride = deconv ? Cout * 27 : 27;
    #pragma unroll
    for (int k = 0; k < 4; k++) {
        int idx = tid + k * 256;
        if (idx < WTOT) {
            int co = idx / 27, t = idx - co * 27;
            int coG = coBase + co;
            wvalid[k] = (coG < Cout);
            wbase[k]  = deconv ? (coG * 27 + (26 - t)) : (coG * Cin * 27 + t);
        } else { wvalid[k] = false; wbase[k] = 0; }
    }

    u64 acc[4][4];
    #pragma unroll
    for (int c = 0; c < 4; c++)
        #pragma unroll
        for (int j = 0; j < 4; j++) acc[c][j] = 0ull;

    float hreg[5], wreg[4];
    #pragma unroll
    for (int k = 0; k < 5; k++) hreg[k] = hval[k] ? __ldg(in + hoff[k]) : 0.f;
    #pragma unroll
    for (int k = 0; k < 4; k++) wreg[k] = wvalid[k] ? __ldg(w + wbase[k]) : 0.f;

    for (int ci = 0; ci < Cin; ci++) {
        #pragma unroll
        for (int k = 0; k < 5; k++) {
            int i = tid + k * 256;
            if (i < HALO) in_s[i] = hreg[k];
        }
        #pragma unroll
        for (int k = 0; k < 4; k++) {
            int idx = tid + k * 256;
            if (idx < WTOT) w_s2[idx] = make_float2(wreg[k], wreg[k]);
        }
        __syncthreads();

        if (ci + 1 < Cin) {
            const float* inp = in + (size_t)(ci + 1) * VOX;
            #pragma unroll
            for (int k = 0; k < 5; k++) hreg[k] = hval[k] ? __ldg(inp + hoff[k]) : 0.f;
            const float* wp_ = w + (size_t)(ci + 1) * wstride;
            #pragma unroll
            for (int k = 0; k < 4; k++) wreg[k] = wvalid[k] ? __ldg(wp_ + wbase[k]) : 0.f;
        }

        const float2* wp = &w_s2[cg * 4 * 27];
        #pragma unroll
        for (int dz = 0; dz < 3; dz++) {
            #pragma unroll
            for (int dy = 0; dy < 3; dy++) {
                const float* row = &in_s[(dz * 10 + ty + dy) * 36 + tx * 8];
                float4 a4 = *(const float4*)row;
                float4 b4 = *(const float4*)(row + 4);
                float2 c2 = *(const float2*)(row + 8);
                float v[10] = {a4.x, a4.y, a4.z, a4.w, b4.x, b4.y, b4.z, b4.w, c2.x, c2.y};
                u64 p[9];
                #pragma unroll
                for (int i = 0; i < 9; i++) p[i] = pk2(v[i], v[i + 1]);
                const int tb = dz * 9 + dy * 3;
                #pragma unroll
                for (int co = 0; co < 4; co++) {
                    const float2* wc = wp + co * 27 + tb;
                    u64 w0 = *(const u64*)(wc + 0);
                    fma2(acc[co][0], p[0], w0); fma2(acc[co][1], p[2], w0);
                    fma2(acc[co][2], p[4], w0); fma2(acc[co][3], p[6], w0);
                    u64 w1 = *(const u64*)(wc + 1);
                    fma2(acc[co][0], p[1], w1); fma2(acc[co][1], p[3], w1);
                    fma2(acc[co][2], p[5], w1); fma2(acc[co][3], p[7], w1);
                    u64 w2 = *(const u64*)(wc + 2);
                    fma2(acc[co][0], p[2], w2); fma2(acc[co][1], p[4], w2);
                    fma2(acc[co][2], p[6], w2); fma2(acc[co][3], p[8], w2);
                }
            }
        }
        __syncthreads();
    }

    const int xo = x0 + tx * 8;
    const size_t base = (size_t)zb * HW + (y0 + ty) * W_ + xo;
    #pragma unroll
    for (int co = 0; co < 4; co++) {
        int coG = coBase + cg * 4 + co;
        if (coG < Cout) {
            float2 q0 = unpk2(acc[co][0]);
            float2 q1 = unpk2(acc[co][1]);
            float2 q2 = unpk2(acc[co][2]);
            float2 q3 = unpk2(acc[co][3]);
            float* op = out + (size_t)coG * VOX + base;
            *(float4*)(op + 0) = make_float4(q0.x, q0.y, q1.x, q1.y);
            *(float4*)(op + 4) = make_float4(q2.x, q2.y, q3.x, q3.y);
        }
    }
}

// ============================ SRU kernels (float2, fast activations) ============
__global__ void si_sru_k(const float* __restrict__ g, float* __restrict__ out,
                         const float* __restrict__ add, int C, int rev)
{
    int tid = blockIdx.x * blockDim.x + threadIdx.x;
    int total = C * HW2;
    if (tid >= total) return;
    int c  = tid / HW2;
    int yx = (tid - c * HW2) * 2;

    const float2* Wp = (const float2*)(g + (size_t)(0 * C + c) * VOX + yx);
    const float2* Fp = (const float2*)(g + (size_t)(1 * C + c) * VOX + yx);
    const float2* Rp = (const float2*)(g + (size_t)(2 * C + c) * VOX + yx);
    const float2* Xp = (const float2*)(g + (size_t)(3 * C + c) * VOX + yx);
    float2*       op = (float2*)(out + (size_t)c * VOX + yx);
    const float2* ap = add ? (const float2*)(add + (size_t)c * VOX + yx) : nullptr;

    int off = rev ? (D_ - 1) * HW2 : 0;
    int zs  = rev ? -HW2 : HW2;

    float2 f = Fp[off], r = Rp[off], xv = Xp[off];
    float fx = sigm(f.x), fy = sigm(f.y);
    float Cx = 1.f - fx, Cy = 1.f - fy;
    float rx = sigm(r.x), ry = sigm(r.y);
    float hx = rx * Cx + (1.f - rx) * tanhx(xv.x);
    float hy = ry * Cy + (1.f - ry) * tanhx(xv.y);
    float2 av = ap ? ap[off] : make_float2(0.f, 0.f);
    op[off] = make_float2(hx + av.x, hy + av.y);

    for (int t = 1; t < D_; t++) {
        off += zs;
        f = Fp[off]; r = Rp[off]; xv = Xp[off];
        float2 wv = Wp[off];
        fx = sigm(f.x); fy = sigm(f.y);
        Cx = fx * Cx + (1.f - fx) * tanhx(wv.x);
        Cy = fy * Cy + (1.f - fy) * tanhx(wv.y);
        rx = sigm(r.x); ry = sigm(r.y);
        hx = rx * Cx + (1.f - rx) * tanhx(xv.x);
        hy = ry * Cy + (1.f - ry) * tanhx(xv.y);
        av = ap ? ap[off] : make_float2(0.f, 0.f);
        op[off] = make_float2(hx + av.x, hy + av.y);
    }
}

__global__ void do_sru_k(const float* __restrict__ g, float* __restrict__ out,
                         const float* __restrict__ add, int C)
{
    int tid = blockIdx.x * blockDim.x + threadIdx.x;
    int total = C * HW2;
    if (tid >= total) return;
    int c  = tid / HW2;
    int yx = (tid - c * HW2) * 2;

    const float2* Wp = (const float2*)(g + (size_t)(0 * C + c) * VOX + yx);
    const float2* F1 = (const float2*)(g + (size_t)(1 * C + c) * VOX + yx);
    const float2* F2 = (const float2*)(g + (size_t)(2 * C + c) * VOX + yx);
    const float2* R1 = (const float2*)(g + (size_t)(3 * C + c) * VOX + yx);
    const float2* R2 = (const float2*)(g + (size_t)(4 * C + c) * VOX + yx);
    const float2* Xp = (const float2*)(g + (size_t)(5 * C + c) * VOX + yx);
    float2*       op = (float2*)(out + (size_t)c * VOX + yx);
    const float2* ap = add ? (const float2*)(add + (size_t)c * VOX + yx) : nullptr;

    {
        float2 f = F1[0], r = R1[0], xv = Xp[0];
        float fx = sigm(f.x), fy = sigm(f.y);
        float Cx = 1.f - fx, Cy = 1.f - fy;
        float rx = sigm(r.x), ry = sigm(r.y);
        op[0] = make_float2(rx * Cx + (1.f - rx) * tanhx(xv.x),
                            ry * Cy + (1.f - ry) * tanhx(xv.y));
        int off = 0;
        for (int t = 1; t < D_; t++) {
            off += HW2;
            f = F1[off]; r = R1[off]; xv = Xp[off];
            float2 wv = Wp[off];
            fx = sigm(f.x); fy = sigm(f.y);
            Cx = fx * Cx + (1.f - fx) * tanhx(wv.x);
            Cy = fy * Cy + (1.f - fy) * tanhx(wv.y);
            rx = sigm(r.x); ry = sigm(r.y);
            op[off] = make_float2(rx * Cx + (1.f - rx) * tanhx(xv.x),
                                  ry * Cy + (1.f - ry) * tanhx(xv.y));
        }
    }
    {
        int off = (D_ - 1) * HW2;
        float2 f = F2[off], r = R2[off], xv = Xp[off];
        float fx = sigm(f.x), fy = sigm(f.y);
        float Cx = 1.f - fx, Cy = 1.f - fy;
        float rx = sigm(r.x), ry = sigm(r.y);
        float hx = rx * Cx + (1.f - rx) * tanhx(xv.x);
        float hy = ry * Cy + (1.f - ry) * tanhx(xv.y);
        float2 prev = op[off];
        float2 av = ap ? ap[off] : make_float2(0.f, 0.f);
        op[off] = make_float2(prev.x + hx + av.x, prev.y + hy + av.y);
        for (int t = 1; t < D_; t++) {
            off -= HW2;
            f = F2[off]; r = R2[off]; xv = Xp[off];
            float2 wv = Wp[off];
            fx = sigm(f.x); fy = sigm(f.y);
            Cx = fx * Cx + (1.f - fx) * tanhx(wv.x);
            Cy = fy * Cy + (1.f - fy) * tanhx(wv.y);
            rx = sigm(r.x); ry = sigm(r.y);
            hx = rx * Cx + (1.f - rx) * tanhx(xv.x);
            hy = ry * Cy + (1.f - ry) * tanhx(xv.y);
            prev = op[off];
            av = ap ? ap[off] : make_float2(0.f, 0.f);
            op[off] = make_float2(prev.x + hx + av.x, prev.y + hy + av.y);
        }
    }
}

// ============================ host ============================
static __half* s_Ahi;

static inline void conv_tc(const float* in, const float* w, float* out,
                           int Cin, int Cout, int deconv)
{
    int Kpad = Cin * 32;
    int total = Cout * Kpad;
    prep_k<<<(total + 255) / 256, 256>>>(w, s_Ahi, Cin, Cout, Kpad, deconv, total);
    dim3 grid(D_ * 48, Cout / 64);
    conv_mma_k<<<grid, 256>>>(in, s_Ahi, out, Cin, Kpad);
}

static inline void conv_scalar(const float* in, const float* w, float* out,
                               int Cin, int Cout, int deconv)
{
    dim3 grid(W_ / 32, (H_ / 8) * D_, (Cout + 31) / 32);
    conv3d_k<<<grid, 256>>>(in, w, out, Cin, Cout, deconv);
}

static inline void si_launch(const float* gbuf, float* out, const float* add, int C, int rev)
{
    int n = C * HW2;
    si_sru_k<<<(n + 255) / 256, 256>>>(gbuf, out, add, C, rev);
}
static inline void do_launch(const float* gbuf, float* out, const float* add, int C)
{
    int n = C * HW2;
    do_sru_k<<<(n + 255) / 256, 256>>>(gbuf, out, add, C);
}

extern "C" void kernel_launch(void* const* d_in, const int* in_sizes, int n_in,
                              void* d_out, int out_size)
{
    (void)in_sizes; (void)n_in; (void)out_size;
    const float* x      = (const float*)d_in[0];
    const float* w_head = (const float*)d_in[1];
    const float* w_e0   = (const float*)d_in[2];
    const float* w_e1   = (const float*)d_in[3];
    const float* w_d0   = (const float*)d_in[4];
    const float* w_d1   = (const float*)d_in[5];
    const float* w_tail = (const float*)d_in[6];
    float* out = (float*)d_out;

    float *gc, *gh, *ge0, *ge1, *gd0, *gd1;
    cudaGetSymbolAddress((void**)&gc,  g_conv);
    cudaGetSymbolAddress((void**)&gh,  g_h);
    cudaGetSymbolAddress((void**)&ge0, g_e0);
    cudaGetSymbolAddress((void**)&ge1, g_e1);
    cudaGetSymbolAddress((void**)&gd0, g_d0);
    cudaGetSymbolAddress((void**)&gd1, g_d1);
    cudaGetSymbolAddress((void**)&s_Ahi, g_Ahi);

    // h = do_sru(x, w_head)          (scalar: Cin=1)
    conv_scalar(x, w_head, gc, 1, 96, 0);
    do_launch(gc, gh, nullptr, 16);
    // e0 = si_sru(h, w_e0, fwd)      (mma: 16 -> 128)
    conv_tc(gh, w_e0, gc, 16, 128, 0);
    si_launch(gc, ge0, nullptr, 32, 0);
    // e1 = si_sru(e0, w_e1, rev)     (mma: 32 -> 256)
    conv_tc(ge0, w_e1, gc, 32, 256, 0);
    si_launch(gc, ge1, nullptr, 64, 1);
    // d0 = si_sru(e1, w_d0, fwd, deconv) + e0   (mma: 64 -> 128)
    conv_tc(ge1, w_d0, gc, 64, 128, 1);
    si_launch(gc, gd0, ge0, 32, 0);
    // d1 = si_sru(d0, w_d1, rev, deconv) + h    (mma: 32 -> 64)
    conv_tc(gd0, w_d1, gc, 32, 64, 1);
    si_launch(gc, gd1, gh, 16, 1);
    // out = do_sru(d1, w_tail, deconv) + x      (scalar: Cout=6)
    conv_scalar(gd1, w_tail, gc, 16, 6, 1);
    do_launch(gc, out, x, 1);
}

// round 15
// speedup vs baseline: 1.6627x; 1.0118x over previous
#include <cuda_runtime.h>
#include <cuda_fp16.h>
#include <math.h>
#include <stdint.h>

#define D_ 31
#define H_ 96
#define W_ 96
#define HW (H_*W_)        // 9216
#define HW2 (HW/2)
#define VOX (D_*HW)       // 285696

// ---- scratch (device globals; no allocation allowed) ----
__device__ float g_conv[256 * VOX];
__device__ float g_h  [16 * VOX];
__device__ float g_e0 [32 * VOX];
__device__ float g_e1 [64 * VOX];
__device__ float g_d0 [32 * VOX];
__device__ float g_d1 [16 * VOX];
__device__ __half g_Ahi[262144];   // weights fp16, [M x Kpad]

// ---- fast activations: ex2.approx + rcp.approx (rel err ~1e-6) ----
#define L2E 1.442695041f
__device__ __forceinline__ float ex2f(float a) {
    float r; asm("ex2.approx.f32 %0, %1;" : "=f"(r) : "f"(a)); return r;
}
__device__ __forceinline__ float rcpf(float a) {
    float r; asm("rcp.approx.f32 %0, %1;" : "=f"(r) : "f"(a)); return r;
}
__device__ __forceinline__ float sigm(float x) {
    return rcpf(1.f + ex2f(-L2E * x));
}
__device__ __forceinline__ float tanhx(float x) {
    return 1.f - 2.f * rcpf(1.f + ex2f(2.f * L2E * x));
}

typedef unsigned long long u64;
__device__ __forceinline__ void fma2(u64& d, u64 a, u64 b) {
    asm("fma.rn.f32x2 %0, %1, %2, %0;" : "+l"(d) : "l"(a), "l"(b));
}
__device__ __forceinline__ u64 pk2(float x, float y) {
    u64 r; asm("mov.b64 %0, {%1, %2};" : "=l"(r) : "f"(x), "f"(y)); return r;
}
__device__ __forceinline__ float2 unpk2(u64 a) {
    float x, y; asm("mov.b64 {%0, %1}, %2;" : "=f"(x), "=f"(y) : "l"(a));
    return make_float2(x, y);
}
__device__ __forceinline__ uint32_t smem_u32(const void* p) {
    uint32_t a;
    asm("{ .reg .u64 t; cvta.to.shared.u64 t, %1; cvt.u32.u64 %0, t; }" : "=r"(a) : "l"(p));
    return a;
}
__device__ __forceinline__ void ldsm4(uint32_t* r, uint32_t addr) {
    asm volatile("ldmatrix.sync.aligned.m8n8.x4.shared.b16 {%0,%1,%2,%3}, [%4];"
                 : "=r"(r[0]), "=r"(r[1]), "=r"(r[2]), "=r"(r[3]) : "r"(addr));
}
__device__ __forceinline__ void mma16816(float* c, const uint32_t* a, uint32_t b0, uint32_t b1) {
    asm volatile("mma.sync.aligned.m16n8k16.row.col.f32.f16.f16.f32 "
                 "{%0,%1,%2,%3},{%4,%5,%6,%7},{%8,%9},{%0,%1,%2,%3};"
                 : "+f"(c[0]), "+f"(c[1]), "+f"(c[2]), "+f"(c[3])
                 : "r"(a[0]), "r"(a[1]), "r"(a[2]), "r"(a[3]), "r"(b0), "r"(b1));
}
__device__ __forceinline__ uint32_t cvt_f16x2(float hi, float lo) {
    uint32_t r;
    asm("cvt.rn.f16x2.f32 %0, %1, %2;" : "=r"(r) : "f"(hi), "f"(lo));
    return r;
}
// cp.async 4B with zero-fill when szz==0
__device__ __forceinline__ void cpa4(uint32_t dst, const void* src, uint32_t szz) {
    asm volatile("cp.async.ca.shared.global [%0], [%1], 4, %2;"
                 :: "r"(dst), "l"(src), "r"(szz) : "memory");
}
__device__ __forceinline__ void cpa16(uint32_t dst, const void* src) {
    asm volatile("cp.async.cg.shared.global [%0], [%1], 16;"
                 :: "r"(dst), "l"(src) : "memory");
}
#define CP_COMMIT() asm volatile("cp.async.commit_group;" ::: "memory")
#define CP_WAIT0()  asm volatile("cp.async.wait_group 0;" ::: "memory")

// ============================================================================
// Weight prep: fp16 weights, layout A[m][k], k=ci*32+t (27 taps zero-padded).
// ============================================================================
__global__ void prep_k(const float* __restrict__ w, __half* __restrict__ Ahi,
                       int Cin, int Cout, int Kpad, int deconv, int total)
{
    int i = blockIdx.x * 256 + threadIdx.x;
    if (i >= total) return;
    int m = i / Kpad, k = i - m * Kpad;
    int t = k & 31, ci = k >> 5;
    float v = 0.f;
    if (t < 27 && m < Cout && ci < Cin)
        v = deconv ? w[((size_t)ci * Cout + m) * 27 + (26 - t)]
                   : w[((size_t)m * Cin + ci) * 27 + t];
    Ahi[i] = __float2half(v);
}

// ============================================================================
// Tensor-core implicit-GEMM conv, fp16 2-MMA scheme: D = Ahi*(Bhi + Blo).
// Block tile: M=64 co, N=192 (96x * 2y). 8 warps, each full M=64 x 24 N.
// Raw tile row stride 104 floats (104 mod 32 = 8 -> tap rows land 8 banks
// apart, cutting B-build LDS conflicts). cp.async double buffering.
// ============================================================================
#define KS 40
#define ABUF (64*KS)
#define RSTR 104            // raw row stride (floats)
#define RAW_E (12*RSTR)     // 1248
#define RAW_T (RAW_E+128)   // + zero pad

__global__ __launch_bounds__(256, 2)
void conv_mma_k(const float* __restrict__ in,
                const __half* __restrict__ Ahi,
                float* __restrict__ out,
                int Cin, int Kpad)
{
    __shared__ __align__(16) __half AsH[2][ABUF];
    __shared__ __align__(16) float rawS[2][RAW_T];

    const int tid  = threadIdx.x;
    const int wid  = tid >> 5, lane = tid & 31;
    const int g    = lane >> 2, t4 = lane & 3;
    const int bx   = blockIdx.x, mb = blockIdx.y;
    const int z    = bx / 48, y0 = (bx - z * 48) * 2;

    const int yp = wid >> 2;
    const int xw = (wid & 3) * 24;

    // ---- raw tile slot descriptors (loop-invariant) ----
    int  roff[5]; uint32_t rsz[5]; bool rin[5];
    #pragma unroll
    for (int k = 0; k < 5; k++) {
        int i = tid + k * 256;
        if (i < RAW_E) {
            int row = i / RSTR, col = i - row * RSTR;
            int zz = z + (row >> 2) - 1;
            int gy = y0 + (row & 3) - 1;
            int gx = col - 1;
            bool v = (col < 98) && ((unsigned)zz < D_) && ((unsigned)gy < H_) && ((unsigned)gx < W_);
            rin[k] = true; rsz[k] = v ? 4u : 0u;
            roff[k] = v ? (zz * HW + gy * 96 + gx) : 0;
        } else { rin[k] = false; rsz[k] = 0; roff[k] = 0; }
    }

    // ---- per-sub tap bases (loop-invariant; invalid -> zero pad) ----
    int tb[2][4];
    #pragma unroll
    for (int par = 0; par < 2; par++) {
        #pragma unroll
        for (int q = 0; q < 4; q++) {
            int t = par * 16 + 2 * t4 + (q & 1) + (q >> 1) * 8;
            if (t < 27) {
                int dz = t / 9, r9 = t - dz * 9;
                int dy = r9 / 3, dx = r9 - dy * 3;
                tb[par][q] = (dz * 4 + dy + yp) * RSTR + xw + g + dx;
            } else {
                tb[par][q] = RAW_E + g;
            }
        }
    }

    const int arow = tid >> 2, akoct = tid & 3;
    const uint32_t offA = (uint32_t)(((lane & 7) + ((lane >> 3) & 1) * 8) * KS + (lane >> 4) * 8) * 2;
    const uint32_t baAH = smem_u32(AsH);
    const uint32_t baRaw = smem_u32(rawS);
    const uint32_t aDst = baAH + (uint32_t)(arow * KS + akoct * 8) * 2;

    float acc[4][3][4];
    #pragma unroll
    for (int mt = 0; mt < 4; mt++)
        #pragma unroll
        for (int nt = 0; nt < 3; nt++)
            #pragma unroll
            for (int j = 0; j < 4; j++) acc[mt][nt][j] = 0.f;

    auto cpStage = [&](int ci, int buf) {
        const float* inp = in + (size_t)ci * VOX;
        const uint32_t rb = baRaw + buf * (RAW_T * 4);
        #pragma unroll
        for (int k = 0; k < 5; k++) {
            int i = tid + k * 256;
            if (rin[k]) cpa4(rb + i * 4, inp + roff[k], rsz[k]);
        }
        const __half* ap = Ahi + (size_t)(mb * 64 + arow) * Kpad + ci * 32 + akoct * 8;
        cpa16(aDst + buf * (ABUF * 2), ap);
        CP_COMMIT();
    };

    // ---- prologue: zero pads, stage ci=0 ----
    if (tid < RAW_T - RAW_E) {
        rawS[0][RAW_E + tid] = 0.f;
        rawS[1][RAW_E + tid] = 0.f;
    }
    cpStage(0, 0);
    CP_WAIT0();
    __syncthreads();

    for (int ci = 0; ci < Cin; ci++) {
        const int buf = ci & 1;
        const bool more = (ci + 1 < Cin);

        if (more) cpStage(ci + 1, 1 - buf);

        const float* rp = rawS[buf];
        const uint32_t saH = baAH + buf * (ABUF * 2);

        #pragma unroll
        for (int sub = 0; sub < 2; sub++) {
            uint32_t ah[4][4];
            #pragma unroll
            for (int mt = 0; mt < 4; mt++)
                ldsm4(ah[mt], saH + (mt * 16) * (KS*2) + offA + sub * 32);

            const int* tq = tb[sub];
            #pragma unroll
            for (int nt = 0; nt < 3; nt++) {
                const int o = nt * 8;
                float vA = rp[tq[0] + o];
                float vB = rp[tq[1] + o];
                float vC = rp[tq[2] + o];
                float vD = rp[tq[3] + o];
                uint32_t b0h = cvt_f16x2(vB, vA);
                uint32_t b1h = cvt_f16x2(vD, vC);
                half2 h0 = *(half2*)&b0h, h1 = *(half2*)&b1h;
                uint32_t b0l = cvt_f16x2(vB - __high2float(h0), vA - __low2float(h0));
                uint32_t b1l = cvt_f16x2(vD - __high2float(h1), vC - __low2float(h1));
                #pragma unroll
                for (int mt = 0; mt < 4; mt++) {
                    mma16816(acc[mt][nt], ah[mt], b0h, b1h);
                    mma16816(acc[mt][nt], ah[mt], b0l, b1l);
                }
            }
        }

        if (more) CP_WAIT0();
        __syncthreads();
    }

    // epilogue: Cout multiple of 64 for all mma layers
    const size_t zy = (size_t)z * HW + (size_t)(y0 + yp) * 96;
    #pragma unroll
    for (int mt = 0; mt < 4; mt++) {
        int co = mb * 64 + mt * 16 + g;
        #pragma unroll
        for (int nt = 0; nt < 3; nt++) {
            int x = xw + nt * 8 + t4 * 2;
            float* op = out + (size_t)co * VOX + zy + x;
            *(float2*)op = make_float2(acc[mt][nt][0], acc[mt][nt][1]);
            *(float2*)(op + (size_t)8 * VOX) = make_float2(acc[mt][nt][2], acc[mt][nt][3]);
        }
    }
}

// ============================================================================
// Scalar FFMA2 conv (head Cin=1 and tail Cout=6 layers).
// ============================================================================
#define HALO 1080
#define WTOT 864

__global__ __launch_bounds__(256, 2)
void conv3d_k(const float* __restrict__ in, const float* __restrict__ w,
              float* __restrict__ out, int Cin, int Cout, int deconv)
{
    __shared__ __align__(16) float  in_s[HALO];
    __shared__ __align__(8)  float2 w_s2[WTOT];

    const int tid = threadIdx.x;
    const int tx  = tid & 3;
    const int ty  = (tid >> 2) & 7;
    const int cg  = tid >> 5;

    const int x0 = blockIdx.x * 32;
    const int y0 = (blockIdx.y % 12) * 8;
    const int zb = blockIdx.y / 12;
    const int coBase = blockIdx.z * 32;

    int  hoff[5]; bool hval[5];
    #pragma unroll
    for (int k = 0; k < 5; k++) {
        int i = tid + k * 256;
        if (i < HALO) {
            int dz  = i / 360;
            int rem = i - dz * 360;
            int yy  = rem / 36;
            int xx  = rem - yy * 36;
            int z = zb + dz - 1, y = y0 + yy - 1, x = x0 + xx - 1;
            hval[k] = ((unsigned)z < D_) && ((unsigned)y < H_) && ((unsigned)x < W_) && (xx < 34);
            hoff[k] = z * HW + y * W_ + x;
        } else { hval[k] = false; hoff[k] = 0; }
    }
    int wbase[4]; bool wvalid[4];
    const int wstride = deconv ? Cout * 27 : 27;
    #pragma unroll
    for (int k = 0; k < 4; k++) {
        int idx = tid + k * 256;
        if (idx < WTOT) {
            int co = idx / 27, t = idx - co * 27;
            int coG = coBase + co;
            wvalid[k] = (coG < Cout);
            wbase[k]  = deconv ? (coG * 27 + (26 - t)) : (coG * Cin * 27 + t);
        } else { wvalid[k] = false; wbase[k] = 0; }
    }

    u64 acc[4][4];
    #pragma unroll
    for (int c = 0; c < 4; c++)
        #pragma unroll
        for (int j = 0; j < 4; j++) acc[c][j] = 0ull;

    float hreg[5], wreg[4];
    #pragma unroll
    for (int k = 0; k < 5; k++) hreg[k] = hval[k] ? __ldg(in + hoff[k]) : 0.f;
    #pragma unroll
    for (int k = 0; k < 4; k++) wreg[k] = wvalid[k] ? __ldg(w + wbase[k]) : 0.f;

    for (int ci = 0; ci < Cin; ci++) {
        #pragma unroll
        for (int k = 0; k < 5; k++) {
            int i = tid + k * 256;
            if (i < HALO) in_s[i] = hreg[k];
        }
        #pragma unroll
        for (int k = 0; k < 4; k++) {
            int idx = tid + k * 256;
            if (idx < WTOT) w_s2[idx] = make_float2(wreg[k], wreg[k]);
        }
        __syncthreads();

        if (ci + 1 < Cin) {
            const float* inp = in + (size_t)(ci + 1) * VOX;
            #pragma unroll
            for (int k = 0; k < 5; k++) hreg[k] = hval[k] ? __ldg(inp + hoff[k]) : 0.f;
            const float* wp_ = w + (size_t)(ci + 1) * wstride;
            #pragma unroll
            for (int k = 0; k < 4; k++) wreg[k] = wvalid[k] ? __ldg(wp_ + wbase[k]) : 0.f;
        }

        const float2* wp = &w_s2[cg * 4 * 27];
        #pragma unroll
        for (int dz = 0; dz < 3; dz++) {
            #pragma unroll
            for (int dy = 0; dy < 3; dy++) {
                const float* row = &in_s[(dz * 10 + ty + dy) * 36 + tx * 8];
                float4 a4 = *(const float4*)row;
                float4 b4 = *(const float4*)(row + 4);
                float2 c2 = *(const float2*)(row + 8);
                float v[10] = {a4.x, a4.y, a4.z, a4.w, b4.x, b4.y, b4.z, b4.w, c2.x, c2.y};
                u64 p[9];
                #pragma unroll
                for (int i = 0; i < 9; i++) p[i] = pk2(v[i], v[i + 1]);
                const int tb = dz * 9 + dy * 3;
                #pragma unroll
                for (int co = 0; co < 4; co++) {
                    const float2* wc = wp + co * 27 + tb;
                    u64 w0 = *(const u64*)(wc + 0);
                    fma2(acc[co][0], p[0], w0); fma2(acc[co][1], p[2], w0);
                    fma2(acc[co][2], p[4], w0); fma2(acc[co][3], p[6], w0);
                    u64 w1 = *(const u64*)(wc + 1);
                    fma2(acc[co][0], p[1], w1); fma2(acc[co][1], p[3], w1);
                    fma2(acc[co][2], p[5], w1); fma2(acc[co][3], p[7], w1);
                    u64 w2 = *(const u64*)(wc + 2);
                    fma2(acc[co][0], p[2], w2); fma2(acc[co][1], p[4], w2);
                    fma2(acc[co][2], p[6], w2); fma2(acc[co][3], p[8], w2);
                }
            }
        }
        __syncthreads();
    }

    const int xo = x0 + tx * 8;
    const size_t base = (size_t)zb * HW + (y0 + ty) * W_ + xo;
    #pragma unroll
    for (int co = 0; co < 4; co++) {
        int coG = coBase + cg * 4 + co;
        if (coG < Cout) {
            float2 q0 = unpk2(acc[co][0]);
            float2 q1 = unpk2(acc[co][1]);
            float2 q2 = unpk2(acc[co][2]);
            float2 q3 = unpk2(acc[co][3]);
            float* op = out + (size_t)coG * VOX + base;
            *(float4*)(op + 0) = make_float4(q0.x, q0.y, q1.x, q1.y);
            *(float4*)(op + 4) = make_float4(q2.x, q2.y, q3.x, q3.y);
        }
    }
}

// ============================ SRU kernels (float2, fast activations) ============
__global__ void si_sru_k(const float* __restrict__ g, float* __restrict__ out,
                         const float* __restrict__ add, int C, int rev)
{
    int tid = blockIdx.x * blockDim.x + threadIdx.x;
    int total = C * HW2;
    if (tid >= total) return;
    int c  = tid / HW2;
    int yx = (tid - c * HW2) * 2;

    const float2* Wp = (const float2*)(g + (size_t)(0 * C + c) * VOX + yx);
    const float2* Fp = (const float2*)(g + (size_t)(1 * C + c) * VOX + yx);
    const float2* Rp = (const float2*)(g + (size_t)(2 * C + c) * VOX + yx);
    const float2* Xp = (const float2*)(g + (size_t)(3 * C + c) * VOX + yx);
    float2*       op = (float2*)(out + (size_t)c * VOX + yx);
    const float2* ap = add ? (const float2*)(add + (size_t)c * VOX + yx) : nullptr;

    int off = rev ? (D_ - 1) * HW2 : 0;
    int zs  = rev ? -HW2 : HW2;

    float2 f = Fp[off], r = Rp[off], xv = Xp[off];
    float fx = sigm(f.x), fy = sigm(f.y);
    float Cx = 1.f - fx, Cy = 1.f - fy;
    float rx = sigm(r.x), ry = sigm(r.y);
    float hx = rx * Cx + (1.f - rx) * tanhx(xv.x);
    float hy = ry * Cy + (1.f - ry) * tanhx(xv.y);
    float2 av = ap ? ap[off] : make_float2(0.f, 0.f);
    op[off] = make_float2(hx + av.x, hy + av.y);

    for (int t = 1; t < D_; t++) {
        off += zs;
        f = Fp[off]; r = Rp[off]; xv = Xp[off];
        float2 wv = Wp[off];
        fx = sigm(f.x); fy = sigm(f.y);
        Cx = fx * Cx + (1.f - fx) * tanhx(wv.x);
        Cy = fy * Cy + (1.f - fy) * tanhx(wv.y);
        rx = sigm(r.x); ry = sigm(r.y);
        hx = rx * Cx + (1.f - rx) * tanhx(xv.x);
        hy = ry * Cy + (1.f - ry) * tanhx(xv.y);
        av = ap ? ap[off] : make_float2(0.f, 0.f);
        op[off] = make_float2(hx + av.x, hy + av.y);
    }
}

__global__ void do_sru_k(const float* __restrict__ g, float* __restrict__ out,
                         const float* __restrict__ add, int C)
{
    int tid = blockIdx.x * blockDim.x + threadIdx.x;
    int total = C * HW2;
    if (tid >= total) return;
    int c  = tid / HW2;
    int yx = (tid - c * HW2) * 2;

    const float2* Wp = (const float2*)(g + (size_t)(0 * C + c) * VOX + yx);
    const float2* F1 = (const float2*)(g + (size_t)(1 * C + c) * VOX + yx);
    const float2* F2 = (const float2*)(g + (size_t)(2 * C + c) * VOX + yx);
    const float2* R1 = (const float2*)(g + (size_t)(3 * C + c) * VOX + yx);
    const float2* R2 = (const float2*)(g + (size_t)(4 * C + c) * VOX + yx);
    const float2* Xp = (const float2*)(g + (size_t)(5 * C + c) * VOX + yx);
    float2*       op = (float2*)(out + (size_t)c * VOX + yx);
    const float2* ap = add ? (const float2*)(add + (size_t)c * VOX + yx) : nullptr;

    {
        float2 f = F1[0], r = R1[0], xv = Xp[0];
        float fx = sigm(f.x), fy = sigm(f.y);
        float Cx = 1.f - fx, Cy = 1.f - fy;
        float rx = sigm(r.x), ry = sigm(r.y);
        op[0] = make_float2(rx * Cx + (1.f - rx) * tanhx(xv.x),
                            ry * Cy + (1.f - ry) * tanhx(xv.y));
        int off = 0;
        for (int t = 1; t < D_; t++) {
            off += HW2;
            f = F1[off]; r = R1[off]; xv = Xp[off];
            float2 wv = Wp[off];
            fx = sigm(f.x); fy = sigm(f.y);
            Cx = fx * Cx + (1.f - fx) * tanhx(wv.x);
            Cy = fy * Cy + (1.f - fy) * tanhx(wv.y);
            rx = sigm(r.x); ry = sigm(r.y);
            op[off] = make_float2(rx * Cx + (1.f - rx) * tanhx(xv.x),
                                  ry * Cy + (1.f - ry) * tanhx(xv.y));
        }
    }
    {
        int off = (D_ - 1) * HW2;
        float2 f = F2[off], r = R2[off], xv = Xp[off];
        float fx = sigm(f.x), fy = sigm(f.y);
        float Cx = 1.f - fx, Cy = 1.f - fy;
        float rx = sigm(r.x), ry = sigm(r.y);
        float hx = rx * Cx + (1.f - rx) * tanhx(xv.x);
        float hy = ry * Cy + (1.f - ry) * tanhx(xv.y);
        float2 prev = op[off];
        float2 av = ap ? ap[off] : make_float2(0.f, 0.f);
        op[off] = make_float2(prev.x + hx + av.x, prev.y + hy + av.y);
        for (int t = 1; t < D_; t++) {
            off -= HW2;
            f = F2[off]; r = R2[off]; xv = Xp[off];
            float2 wv = Wp[off];
            fx = sigm(f.x); fy = sigm(f.y);
            Cx = fx * Cx + (1.f - fx) * tanhx(wv.x);
            Cy = fy * Cy + (1.f - fy) * tanhx(wv.y);
            rx = sigm(r.x); ry = sigm(r.y);
            hx = rx * Cx + (1.f - rx) * tanhx(xv.x);
            hy = ry * Cy + (1.f - ry) * tanhx(xv.y);
            prev = op[off];
            av = ap ? ap[off] : make_float2(0.f, 0.f);
            op[off] = make_float2(prev.x + hx + av.x, prev.y + hy + av.y);
        }
    }
}

// ============================ host ============================
static __half* s_Ahi;

static inline void conv_tc(const float* in, const float* w, float* out,
                           int Cin, int Cout, int deconv)
{
    int Kpad = Cin * 32;
    int total = Cout * Kpad;
    prep_k<<<(total + 255) / 256, 256>>>(w, s_Ahi, Cin, Cout, Kpad, deconv, total);
    dim3 grid(D_ * 48, Cout / 64);
    conv_mma_k<<<grid, 256>>>(in, s_Ahi, out, Cin, Kpad);
}

static inline void conv_scalar(const float* in, const float* w, float* out,
                               int Cin, int Cout, int deconv)
{
    dim3 grid(W_ / 32, (H_ / 8) * D_, (Cout + 31) / 32);
    conv3d_k<<<grid, 256>>>(in, w, out, Cin, Cout, deconv);
}

static inline void si_launch(const float* gbuf, float* out, const float* add, int C, int rev)
{
    int n = C * HW2;
    si_sru_k<<<(n + 255) / 256, 256>>>(gbuf, out, add, C, rev);
}
static inline void do_launch(const float* gbuf, float* out, const float* add, int C)
{
    int n = C * HW2;
    do_sru_k<<<(n + 255) / 256, 256>>>(gbuf, out, add, C);
}

extern "C" void kernel_launch(void* const* d_in, const int* in_sizes, int n_in,
                              void* d_out, int out_size)
{
    (void)in_sizes; (void)n_in; (void)out_size;
    const float* x      = (const float*)d_in[0];
    const float* w_head = (const float*)d_in[1];
    const float* w_e0   = (const float*)d_in[2];
    const float* w_e1   = (const float*)d_in[3];
    const float* w_d0   = (const float*)d_in[4];
    const float* w_d1   = (const float*)d_in[5];
    const float* w_tail = (const float*)d_in[6];
    float* out = (float*)d_out;

    float *gc, *gh, *ge0, *ge1, *gd0, *gd1;
    cudaGetSymbolAddress((void**)&gc,  g_conv);
    cudaGetSymbolAddress((void**)&gh,  g_h);
    cudaGetSymbolAddress((void**)&ge0, g_e0);
    cudaGetSymbolAddress((void**)&ge1, g_e1);
    cudaGetSymbolAddress((void**)&gd0, g_d0);
    cudaGetSymbolAddress((void**)&gd1, g_d1);
    cudaGetSymbolAddress((void**)&s_Ahi, g_Ahi);

    // h = do_sru(x, w_head)          (scalar: Cin=1)
    conv_scalar(x, w_head, gc, 1, 96, 0);
    do_launch(gc, gh, nullptr, 16);
    // e0 = si_sru(h, w_e0, fwd)      (mma: 16 -> 128)
    conv_tc(gh, w_e0, gc, 16, 128, 0);
    si_launch(gc, ge0, nullptr, 32, 0);
    // e1 = si_sru(e0, w_e1, rev)     (mma: 32 -> 256)
    conv_tc(ge0, w_e1, gc, 32, 256, 0);
    si_launch(gc, ge1, nullptr, 64, 1);
    // d0 = si_sru(e1, w_d0, fwd, deconv) + e0   (mma: 64 -> 128)
    conv_tc(ge1, w_d0, gc, 64, 128, 1);
    si_launch(gc, gd0, ge0, 32, 0);
    // d1 = si_sru(d0, w_d1, rev, deconv) + h    (mma: 32 -> 64)
    conv_tc(gd0, w_d1, gc, 32, 64, 1);
    si_launch(gc, gd1, gh, 16, 1);
    // out = do_sru(d1, w_tail, deconv) + x      (scalar: Cout=6)
    conv_scalar(gd1, w_tail, gc, 16, 6, 1);
    do_launch(gc, out, x, 1);
}

// round 16
// speedup vs baseline: 1.7391x; 1.0460x over previous
#include <cuda_runtime.h>
#include <cuda_fp16.h>
#include <math.h>
#include <stdint.h>

#define D_ 31
#define H_ 96
#define W_ 96
#define HW (H_*W_)        // 9216
#define HW2 (HW/2)
#define VOX (D_*HW)       // 285696

// ---- scratch (device globals; no allocation allowed) ----
__device__ float g_conv[256 * VOX];
__device__ float g_h  [16 * VOX];
__device__ float g_e0 [32 * VOX];
__device__ float g_e1 [64 * VOX];
__device__ float g_d0 [32 * VOX];
__device__ float g_d1 [16 * VOX];
__device__ __half g_Ahi[262144];   // weights fp16, [M x Kpad]

// ---- fast activations: ex2.approx + rcp.approx (rel err ~1e-6) ----
#define L2E 1.442695041f
__device__ __forceinline__ float ex2f(float a) {
    float r; asm("ex2.approx.f32 %0, %1;" : "=f"(r) : "f"(a)); return r;
}
__device__ __forceinline__ float rcpf(float a) {
    float r; asm("rcp.approx.f32 %0, %1;" : "=f"(r) : "f"(a)); return r;
}
__device__ __forceinline__ float sigm(float x) {
    return rcpf(1.f + ex2f(-L2E * x));
}
__device__ __forceinline__ float tanhx(float x) {
    return 1.f - 2.f * rcpf(1.f + ex2f(2.f * L2E * x));
}

typedef unsigned long long u64;
__device__ __forceinline__ void fma2(u64& d, u64 a, u64 b) {
    asm("fma.rn.f32x2 %0, %1, %2, %0;" : "+l"(d) : "l"(a), "l"(b));
}
__device__ __forceinline__ u64 pk2(float x, float y) {
    u64 r; asm("mov.b64 %0, {%1, %2};" : "=l"(r) : "f"(x), "f"(y)); return r;
}
__device__ __forceinline__ float2 unpk2(u64 a) {
    float x, y; asm("mov.b64 {%0, %1}, %2;" : "=f"(x), "=f"(y) : "l"(a));
    return make_float2(x, y);
}
__device__ __forceinline__ uint32_t smem_u32(const void* p) {
    uint32_t a;
    asm("{ .reg .u64 t; cvta.to.shared.u64 t, %1; cvt.u32.u64 %0, t; }" : "=r"(a) : "l"(p));
    return a;
}
__device__ __forceinline__ void ldsm4(uint32_t* r, uint32_t addr) {
    asm volatile("ldmatrix.sync.aligned.m8n8.x4.shared.b16 {%0,%1,%2,%3}, [%4];"
                 : "=r"(r[0]), "=r"(r[1]), "=r"(r[2]), "=r"(r[3]) : "r"(addr));
}
__device__ __forceinline__ void mma16816(float* c, const uint32_t* a, uint32_t b0, uint32_t b1) {
    asm volatile("mma.sync.aligned.m16n8k16.row.col.f32.f16.f16.f32 "
                 "{%0,%1,%2,%3},{%4,%5,%6,%7},{%8,%9},{%0,%1,%2,%3};"
                 : "+f"(c[0]), "+f"(c[1]), "+f"(c[2]), "+f"(c[3])
                 : "r"(a[0]), "r"(a[1]), "r"(a[2]), "r"(a[3]), "r"(b0), "r"(b1));
}
__device__ __forceinline__ uint32_t cvt_f16x2(float hi, float lo) {
    uint32_t r;
    asm("cvt.rn.f16x2.f32 %0, %1, %2;" : "=r"(r) : "f"(hi), "f"(lo));
    return r;
}
// cp.async 4B with zero-fill when szz==0
__device__ __forceinline__ void cpa4(uint32_t dst, const void* src, uint32_t szz) {
    asm volatile("cp.async.ca.shared.global [%0], [%1], 4, %2;"
                 :: "r"(dst), "l"(src), "r"(szz) : "memory");
}
__device__ __forceinline__ void cpa16(uint32_t dst, const void* src) {
    asm volatile("cp.async.cg.shared.global [%0], [%1], 16;"
                 :: "r"(dst), "l"(src) : "memory");
}
#define CP_COMMIT() asm volatile("cp.async.commit_group;" ::: "memory")
#define CP_WAIT0()  asm volatile("cp.async.wait_group 0;" ::: "memory")

// ============================================================================
// Weight prep: fp16 weights, layout A[m][k], k=ci*32+t (27 taps zero-padded).
// ============================================================================
__global__ void prep_k(const float* __restrict__ w, __half* __restrict__ Ahi,
                       int Cin, int Cout, int Kpad, int deconv, int total)
{
    int i = blockIdx.x * 256 + threadIdx.x;
    if (i >= total) return;
    int m = i / Kpad, k = i - m * Kpad;
    int t = k & 31, ci = k >> 5;
    float v = 0.f;
    if (t < 27 && m < Cout && ci < Cin)
        v = deconv ? w[((size_t)ci * Cout + m) * 27 + (26 - t)]
                   : w[((size_t)m * Cin + ci) * 27 + t];
    Ahi[i] = __float2half(v);
}

// ============================================================================
// Tensor-core implicit-GEMM conv, fp16 2-MMA scheme: D = Ahi*(Bhi + Blo).
// Block tile: M=64 co, N=192 (96x * 2y). 8 warps, each full M=64 x 24 N.
// Stage = 2 input channels (K=64) -> one barrier per ci-PAIR; cp.async
// double buffering with a 2x longer prefetch window.
// ============================================================================
#define KS 40
#define ABUF (64*KS)        // halves per ci slot
#define RSTR 104            // raw row stride (floats)
#define RAW_E (12*RSTR)     // 1248
#define RAW_T (RAW_E+128)   // + zero pad

__global__ __launch_bounds__(256, 2)
void conv_mma_k(const float* __restrict__ in,
                const __half* __restrict__ Ahi,
                float* __restrict__ out,
                int NCP, int Kpad)
{
    __shared__ __align__(16) __half AsH[4][ABUF];      // [stage*2 + slot]
    __shared__ __align__(16) float rawS[4][RAW_T];     // [stage*2 + slot]

    const int tid  = threadIdx.x;
    const int wid  = tid >> 5, lane = tid & 31;
    const int g    = lane >> 2, t4 = lane & 3;
    const int bx   = blockIdx.x, mb = blockIdx.y;
    const int z    = bx / 48, y0 = (bx - z * 48) * 2;

    const int yp = wid >> 2;
    const int xw = (wid & 3) * 24;

    // ---- raw tile slot descriptors (loop-invariant) ----
    int  roff[5]; uint32_t rsz[5]; bool rin[5];
    #pragma unroll
    for (int k = 0; k < 5; k++) {
        int i = tid + k * 256;
        if (i < RAW_E) {
            int row = i / RSTR, col = i - row * RSTR;
            int zz = z + (row >> 2) - 1;
            int gy = y0 + (row & 3) - 1;
            int gx = col - 1;
            bool v = (col < 98) && ((unsigned)zz < D_) && ((unsigned)gy < H_) && ((unsigned)gx < W_);
            rin[k] = true; rsz[k] = v ? 4u : 0u;
            roff[k] = v ? (zz * HW + gy * 96 + gx) : 0;
        } else { rin[k] = false; rsz[k] = 0; roff[k] = 0; }
    }

    // ---- per-sub tap bases (loop-invariant; invalid -> zero pad) ----
    int tb[2][4];
    #pragma unroll
    for (int par = 0; par < 2; par++) {
        #pragma unroll
        for (int q = 0; q < 4; q++) {
            int t = par * 16 + 2 * t4 + (q & 1) + (q >> 1) * 8;
            if (t < 27) {
                int dz = t / 9, r9 = t - dz * 9;
                int dy = r9 / 3, dx = r9 - dy * 3;
                tb[par][q] = (dz * 4 + dy + yp) * RSTR + xw + g + dx;
            } else {
                tb[par][q] = RAW_E + g;
            }
        }
    }

    const int arow = tid >> 2, akoct = tid & 3;
    const uint32_t offA = (uint32_t)(((lane & 7) + ((lane >> 3) & 1) * 8) * KS + (lane >> 4) * 8) * 2;
    const uint32_t baAH = smem_u32(AsH);
    const uint32_t baRaw = smem_u32(rawS);
    const uint32_t aDst = baAH + (uint32_t)(arow * KS + akoct * 8) * 2;

    float acc[4][3][4];
    #pragma unroll
    for (int mt = 0; mt < 4; mt++)
        #pragma unroll
        for (int nt = 0; nt < 3; nt++)
            #pragma unroll
            for (int j = 0; j < 4; j++) acc[mt][nt][j] = 0.f;

    // stage a ci-pair (2 channels) into stage buf (slots buf*2, buf*2+1)
    auto cpStage = [&](int cp, int buf) {
        #pragma unroll
        for (int s = 0; s < 2; s++) {
            const int ci = cp * 2 + s;
            const int slot = buf * 2 + s;
            const float* inp = in + (size_t)ci * VOX;
            const uint32_t rb = baRaw + slot * (RAW_T * 4);
            #pragma unroll
            for (int k = 0; k < 5; k++) {
                int i = tid + k * 256;
                if (rin[k]) cpa4(rb + i * 4, inp + roff[k], rsz[k]);
            }
            const __half* ap = Ahi + (size_t)(mb * 64 + arow) * Kpad + ci * 32 + akoct * 8;
            cpa16(aDst + slot * (ABUF * 2), ap);
        }
        CP_COMMIT();
    };

    // ---- prologue: zero pads (all 4 slots), stage pair 0 ----
    if (tid < 128) {
        #pragma unroll
        for (int s = 0; s < 4; s++) rawS[s][RAW_E + tid] = 0.f;
    }
    cpStage(0, 0);
    CP_WAIT0();
    __syncthreads();

    for (int cp = 0; cp < NCP; cp++) {
        const int buf = cp & 1;
        const bool more = (cp + 1 < NCP);

        if (more) cpStage(cp + 1, 1 - buf);

        #pragma unroll
        for (int s = 0; s < 2; s++) {
            const int slot = buf * 2 + s;
            const float* rp = rawS[slot];
            const uint32_t saH = baAH + slot * (ABUF * 2);

            #pragma unroll
            for (int sub = 0; sub < 2; sub++) {
                uint32_t ah[4][4];
                #pragma unroll
                for (int mt = 0; mt < 4; mt++)
                    ldsm4(ah[mt], saH + (mt * 16) * (KS*2) + offA + sub * 32);

                const int* tq = tb[sub];
                #pragma unroll
                for (int nt = 0; nt < 3; nt++) {
                    const int o = nt * 8;
                    float vA = rp[tq[0] + o];
                    float vB = rp[tq[1] + o];
                    float vC = rp[tq[2] + o];
                    float vD = rp[tq[3] + o];
                    uint32_t b0h = cvt_f16x2(vB, vA);
                    uint32_t b1h = cvt_f16x2(vD, vC);
                    half2 h0 = *(half2*)&b0h, h1 = *(half2*)&b1h;
                    uint32_t b0l = cvt_f16x2(vB - __high2float(h0), vA - __low2float(h0));
                    uint32_t b1l = cvt_f16x2(vD - __high2float(h1), vC - __low2float(h1));
                    #pragma unroll
                    for (int mt = 0; mt < 4; mt++) {
                        mma16816(acc[mt][nt], ah[mt], b0h, b1h);
                        mma16816(acc[mt][nt], ah[mt], b0l, b1l);
                    }
                }
            }
        }

        if (more) CP_WAIT0();
        __syncthreads();
    }

    // epilogue: Cout multiple of 64 for all mma layers
    const size_t zy = (size_t)z * HW + (size_t)(y0 + yp) * 96;
    #pragma unroll
    for (int mt = 0; mt < 4; mt++) {
        int co = mb * 64 + mt * 16 + g;
        #pragma unroll
        for (int nt = 0; nt < 3; nt++) {
            int x = xw + nt * 8 + t4 * 2;
            float* op = out + (size_t)co * VOX + zy + x;
            *(float2*)op = make_float2(acc[mt][nt][0], acc[mt][nt][1]);
            *(float2*)(op + (size_t)8 * VOX) = make_float2(acc[mt][nt][2], acc[mt][nt][3]);
        }
    }
}

// ============================================================================
// Scalar FFMA2 conv (head Cin=1 and tail Cout=6 layers).
// ============================================================================
#define HALO 1080
#define WTOT 864

__global__ __launch_bounds__(256, 2)
void conv3d_k(const float* __restrict__ in, const float* __restrict__ w,
              float* __restrict__ out, int Cin, int Cout, int deconv)
{
    __shared__ __align__(16) float  in_s[HALO];
    __shared__ __align__(8)  float2 w_s2[WTOT];

    const int tid = threadIdx.x;
    const int tx  = tid & 3;
    const int ty  = (tid >> 2) & 7;
    const int cg  = tid >> 5;

    const int x0 = blockIdx.x * 32;
    const int y0 = (blockIdx.y % 12) * 8;
    const int zb = blockIdx.y / 12;
    const int coBase = blockIdx.z * 32;

    int  hoff[5]; bool hval[5];
    #pragma unroll
    for (int k = 0; k < 5; k++) {
        int i = tid + k * 256;
        if (i < HALO) {
            int dz  = i / 360;
            int rem = i - dz * 360;
            int yy  = rem / 36;
            int xx  = rem - yy * 36;
            int z = zb + dz - 1, y = y0 + yy - 1, x = x0 + xx - 1;
            hval[k] = ((unsigned)z < D_) && ((unsigned)y < H_) && ((unsigned)x < W_) && (xx < 34);
            hoff[k] = z * HW + y * W_ + x;
        } else { hval[k] = false; hoff[k] = 0; }
    }
    int wbase[4]; bool wvalid[4];
    const int wstride = deconv ? Cout * 27 : 27;
    #pragma unroll
    for (int k = 0; k < 4; k++) {
        int idx = tid + k * 256;
        if (idx < WTOT) {
            int co = idx / 27, t = idx - co * 27;
            int coG = coBase + co;
            wvalid[k] = (coG < Cout);
            wbase[k]  = deconv ? (coG * 27 + (26 - t)) : (coG * Cin * 27 + t);
        } else { wvalid[k] = false; wbase[k] = 0; }
    }

    u64 acc[4][4];
    #pragma unroll
    for (int c = 0; c < 4; c++)
        #pragma unroll
        for (int j = 0; j < 4; j++) acc[c][j] = 0ull;

    float hreg[5], wreg[4];
    #pragma unroll
    for (int k = 0; k < 5; k++) hreg[k] = hval[k] ? __ldg(in + hoff[k]) : 0.f;
    #pragma unroll
    for (int k = 0; k < 4; k++) wreg[k] = wvalid[k] ? __ldg(w + wbase[k]) : 0.f;

    for (int ci = 0; ci < Cin; ci++) {
        #pragma unroll
        for (int k = 0; k < 5; k++) {
            int i = tid + k * 256;
            if (i < HALO) in_s[i] = hreg[k];
        }
        #pragma unroll
        for (int k = 0; k < 4; k++) {
            int idx = tid + k * 256;
            if (idx < WTOT) w_s2[idx] = make_float2(wreg[k], wreg[k]);
        }
        __syncthreads();

        if (ci + 1 < Cin) {
            const float* inp = in + (size_t)(ci + 1) * VOX;
            #pragma unroll
            for (int k = 0; k < 5; k++) hreg[k] = hval[k] ? __ldg(inp + hoff[k]) : 0.f;
            const float* wp_ = w + (size_t)(ci + 1) * wstride;
            #pragma unroll
            for (int k = 0; k < 4; k++) wreg[k] = wvalid[k] ? __ldg(wp_ + wbase[k]) : 0.f;
        }

        const float2* wp = &w_s2[cg * 4 * 27];
        #pragma unroll
        for (int dz = 0; dz < 3; dz++) {
            #pragma unroll
            for (int dy = 0; dy < 3; dy++) {
                const float* row = &in_s[(dz * 10 + ty + dy) * 36 + tx * 8];
                float4 a4 = *(const float4*)row;
                float4 b4 = *(const float4*)(row + 4);
                float2 c2 = *(const float2*)(row + 8);
                float v[10] = {a4.x, a4.y, a4.z, a4.w, b4.x, b4.y, b4.z, b4.w, c2.x, c2.y};
                u64 p[9];
                #pragma unroll
                for (int i = 0; i < 9; i++) p[i] = pk2(v[i], v[i + 1]);
                const int tb = dz * 9 + dy * 3;
                #pragma unroll
                for (int co = 0; co < 4; co++) {
                    const float2* wc = wp + co * 27 + tb;
                    u64 w0 = *(const u64*)(wc + 0);
                    fma2(acc[co][0], p[0], w0); fma2(acc[co][1], p[2], w0);
                    fma2(acc[co][2], p[4], w0); fma2(acc[co][3], p[6], w0);
                    u64 w1 = *(const u64*)(wc + 1);
                    fma2(acc[co][0], p[1], w1); fma2(acc[co][1], p[3], w1);
                    fma2(acc[co][2], p[5], w1); fma2(acc[co][3], p[7], w1);
                    u64 w2 = *(const u64*)(wc + 2);
                    fma2(acc[co][0], p[2], w2); fma2(acc[co][1], p[4], w2);
                    fma2(acc[co][2], p[6], w2); fma2(acc[co][3], p[8], w2);
                }
            }
        }
        __syncthreads();
    }

    const int xo = x0 + tx * 8;
    const size_t base = (size_t)zb * HW + (y0 + ty) * W_ + xo;
    #pragma unroll
    for (int co = 0; co < 4; co++) {
        int coG = coBase + cg * 4 + co;
        if (coG < Cout) {
            float2 q0 = unpk2(acc[co][0]);
            float2 q1 = unpk2(acc[co][1]);
            float2 q2 = unpk2(acc[co][2]);
            float2 q3 = unpk2(acc[co][3]);
            float* op = out + (size_t)coG * VOX + base;
            *(float4*)(op + 0) = make_float4(q0.x, q0.y, q1.x, q1.y);
            *(float4*)(op + 4) = make_float4(q2.x, q2.y, q3.x, q3.y);
        }
    }
}

// ============================ SRU kernels (float2, fast activations) ============
__global__ void si_sru_k(const float* __restrict__ g, float* __restrict__ out,
                         const float* __restrict__ add, int C, int rev)
{
    int tid = blockIdx.x * blockDim.x + threadIdx.x;
    int total = C * HW2;
    if (tid >= total) return;
    int c  = tid / HW2;
    int yx = (tid - c * HW2) * 2;

    const float2* Wp = (const float2*)(g + (size_t)(0 * C + c) * VOX + yx);
    const float2* Fp = (const float2*)(g + (size_t)(1 * C + c) * VOX + yx);
    const float2* Rp = (const float2*)(g + (size_t)(2 * C + c) * VOX + yx);
    const float2* Xp = (const float2*)(g + (size_t)(3 * C + c) * VOX + yx);
    float2*       op = (float2*)(out + (size_t)c * VOX + yx);
    const float2* ap = add ? (const float2*)(add + (size_t)c * VOX + yx) : nullptr;

    int off = rev ? (D_ - 1) * HW2 : 0;
    int zs  = rev ? -HW2 : HW2;

    float2 f = Fp[off], r = Rp[off], xv = Xp[off];
    float fx = sigm(f.x), fy = sigm(f.y);
    float Cx = 1.f - fx, Cy = 1.f - fy;
    float rx = sigm(r.x), ry = sigm(r.y);
    float hx = rx * Cx + (1.f - rx) * tanhx(xv.x);
    float hy = ry * Cy + (1.f - ry) * tanhx(xv.y);
    float2 av = ap ? ap[off] : make_float2(0.f, 0.f);
    op[off] = make_float2(hx + av.x, hy + av.y);

    for (int t = 1; t < D_; t++) {
        off += zs;
        f = Fp[off]; r = Rp[off]; xv = Xp[off];
        float2 wv = Wp[off];
        fx = sigm(f.x); fy = sigm(f.y);
        Cx = fx * Cx + (1.f - fx) * tanhx(wv.x);
        Cy = fy * Cy + (1.f - fy) * tanhx(wv.y);
        rx = sigm(r.x); ry = sigm(r.y);
        hx = rx * Cx + (1.f - rx) * tanhx(xv.x);
        hy = ry * Cy + (1.f - ry) * tanhx(xv.y);
        av = ap ? ap[off] : make_float2(0.f, 0.f);
        op[off] = make_float2(hx + av.x, hy + av.y);
    }
}

__global__ void do_sru_k(const float* __restrict__ g, float* __restrict__ out,
                         const float* __restrict__ add, int C)
{
    int tid = blockIdx.x * blockDim.x + threadIdx.x;
    int total = C * HW2;
    if (tid >= total) return;
    int c  = tid / HW2;
    int yx = (tid - c * HW2) * 2;

    const float2* Wp = (const float2*)(g + (size_t)(0 * C + c) * VOX + yx);
    const float2* F1 = (const float2*)(g + (size_t)(1 * C + c) * VOX + yx);
    const float2* F2 = (const float2*)(g + (size_t)(2 * C + c) * VOX + yx);
    const float2* R1 = (const float2*)(g + (size_t)(3 * C + c) * VOX + yx);
    const float2* R2 = (const float2*)(g + (size_t)(4 * C + c) * VOX + yx);
    const float2* Xp = (const float2*)(g + (size_t)(5 * C + c) * VOX + yx);
    float2*       op = (float2*)(out + (size_t)c * VOX + yx);
    const float2* ap = add ? (const float2*)(add + (size_t)c * VOX + yx) : nullptr;

    {
        float2 f = F1[0], r = R1[0], xv = Xp[0];
        float fx = sigm(f.x), fy = sigm(f.y);
        float Cx = 1.f - fx, Cy = 1.f - fy;
        float rx = sigm(r.x), ry = sigm(r.y);
        op[0] = make_float2(rx * Cx + (1.f - rx) * tanhx(xv.x),
                            ry * Cy + (1.f - ry) * tanhx(xv.y));
        int off = 0;
        for (int t = 1; t < D_; t++) {
            off += HW2;
            f = F1[off]; r = R1[off]; xv = Xp[off];
            float2 wv = Wp[off];
            fx = sigm(f.x); fy = sigm(f.y);
            Cx = fx * Cx + (1.f - fx) * tanhx(wv.x);
            Cy = fy * Cy + (1.f - fy) * tanhx(wv.y);
            rx = sigm(r.x); ry = sigm(r.y);
            op[off] = make_float2(rx * Cx + (1.f - rx) * tanhx(xv.x),
                                  ry * Cy + (1.f - ry) * tanhx(xv.y));
        }
    }
    {
        int off = (D_ - 1) * HW2;
        float2 f = F2[off], r = R2[off], xv = Xp[off];
        float fx = sigm(f.x), fy = sigm(f.y);
        float Cx = 1.f - fx, Cy = 1.f - fy;
        float rx = sigm(r.x), ry = sigm(r.y);
        float hx = rx * Cx + (1.f - rx) * tanhx(xv.x);
        float hy = ry * Cy + (1.f - ry) * tanhx(xv.y);
        float2 prev = op[off];
        float2 av = ap ? ap[off] : make_float2(0.f, 0.f);
        op[off] = make_float2(prev.x + hx + av.x, prev.y + hy + av.y);
        for (int t = 1; t < D_; t++) {
            off -= HW2;
            f = F2[off]; r = R2[off]; xv = Xp[off];
            float2 wv = Wp[off];
            fx = sigm(f.x); fy = sigm(f.y);
            Cx = fx * Cx + (1.f - fx) * tanhx(wv.x);
            Cy = fy * Cy + (1.f - fy) * tanhx(wv.y);
            rx = sigm(r.x); ry = sigm(r.y);
            hx = rx * Cx + (1.f - rx) * tanhx(xv.x);
            hy = ry * Cy + (1.f - ry) * tanhx(xv.y);
            prev = op[off];
            av = ap ? ap[off] : make_float2(0.f, 0.f);
            op[off] = make_float2(prev.x + hx + av.x, prev.y + hy + av.y);
        }
    }
}

// ============================ host ============================
static __half* s_Ahi;

static inline void conv_tc(const float* in, const float* w, float* out,
                           int Cin, int Cout, int deconv)
{
    int Kpad = Cin * 32;
    int total = Cout * Kpad;
    prep_k<<<(total + 255) / 256, 256>>>(w, s_Ahi, Cin, Cout, Kpad, deconv, total);
    dim3 grid(D_ * 48, Cout / 64);
    conv_mma_k<<<grid, 256>>>(in, s_Ahi, out, Cin / 2, Kpad);
}

static inline void conv_scalar(const float* in, const float* w, float* out,
                               int Cin, int Cout, int deconv)
{
    dim3 grid(W_ / 32, (H_ / 8) * D_, (Cout + 31) / 32);
    conv3d_k<<<grid, 256>>>(in, w, out, Cin, Cout, deconv);
}

static inline void si_launch(const float* gbuf, float* out, const float* add, int C, int rev)
{
    int n = C * HW2;
    si_sru_k<<<(n + 255) / 256, 256>>>(gbuf, out, add, C, rev);
}
static inline void do_launch(const float* gbuf, float* out, const float* add, int C)
{
    int n = C * HW2;
    do_sru_k<<<(n + 255) / 256, 256>>>(gbuf, out, add, C);
}

extern "C" void kernel_launch(void* const* d_in, const int* in_sizes, int n_in,
                              void* d_out, int out_size)
{
    (void)in_sizes; (void)n_in; (void)out_size;
    const float* x      = (const float*)d_in[0];
    const float* w_head = (const float*)d_in[1];
    const float* w_e0   = (const float*)d_in[2];
    const float* w_e1   = (const float*)d_in[3];
    const float* w_d0   = (const float*)d_in[4];
    const float* w_d1   = (const float*)d_in[5];
    const float* w_tail = (const float*)d_in[6];
    float* out = (float*)d_out;

    float *gc, *gh, *ge0, *ge1, *gd0, *gd1;
    cudaGetSymbolAddress((void**)&gc,  g_conv);
    cudaGetSymbolAddress((void**)&gh,  g_h);
    cudaGetSymbolAddress((void**)&ge0, g_e0);
    cudaGetSymbolAddress((void**)&ge1, g_e1);
    cudaGetSymbolAddress((void**)&gd0, g_d0);
    cudaGetSymbolAddress((void**)&gd1, g_d1);
    cudaGetSymbolAddress((void**)&s_Ahi, g_Ahi);

    // h = do_sru(x, w_head)          (scalar: Cin=1)
    conv_scalar(x, w_head, gc, 1, 96, 0);
    do_launch(gc, gh, nullptr, 16);
    // e0 = si_sru(h, w_e0, fwd)      (mma: 16 -> 128)
    conv_tc(gh, w_e0, gc, 16, 128, 0);
    si_launch(gc, ge0, nullptr, 32, 0);
    // e1 = si_sru(e0, w_e1, rev)     (mma: 32 -> 256)
    conv_tc(ge0, w_e1, gc, 32, 256, 0);
    si_launch(gc, ge1, nullptr, 64, 1);
    // d0 = si_sru(e1, w_d0, fwd, deconv) + e0   (mma: 64 -> 128)
    conv_tc(ge1, w_d0, gc, 64, 128, 1);
    si_launch(gc, gd0, ge0, 32, 0);
    // d1 = si_sru(d0, w_d1, rev, deconv) + h    (mma: 32 -> 64)
    conv_tc(gd0, w_d1, gc, 32, 64, 1);
    si_launch(gc, gd1, gh, 16, 1);
    // out = do_sru(d1, w_tail, deconv) + x      (scalar: Cout=6)
    conv_scalar(gd1, w_tail, gc, 16, 6, 1);
    do_launch(gc, out, x, 1);
}

// round 17
// speedup vs baseline: 2.1018x; 1.2085x over previous
#include <cuda_runtime.h>
#include <cuda_fp16.h>
#include <math.h>
#include <stdint.h>

#define D_ 31
#define H_ 96
#define W_ 96
#define HW (H_*W_)        // 9216
#define HW2 (HW/2)
#define VOX (D_*HW)       // 285696

// ---- scratch (device globals; no allocation allowed) ----
__device__ float g_conv[256 * VOX];
__device__ float g_h  [16 * VOX];
__device__ float g_e0 [32 * VOX];
__device__ float g_e1 [64 * VOX];
__device__ float g_d0 [32 * VOX];
__device__ float g_d1 [16 * VOX];
__device__ __half g_Ahi[262144];   // weights fp16, [M x Kpad]

// ---- fast activations: ex2.approx + rcp.approx (rel err ~1e-6) ----
#define L2E 1.442695041f
__device__ __forceinline__ float ex2f(float a) {
    float r; asm("ex2.approx.f32 %0, %1;" : "=f"(r) : "f"(a)); return r;
}
__device__ __forceinline__ float rcpf(float a) {
    float r; asm("rcp.approx.f32 %0, %1;" : "=f"(r) : "f"(a)); return r;
}
__device__ __forceinline__ float sigm(float x) {
    return rcpf(1.f + ex2f(-L2E * x));
}
__device__ __forceinline__ float tanhx(float x) {
    return 1.f - 2.f * rcpf(1.f + ex2f(2.f * L2E * x));
}

typedef unsigned long long u64;
__device__ __forceinline__ void fma2(u64& d, u64 a, u64 b) {
    asm("fma.rn.f32x2 %0, %1, %2, %0;" : "+l"(d) : "l"(a), "l"(b));
}
__device__ __forceinline__ u64 pk2(float x, float y) {
    u64 r; asm("mov.b64 %0, {%1, %2};" : "=l"(r) : "f"(x), "f"(y)); return r;
}
__device__ __forceinline__ float2 unpk2(u64 a) {
    float x, y; asm("mov.b64 {%0, %1}, %2;" : "=f"(x), "=f"(y) : "l"(a));
    return make_float2(x, y);
}
__device__ __forceinline__ uint32_t smem_u32(const void* p) {
    uint32_t a;
    asm("{ .reg .u64 t; cvta.to.shared.u64 t, %1; cvt.u32.u64 %0, t; }" : "=r"(a) : "l"(p));
    return a;
}
__device__ __forceinline__ void ldsm4(uint32_t* r, uint32_t addr) {
    asm volatile("ldmatrix.sync.aligned.m8n8.x4.shared.b16 {%0,%1,%2,%3}, [%4];"
                 : "=r"(r[0]), "=r"(r[1]), "=r"(r[2]), "=r"(r[3]) : "r"(addr));
}
__device__ __forceinline__ void mma16816(float* c, const uint32_t* a, uint32_t b0, uint32_t b1) {
    asm volatile("mma.sync.aligned.m16n8k16.row.col.f32.f16.f16.f32 "
                 "{%0,%1,%2,%3},{%4,%5,%6,%7},{%8,%9},{%0,%1,%2,%3};"
                 : "+f"(c[0]), "+f"(c[1]), "+f"(c[2]), "+f"(c[3])
                 : "r"(a[0]), "r"(a[1]), "r"(a[2]), "r"(a[3]), "r"(b0), "r"(b1));
}
__device__ __forceinline__ uint32_t cvt_f16x2(float hi, float lo) {
    uint32_t r;
    asm("cvt.rn.f16x2.f32 %0, %1, %2;" : "=r"(r) : "f"(hi), "f"(lo));
    return r;
}
// cp.async 4B with zero-fill when szz==0
__device__ __forceinline__ void cpa4(uint32_t dst, const void* src, uint32_t szz) {
    asm volatile("cp.async.ca.shared.global [%0], [%1], 4, %2;"
                 :: "r"(dst), "l"(src), "r"(szz) : "memory");
}
__device__ __forceinline__ void cpa16(uint32_t dst, const void* src) {
    asm volatile("cp.async.cg.shared.global [%0], [%1], 16;"
                 :: "r"(dst), "l"(src) : "memory");
}
#define CP_COMMIT() asm volatile("cp.async.commit_group;" ::: "memory")
#define CP_WAIT0()  asm volatile("cp.async.wait_group 0;" ::: "memory")

// ============================================================================
// Weight prep: fp16 weights, layout A[m][k], k=ci*32+t (27 taps zero-padded).
// ============================================================================
__global__ void prep_k(const float* __restrict__ w, __half* __restrict__ Ahi,
                       int Cin, int Cout, int Kpad, int deconv, int total)
{
    int i = blockIdx.x * 256 + threadIdx.x;
    if (i >= total) return;
    int m = i / Kpad, k = i - m * Kpad;
    int t = k & 31, ci = k >> 5;
    float v = 0.f;
    if (t < 27 && m < Cout && ci < Cin)
        v = deconv ? w[((size_t)ci * Cout + m) * 27 + (26 - t)]
                   : w[((size_t)m * Cin + ci) * 27 + t];
    Ahi[i] = __float2half(v);
}

// ============================================================================
// Tensor-core implicit-GEMM conv, single-MMA fp16 scheme: D = A_f16 * B_f16.
// Block tile: M=64 co, N=192 (96x * 2y). 8 warps, each full M=64 x 24 N.
// Stage = 2 input channels (K=64) -> one barrier per ci-PAIR; cp.async
// double buffering.
// ============================================================================
#define KS 40
#define ABUF (64*KS)        // halves per ci slot
#define RSTR 104            // raw row stride (floats)
#define RAW_E (12*RSTR)     // 1248
#define RAW_T (RAW_E+128)   // + zero pad

__global__ __launch_bounds__(256, 2)
void conv_mma_k(const float* __restrict__ in,
                const __half* __restrict__ Ahi,
                float* __restrict__ out,
                int NCP, int Kpad)
{
    __shared__ __align__(16) __half AsH[4][ABUF];      // [stage*2 + slot]
    __shared__ __align__(16) float rawS[4][RAW_T];     // [stage*2 + slot]

    const int tid  = threadIdx.x;
    const int wid  = tid >> 5, lane = tid & 31;
    const int g    = lane >> 2, t4 = lane & 3;
    const int bx   = blockIdx.x, mb = blockIdx.y;
    const int z    = bx / 48, y0 = (bx - z * 48) * 2;

    const int yp = wid >> 2;
    const int xw = (wid & 3) * 24;

    // ---- raw tile slot descriptors (loop-invariant) ----
    int  roff[5]; uint32_t rsz[5]; bool rin[5];
    #pragma unroll
    for (int k = 0; k < 5; k++) {
        int i = tid + k * 256;
        if (i < RAW_E) {
            int row = i / RSTR, col = i - row * RSTR;
            int zz = z + (row >> 2) - 1;
            int gy = y0 + (row & 3) - 1;
            int gx = col - 1;
            bool v = (col < 98) && ((unsigned)zz < D_) && ((unsigned)gy < H_) && ((unsigned)gx < W_);
            rin[k] = true; rsz[k] = v ? 4u : 0u;
            roff[k] = v ? (zz * HW + gy * 96 + gx) : 0;
        } else { rin[k] = false; rsz[k] = 0; roff[k] = 0; }
    }

    // ---- per-sub tap bases (loop-invariant; invalid -> zero pad) ----
    int tb[2][4];
    #pragma unroll
    for (int par = 0; par < 2; par++) {
        #pragma unroll
        for (int q = 0; q < 4; q++) {
            int t = par * 16 + 2 * t4 + (q & 1) + (q >> 1) * 8;
            if (t < 27) {
                int dz = t / 9, r9 = t - dz * 9;
                int dy = r9 / 3, dx = r9 - dy * 3;
                tb[par][q] = (dz * 4 + dy + yp) * RSTR + xw + g + dx;
            } else {
                tb[par][q] = RAW_E + g;
            }
        }
    }

    const int arow = tid >> 2, akoct = tid & 3;
    const uint32_t offA = (uint32_t)(((lane & 7) + ((lane >> 3) & 1) * 8) * KS + (lane >> 4) * 8) * 2;
    const uint32_t baAH = smem_u32(AsH);
    const uint32_t baRaw = smem_u32(rawS);
    const uint32_t aDst = baAH + (uint32_t)(arow * KS + akoct * 8) * 2;

    float acc[4][3][4];
    #pragma unroll
    for (int mt = 0; mt < 4; mt++)
        #pragma unroll
        for (int nt = 0; nt < 3; nt++)
            #pragma unroll
            for (int j = 0; j < 4; j++) acc[mt][nt][j] = 0.f;

    // stage a ci-pair (2 channels) into stage buf (slots buf*2, buf*2+1)
    auto cpStage = [&](int cp, int buf) {
        #pragma unroll
        for (int s = 0; s < 2; s++) {
            const int ci = cp * 2 + s;
            const int slot = buf * 2 + s;
            const float* inp = in + (size_t)ci * VOX;
            const uint32_t rb = baRaw + slot * (RAW_T * 4);
            #pragma unroll
            for (int k = 0; k < 5; k++) {
                int i = tid + k * 256;
                if (rin[k]) cpa4(rb + i * 4, inp + roff[k], rsz[k]);
            }
            const __half* ap = Ahi + (size_t)(mb * 64 + arow) * Kpad + ci * 32 + akoct * 8;
            cpa16(aDst + slot * (ABUF * 2), ap);
        }
        CP_COMMIT();
    };

    // ---- prologue: zero pads (all 4 slots), stage pair 0 ----
    if (tid < 128) {
        #pragma unroll
        for (int s = 0; s < 4; s++) rawS[s][RAW_E + tid] = 0.f;
    }
    cpStage(0, 0);
    CP_WAIT0();
    __syncthreads();

    for (int cp = 0; cp < NCP; cp++) {
        const int buf = cp & 1;
        const bool more = (cp + 1 < NCP);

        if (more) cpStage(cp + 1, 1 - buf);

        #pragma unroll
        for (int s = 0; s < 2; s++) {
            const int slot = buf * 2 + s;
            const float* rp = rawS[slot];
            const uint32_t saH = baAH + slot * (ABUF * 2);

            #pragma unroll
            for (int sub = 0; sub < 2; sub++) {
                uint32_t ah[4][4];
                #pragma unroll
                for (int mt = 0; mt < 4; mt++)
                    ldsm4(ah[mt], saH + (mt * 16) * (KS*2) + offA + sub * 32);

                const int* tq = tb[sub];
                #pragma unroll
                for (int nt = 0; nt < 3; nt++) {
                    const int o = nt * 8;
                    float vA = rp[tq[0] + o];
                    float vB = rp[tq[1] + o];
                    float vC = rp[tq[2] + o];
                    float vD = rp[tq[3] + o];
                    uint32_t b0 = cvt_f16x2(vB, vA);
                    uint32_t b1 = cvt_f16x2(vD, vC);
                    #pragma unroll
                    for (int mt = 0; mt < 4; mt++)
                        mma16816(acc[mt][nt], ah[mt], b0, b1);
                }
            }
        }

        if (more) CP_WAIT0();
        __syncthreads();
    }

    // epilogue: Cout multiple of 64 for all mma layers
    const size_t zy = (size_t)z * HW + (size_t)(y0 + yp) * 96;
    #pragma unroll
    for (int mt = 0; mt < 4; mt++) {
        int co = mb * 64 + mt * 16 + g;
        #pragma unroll
        for (int nt = 0; nt < 3; nt++) {
            int x = xw + nt * 8 + t4 * 2;
            float* op = out + (size_t)co * VOX + zy + x;
            *(float2*)op = make_float2(acc[mt][nt][0], acc[mt][nt][1]);
            *(float2*)(op + (size_t)8 * VOX) = make_float2(acc[mt][nt][2], acc[mt][nt][3]);
        }
    }
}

// ============================================================================
// Scalar FFMA2 conv (head Cin=1 and tail Cout=6 layers).
// ============================================================================
#define HALO 1080
#define WTOT 864

__global__ __launch_bounds__(256, 2)
void conv3d_k(const float* __restrict__ in, const float* __restrict__ w,
              float* __restrict__ out, int Cin, int Cout, int deconv)
{
    __shared__ __align__(16) float  in_s[HALO];
    __shared__ __align__(8)  float2 w_s2[WTOT];

    const int tid = threadIdx.x;
    const int tx  = tid & 3;
    const int ty  = (tid >> 2) & 7;
    const int cg  = tid >> 5;

    const int x0 = blockIdx.x * 32;
    const int y0 = (blockIdx.y % 12) * 8;
    const int zb = blockIdx.y / 12;
    const int coBase = blockIdx.z * 32;

    int  hoff[5]; bool hval[5];
    #pragma unroll
    for (int k = 0; k < 5; k++) {
        int i = tid + k * 256;
        if (i < HALO) {
            int dz  = i / 360;
            int rem = i - dz * 360;
            int yy  = rem / 36;
            int xx  = rem - yy * 36;
            int z = zb + dz - 1, y = y0 + yy - 1, x = x0 + xx - 1;
            hval[k] = ((unsigned)z < D_) && ((unsigned)y < H_) && ((unsigned)x < W_) && (xx < 34);
            hoff[k] = z * HW + y * W_ + x;
        } else { hval[k] = false; hoff[k] = 0; }
    }
    int wbase[4]; bool wvalid[4];
    const int wstride = deconv ? Cout * 27 : 27;
    #pragma unroll
    for (int k = 0; k < 4; k++) {
        int idx = tid + k * 256;
        if (idx < WTOT) {
            int co = idx / 27, t = idx - co * 27;
            int coG = coBase + co;
            wvalid[k] = (coG < Cout);
            wbase[k]  = deconv ? (coG * 27 + (26 - t)) : (coG * Cin * 27 + t);
        } else { wvalid[k] = false; wbase[k] = 0; }
    }

    u64 acc[4][4];
    #pragma unroll
    for (int c = 0; c < 4; c++)
        #pragma unroll
        for (int j = 0; j < 4; j++) acc[c][j] = 0ull;

    float hreg[5], wreg[4];
    #pragma unroll
    for (int k = 0; k < 5; k++) hreg[k] = hval[k] ? __ldg(in + hoff[k]) : 0.f;
    #pragma unroll
    for (int k = 0; k < 4; k++) wreg[k] = wvalid[k] ? __ldg(w + wbase[k]) : 0.f;

    for (int ci = 0; ci < Cin; ci++) {
        #pragma unroll
        for (int k = 0; k < 5; k++) {
            int i = tid + k * 256;
            if (i < HALO) in_s[i] = hreg[k];
        }
        #pragma unroll
        for (int k = 0; k < 4; k++) {
            int idx = tid + k * 256;
            if (idx < WTOT) w_s2[idx] = make_float2(wreg[k], wreg[k]);
        }
        __syncthreads();

        if (ci + 1 < Cin) {
            const float* inp = in + (size_t)(ci + 1) * VOX;
            #pragma unroll
            for (int k = 0; k < 5; k++) hreg[k] = hval[k] ? __ldg(inp + hoff[k]) : 0.f;
            const float* wp_ = w + (size_t)(ci + 1) * wstride;
            #pragma unroll
            for (int k = 0; k < 4; k++) wreg[k] = wvalid[k] ? __ldg(wp_ + wbase[k]) : 0.f;
        }

        const float2* wp = &w_s2[cg * 4 * 27];
        #pragma unroll
        for (int dz = 0; dz < 3; dz++) {
            #pragma unroll
            for (int dy = 0; dy < 3; dy++) {
                const float* row = &in_s[(dz * 10 + ty + dy) * 36 + tx * 8];
                float4 a4 = *(const float4*)row;
                float4 b4 = *(const float4*)(row + 4);
                float2 c2 = *(const float2*)(row + 8);
                float v[10] = {a4.x, a4.y, a4.z, a4.w, b4.x, b4.y, b4.z, b4.w, c2.x, c2.y};
                u64 p[9];
                #pragma unroll
                for (int i = 0; i < 9; i++) p[i] = pk2(v[i], v[i + 1]);
                const int tb = dz * 9 + dy * 3;
                #pragma unroll
                for (int co = 0; co < 4; co++) {
                    const float2* wc = wp + co * 27 + tb;
                    u64 w0 = *(const u64*)(wc + 0);
                    fma2(acc[co][0], p[0], w0); fma2(acc[co][1], p[2], w0);
                    fma2(acc[co][2], p[4], w0); fma2(acc[co][3], p[6], w0);
                    u64 w1 = *(const u64*)(wc + 1);
                    fma2(acc[co][0], p[1], w1); fma2(acc[co][1], p[3], w1);
                    fma2(acc[co][2], p[5], w1); fma2(acc[co][3], p[7], w1);
                    u64 w2 = *(const u64*)(wc + 2);
                    fma2(acc[co][0], p[2], w2); fma2(acc[co][1], p[4], w2);
                    fma2(acc[co][2], p[6], w2); fma2(acc[co][3], p[8], w2);
                }
            }
        }
        __syncthreads();
    }

    const int xo = x0 + tx * 8;
    const size_t base = (size_t)zb * HW + (y0 + ty) * W_ + xo;
    #pragma unroll
    for (int co = 0; co < 4; co++) {
        int coG = coBase + cg * 4 + co;
        if (coG < Cout) {
            float2 q0 = unpk2(acc[co][0]);
            float2 q1 = unpk2(acc[co][1]);
            float2 q2 = unpk2(acc[co][2]);
            float2 q3 = unpk2(acc[co][3]);
            float* op = out + (size_t)coG * VOX + base;
            *(float4*)(op + 0) = make_float4(q0.x, q0.y, q1.x, q1.y);
            *(float4*)(op + 4) = make_float4(q2.x, q2.y, q3.x, q3.y);
        }
    }
}

// ============================ SRU kernels (float2, fast activations) ============
__global__ void si_sru_k(const float* __restrict__ g, float* __restrict__ out,
                         const float* __restrict__ add, int C, int rev)
{
    int tid = blockIdx.x * blockDim.x + threadIdx.x;
    int total = C * HW2;
    if (tid >= total) return;
    int c  = tid / HW2;
    int yx = (tid - c * HW2) * 2;

    const float2* Wp = (const float2*)(g + (size_t)(0 * C + c) * VOX + yx);
    const float2* Fp = (const float2*)(g + (size_t)(1 * C + c) * VOX + yx);
    const float2* Rp = (const float2*)(g + (size_t)(2 * C + c) * VOX + yx);
    const float2* Xp = (const float2*)(g + (size_t)(3 * C + c) * VOX + yx);
    float2*       op = (float2*)(out + (size_t)c * VOX + yx);
    const float2* ap = add ? (const float2*)(add + (size_t)c * VOX + yx) : nullptr;

    int off = rev ? (D_ - 1) * HW2 : 0;
    int zs  = rev ? -HW2 : HW2;

    float2 f = Fp[off], r = Rp[off], xv = Xp[off];
    float fx = sigm(f.x), fy = sigm(f.y);
    float Cx = 1.f - fx, Cy = 1.f - fy;
    float rx = sigm(r.x), ry = sigm(r.y);
    float hx = rx * Cx + (1.f - rx) * tanhx(xv.x);
    float hy = ry * Cy + (1.f - ry) * tanhx(xv.y);
    float2 av = ap ? ap[off] : make_float2(0.f, 0.f);
    op[off] = make_float2(hx + av.x, hy + av.y);

    for (int t = 1; t < D_; t++) {
        off += zs;
        f = Fp[off]; r = Rp[off]; xv = Xp[off];
        float2 wv = Wp[off];
        fx = sigm(f.x); fy = sigm(f.y);
        Cx = fx * Cx + (1.f - fx) * tanhx(wv.x);
        Cy = fy * Cy + (1.f - fy) * tanhx(wv.y);
        rx = sigm(r.x); ry = sigm(r.y);
        hx = rx * Cx + (1.f - rx) * tanhx(xv.x);
        hy = ry * Cy + (1.f - ry) * tanhx(xv.y);
        av = ap ? ap[off] : make_float2(0.f, 0.f);
        op[off] = make_float2(hx + av.x, hy + av.y);
    }
}

__global__ void do_sru_k(const float* __restrict__ g, float* __restrict__ out,
                         const float* __restrict__ add, int C)
{
    int tid = blockIdx.x * blockDim.x + threadIdx.x;
    int total = C * HW2;
    if (tid >= total) return;
    int c  = tid / HW2;
    int yx = (tid - c * HW2) * 2;

    const float2* Wp = (const float2*)(g + (size_t)(0 * C + c) * VOX + yx);
    const float2* F1 = (const float2*)(g + (size_t)(1 * C + c) * VOX + yx);
    const float2* F2 = (const float2*)(g + (size_t)(2 * C + c) * VOX + yx);
    const float2* R1 = (const float2*)(g + (size_t)(3 * C + c) * VOX + yx);
    const float2* R2 = (const float2*)(g + (size_t)(4 * C + c) * VOX + yx);
    const float2* Xp = (const float2*)(g + (size_t)(5 * C + c) * VOX + yx);
    float2*       op = (float2*)(out + (size_t)c * VOX + yx);
    const float2* ap = add ? (const float2*)(add + (size_t)c * VOX + yx) : nullptr;

    {
        float2 f = F1[0], r = R1[0], xv = Xp[0];
        float fx = sigm(f.x), fy = sigm(f.y);
        float Cx = 1.f - fx, Cy = 1.f - fy;
        float rx = sigm(r.x), ry = sigm(r.y);
        op[0] = make_float2(rx * Cx + (1.f - rx) * tanhx(xv.x),
                            ry * Cy + (1.f - ry) * tanhx(xv.y));
        int off = 0;
        for (int t = 1; t < D_; t++) {
            off += HW2;
            f = F1[off]; r = R1[off]; xv = Xp[off];
            float2 wv = Wp[off];
            fx = sigm(f.x); fy = sigm(f.y);
            Cx = fx * Cx + (1.f - fx) * tanhx(wv.x);
            Cy = fy * Cy + (1.f - fy) * tanhx(wv.y);
            rx = sigm(r.x); ry = sigm(r.y);
            op[off] = make_float2(rx * Cx + (1.f - rx) * tanhx(xv.x),
                                  ry * Cy + (1.f - ry) * tanhx(xv.y));
        }
    }
    {
        int off = (D_ - 1) * HW2;
        float2 f = F2[off], r = R2[off], xv = Xp[off];
        float fx = sigm(f.x), fy = sigm(f.y);
        float Cx = 1.f - fx, Cy = 1.f - fy;
        float rx = sigm(r.x), ry = sigm(r.y);
        float hx = rx * Cx + (1.f - rx) * tanhx(xv.x);
        float hy = ry * Cy + (1.f - ry) * tanhx(xv.y);
        float2 prev = op[off];
        float2 av = ap ? ap[off] : make_float2(0.f, 0.f);
        op[off] = make_float2(prev.x + hx + av.x, prev.y + hy + av.y);
        for (int t = 1; t < D_; t++) {
            off -= HW2;
            f = F2[off]; r = R2[off]; xv = Xp[off];
            float2 wv = Wp[off];
            fx = sigm(f.x); fy = sigm(f.y);
            Cx = fx * Cx + (1.f - fx) * tanhx(wv.x);
            Cy = fy * Cy + (1.f - fy) * tanhx(wv.y);
            rx = sigm(r.x); ry = sigm(r.y);
            hx = rx * Cx + (1.f - rx) * tanhx(xv.x);
            hy = ry * Cy + (1.f - ry) * tanhx(xv.y);
            prev = op[off];
            av = ap ? ap[off] : make_float2(0.f, 0.f);
            op[off] = make_float2(prev.x + hx + av.x, prev.y + hy + av.y);
        }
    }
}

// ============================ host ============================
static __half* s_Ahi;

static inline void conv_tc(const float* in, const float* w, float* out,
                           int Cin, int Cout, int deconv)
{
    int Kpad = Cin * 32;
    int total = Cout * Kpad;
    prep_k<<<(total + 255) / 256, 256>>>(w, s_Ahi, Cin, Cout, Kpad, deconv, total);
    dim3 grid(D_ * 48, Cout / 64);
    conv_mma_k<<<grid, 256>>>(in, s_Ahi, out, Cin / 2, Kpad);
}

static inline void conv_scalar(const float* in, const float* w, float* out,
                               int Cin, int Cout, int deconv)
{
    dim3 grid(W_ / 32, (H_ / 8) * D_, (Cout + 31) / 32);
    conv3d_k<<<grid, 256>>>(in, w, out, Cin, Cout, deconv);
}

static inline void si_launch(const float* gbuf, float* out, const float* add, int C, int rev)
{
    int n = C * HW2;
    si_sru_k<<<(n + 255) / 256, 256>>>(gbuf, out, add, C, rev);
}
static inline void do_launch(const float* gbuf, float* out, const float* add, int C)
{
    int n = C * HW2;
    do_sru_k<<<(n + 255) / 256, 256>>>(gbuf, out, add, C);
}

extern "C" void kernel_launch(void* const* d_in, const int* in_sizes, int n_in,
                              void* d_out, int out_size)
{
    (void)in_sizes; (void)n_in; (void)out_size;
    const float* x      = (const float*)d_in[0];
    const float* w_head = (const float*)d_in[1];
    const float* w_e0   = (const float*)d_in[2];
    const float* w_e1   = (const float*)d_in[3];
    const float* w_d0   = (const float*)d_in[4];
    const float* w_d1   = (const float*)d_in[5];
    const float* w_tail = (const float*)d_in[6];
    float* out = (float*)d_out;

    float *gc, *gh, *ge0, *ge1, *gd0, *gd1;
    cudaGetSymbolAddress((void**)&gc,  g_conv);
    cudaGetSymbolAddress((void**)&gh,  g_h);
    cudaGetSymbolAddress((void**)&ge0, g_e0);
    cudaGetSymbolAddress((void**)&ge1, g_e1);
    cudaGetSymbolAddress((void**)&gd0, g_d0);
    cudaGetSymbolAddress((void**)&gd1, g_d1);
    cudaGetSymbolAddress((void**)&s_Ahi, g_Ahi);

    // h = do_sru(x, w_head)          (scalar: Cin=1)
    conv_scalar(x, w_head, gc, 1, 96, 0);
    do_launch(gc, gh, nullptr, 16);
    // e0 = si_sru(h, w_e0, fwd)      (mma: 16 -> 128)
    conv_tc(gh, w_e0, gc, 16, 128, 0);
    si_launch(gc, ge0, nullptr, 32, 0);
    // e1 = si_sru(e0, w_e1, rev)     (mma: 32 -> 256)
    conv_tc(ge0, w_e1, gc, 32, 256, 0);
    si_launch(gc, ge1, nullptr, 64, 1);
    // d0 = si_sru(e1, w_d0, fwd, deconv) + e0   (mma: 64 -> 128)
    conv_tc(ge1, w_d0, gc, 64, 128, 1);
    si_launch(gc, gd0, ge0, 32, 0);
    // d1 = si_sru(d0, w_d1, rev, deconv) + h    (mma: 32 -> 64)
    conv_tc(gd0, w_d1, gc, 32, 64, 1);
    si_launch(gc, gd1, gh, 16, 1);
    // out = do_sru(d1, w_tail, deconv) + x      (scalar: Cout=6)
    conv_scalar(gd1, w_tail, gc, 16, 6, 1);
    do_launch(gc, out, x, 1);
}